// round 8
// baseline (speedup 1.0000x reference)
#include <cuda_runtime.h>
#include <math.h>

// ---------------- problem constants ----------------
#define NN   4096
#define EE   65536
#define IND  512
#define HDIM 256
#define QD   256
#define NHD  8
#define HD   32
#define OUTD 10
#define LL   2
#define MW   (NN/32)
#define NNQD ((long long)NN*QD)

// ---------------- static scratch ----------------
__device__ float    g_h   [NN*HDIM];
__device__ float    g_bufA[3*NN*QD];     // Qt, Kt, V
__device__ float    g_bufB[3*NN*QD];     // Q, K, V
__device__ float    g_bufC[3*NN*QD];     // mq, mk, mv
__device__ float    g_bufD[2*NN*QD];     // eA, eB
__device__ float    g_W3  [2*3*HDIM*QD];
__device__ float    g_b3  [2*3*QD];
__device__ float    g_Bc2 [2*2*QD*QD];   // staged [Bc | BcT] per layer
__device__ float    g_vm  [QD];
__device__ float    g_gatt[NN*QD];
__device__ float    g_mo  [NN*QD];
__device__ float    g_mha [NN*QD];
__device__ float    g_m2  [(size_t)EE*QD];   // 64MB (only edge intermediate left)
__device__ unsigned g_mask[(size_t)NN*MW];
__device__ float    g_agg [NN*HDIM];
__device__ float    g_pool[2*HDIM];
__device__ float    g_z   [HDIM];

// ---------------- TF32 helpers ----------------
__device__ __forceinline__ unsigned f2tf(float f) {
    unsigned u;
    asm("cvt.rna.tf32.f32 %0, %1;" : "=r"(u) : "f"(f));
    return u;
}
__device__ __forceinline__ void mma_tf32(float* c, const unsigned* a, const unsigned* b) {
    asm volatile(
        "mma.sync.aligned.m16n8k8.row.col.f32.tf32.tf32.f32 "
        "{%0,%1,%2,%3}, {%4,%5,%6,%7}, {%8,%9}, {%0,%1,%2,%3};"
        : "+f"(c[0]), "+f"(c[1]), "+f"(c[2]), "+f"(c[3])
        : "r"(a[0]), "r"(a[1]), "r"(a[2]), "r"(a[3]), "r"(b[0]), "r"(b[1]));
}
__device__ __forceinline__ void cpasync16(void* sdst, const void* gsrc) {
    unsigned sa = (unsigned)__cvta_generic_to_shared(sdst);
    asm volatile("cp.async.cg.shared.global [%0], [%1], 16;\n" :: "r"(sa), "l"(gsrc));
}
#define CP_COMMIT() asm volatile("cp.async.commit_group;\n" ::: "memory")

// =====================================================================
// Generic TF32 GEMM (proven; batched via blockIdx.z)
// =====================================================================
template<int BM, int BN, int TRANSB, int STAGES>
constexpr size_t tg_smem() {
    return (size_t)STAGES * ((size_t)BM * 36 + (TRANSB ? (size_t)BN * 36
                                                       : (size_t)32 * (BN + 8))) * 4;
}

template<int BM, int BN, int WM, int WN, int TRANSB, int STAGES>
__global__ __launch_bounds__(256)
void tgemm_k(const float* __restrict__ A, int lda, long long sA,
             const float* __restrict__ B, int ldb, long long sB,
             float* __restrict__ C, int ldc, long long sC,
             int K,
             const float* __restrict__ bias, long long sBias, int act)
{
    constexpr int BK   = 32;
    constexpr int WX   = BN / WN;
    constexpr int WY   = BM / WM;
    static_assert(WX * WY == 8, "8 warps");
    constexpr int MM   = WM / 16;
    constexpr int MN   = WN / 8;
    constexpr int AL   = BM * (BK / 4) / 256;
    constexpr int BLt  = BN * (BK / 4) / 256;
    constexpr int BLn  = BK * (BN / 4) / 256;
    constexpr int ASTR = BK + 4;
    constexpr int BNSTR= BN + 8;
    constexpr int ASZ  = BM * ASTR;
    constexpr int BSZ  = TRANSB ? BN * ASTR : BK * BNSTR;

    const int tid  = threadIdx.x;
    const int wid  = tid >> 5;
    const int lane = tid & 31;
    const int wx   = wid % WX;
    const int wy   = wid / WX;
    const int lg   = lane >> 2;
    const int lt   = lane & 3;
    const int m0   = blockIdx.y * BM;
    const int n0   = blockIdx.x * BN;

    const float* Ab    = A + sA * blockIdx.z;
    const float* Bb    = B + sB * blockIdx.z;
    float*       Cb    = C + sC * blockIdx.z;
    const float* biasb = bias ? bias + sBias * blockIdx.z : nullptr;

    extern __shared__ float smem[];
    float* AsBase = smem;
    float* BsBase = smem + (size_t)STAGES * ASZ;

    auto load_stage = [&](int s, int k0) {
        float* as = AsBase + (size_t)s * ASZ;
#pragma unroll
        for (int j = 0; j < AL; j++) {
            int idx = tid + j * 256;
            int m   = idx >> 3;
            int k4  = idx & 7;
            cpasync16(&as[m * ASTR + k4 * 4],
                      &Ab[(size_t)(m0 + m) * lda + k0 + k4 * 4]);
        }
        float* bs = BsBase + (size_t)s * BSZ;
        if (TRANSB) {
#pragma unroll
            for (int j = 0; j < BLt; j++) {
                int idx = tid + j * 256;
                int n   = idx >> 3;
                int k4  = idx & 7;
                cpasync16(&bs[n * ASTR + k4 * 4],
                          &Bb[(size_t)(n0 + n) * ldb + k0 + k4 * 4]);
            }
        } else {
#pragma unroll
            for (int j = 0; j < BLn; j++) {
                int idx = tid + j * 256;
                int k   = idx / (BN / 4);
                int n4  = idx % (BN / 4);
                cpasync16(&bs[k * BNSTR + n4 * 4],
                          &Bb[(size_t)(k0 + k) * ldb + n0 + n4 * 4]);
            }
        }
    };

    float acc[MM][MN][4];
#pragma unroll
    for (int i = 0; i < MM; i++)
#pragma unroll
        for (int j = 0; j < MN; j++)
#pragma unroll
            for (int c = 0; c < 4; c++) acc[i][j][c] = 0.f;

    const int ktiles = K / BK;
#pragma unroll
    for (int s = 0; s < STAGES - 1; s++) {
        if (s < ktiles) load_stage(s, s * BK);
        CP_COMMIT();
    }

    for (int t = 0; t < ktiles; t++) {
        asm volatile("cp.async.wait_group %0;\n" :: "n"(STAGES - 2) : "memory");
        __syncthreads();

        int nt = t + STAGES - 1;
        if (nt < ktiles) load_stage(nt % STAGES, nt * BK);
        CP_COMMIT();

        const float* as = AsBase + (size_t)(t % STAGES) * ASZ;
        const float* bs = BsBase + (size_t)(t % STAGES) * BSZ;

#pragma unroll
        for (int ks = 0; ks < BK / 8; ks++) {
            const int kk = ks * 8;
            unsigned af[MM][4], bf[MN][2];
#pragma unroll
            for (int i = 0; i < MM; i++) {
                int row = wy * WM + i * 16 + lg;
                af[i][0] = f2tf(as[row * ASTR + kk + lt]);
                af[i][1] = f2tf(as[(row + 8) * ASTR + kk + lt]);
                af[i][2] = f2tf(as[row * ASTR + kk + lt + 4]);
                af[i][3] = f2tf(as[(row + 8) * ASTR + kk + lt + 4]);
            }
#pragma unroll
            for (int j = 0; j < MN; j++) {
                int col = wx * WN + j * 8 + lg;
                if (TRANSB) {
                    bf[j][0] = f2tf(bs[col * ASTR + kk + lt]);
                    bf[j][1] = f2tf(bs[col * ASTR + kk + lt + 4]);
                } else {
                    bf[j][0] = f2tf(bs[(kk + lt) * BNSTR + col]);
                    bf[j][1] = f2tf(bs[(kk + lt + 4) * BNSTR + col]);
                }
            }
#pragma unroll
            for (int i = 0; i < MM; i++)
#pragma unroll
                for (int j = 0; j < MN; j++)
                    mma_tf32(acc[i][j], af[i], bf[j]);
        }
        __syncthreads();
    }

#pragma unroll
    for (int i = 0; i < MM; i++) {
        int mA = m0 + wy * WM + i * 16 + lg;
        int mB = mA + 8;
#pragma unroll
        for (int j = 0; j < MN; j++) {
            int n = n0 + wx * WN + j * 8 + lt * 2;
            float b0 = biasb ? biasb[n] : 0.f;
            float b1 = biasb ? biasb[n + 1] : 0.f;
            float v0 = acc[i][j][0] + b0;
            float v1 = acc[i][j][1] + b1;
            float v2 = acc[i][j][2] + b0;
            float v3 = acc[i][j][3] + b1;
            if (act == 1) {
                v0 = fmaxf(v0, 0.f); v1 = fmaxf(v1, 0.f);
                v2 = fmaxf(v2, 0.f); v3 = fmaxf(v3, 0.f);
            }
            Cb[(size_t)mA * ldc + n]     = v0;
            Cb[(size_t)mA * ldc + n + 1] = v1;
            Cb[(size_t)mB * ldc + n]     = v2;
            Cb[(size_t)mB * ldc + n + 1] = v3;
        }
    }
}

// =====================================================================
// Edge GEMM 1 (gather): m2 = relu( relu(eA[tgt]+eB[src]+b1) @ Wm2 + b2 )
//  BM=128, BN=128, BK=32, K=256. A gathered per K-tile; B 3-stage cp.async.
// =====================================================================
#define EG_ASTR 36
#define EG_BSTR 136
#define EG_SMEM ((128*EG_ASTR + 3*32*EG_BSTR) * 4)

__global__ __launch_bounds__(256)
void egemm_gather_k(const float* __restrict__ eA, const float* __restrict__ eB,
                    const float* __restrict__ b1, const int* __restrict__ ei,
                    const float* __restrict__ W, const float* __restrict__ b2,
                    float* __restrict__ C)
{
    __shared__ int tgts[128], srcs[128];
    extern __shared__ float smem[];
    float* As = smem;                  // [128][36]
    float* Bs = smem + 128 * EG_ASTR;  // 3 stages [32][136]

    const int tid  = threadIdx.x;
    const int wid  = tid >> 5;
    const int lane = tid & 31;
    const int wx   = wid & 3;          // WX=4 (WN=32)
    const int wy   = wid >> 2;         // WY=2 (WM=64)
    const int lg   = lane >> 2;
    const int lt   = lane & 3;
    const int m0   = blockIdx.y * 128;
    const int n0   = blockIdx.x * 128;

    if (tid < 128) { srcs[tid] = ei[m0 + tid]; tgts[tid] = ei[EE + m0 + tid]; }

    auto loadB = [&](int s, int k0) {
        float* bs = Bs + s * 32 * EG_BSTR;
#pragma unroll
        for (int j = 0; j < 4; j++) {
            int idx = tid + j * 256;
            int k = idx >> 5, n4 = idx & 31;
            cpasync16(&bs[k * EG_BSTR + n4 * 4], &W[(size_t)(k0 + k) * QD + n0 + n4 * 4]);
        }
    };
    loadB(0, 0);  CP_COMMIT();
    loadB(1, 32); CP_COMMIT();

    float acc[4][4][4];
#pragma unroll
    for (int i = 0; i < 4; i++)
#pragma unroll
        for (int j = 0; j < 4; j++)
#pragma unroll
            for (int c = 0; c < 4; c++) acc[i][j][c] = 0.f;

    const float4* eA4 = (const float4*)eA;
    const float4* eB4 = (const float4*)eB;
    const float4* b14 = (const float4*)b1;

    for (int t = 0; t < 8; t++) {
        const int k0 = t * 32;
        asm volatile("cp.async.wait_group 1;\n" ::: "memory");
        __syncthreads();   // prev compute done; tgts visible (iter 0)

        // gather + relu -> As
#pragma unroll
        for (int j = 0; j < 4; j++) {
            int idx = tid + j * 256;
            int m = idx >> 3, k4 = idx & 7;
            float4 a = eA4[(size_t)tgts[m] * (QD/4) + (k0 >> 2) + k4];
            float4 b = eB4[(size_t)srcs[m] * (QD/4) + (k0 >> 2) + k4];
            float4 c = b14[(k0 >> 2) + k4];
            As[m * EG_ASTR + k4 * 4 + 0] = fmaxf(a.x + b.x + c.x, 0.f);
            As[m * EG_ASTR + k4 * 4 + 1] = fmaxf(a.y + b.y + c.y, 0.f);
            As[m * EG_ASTR + k4 * 4 + 2] = fmaxf(a.z + b.z + c.z, 0.f);
            As[m * EG_ASTR + k4 * 4 + 3] = fmaxf(a.w + b.w + c.w, 0.f);
        }
        if (t + 2 < 8) loadB((t + 2) % 3, (t + 2) * 32);
        CP_COMMIT();
        __syncthreads();   // As visible

        const float* bs = Bs + (t % 3) * 32 * EG_BSTR;
#pragma unroll
        for (int ks = 0; ks < 4; ks++) {
            const int kk = ks * 8;
            unsigned af[4][4], bf[4][2];
#pragma unroll
            for (int i = 0; i < 4; i++) {
                int row = wy * 64 + i * 16 + lg;
                af[i][0] = f2tf(As[row * EG_ASTR + kk + lt]);
                af[i][1] = f2tf(As[(row + 8) * EG_ASTR + kk + lt]);
                af[i][2] = f2tf(As[row * EG_ASTR + kk + lt + 4]);
                af[i][3] = f2tf(As[(row + 8) * EG_ASTR + kk + lt + 4]);
            }
#pragma unroll
            for (int j = 0; j < 4; j++) {
                int col = wx * 32 + j * 8 + lg;
                bf[j][0] = f2tf(bs[(kk + lt) * EG_BSTR + col]);
                bf[j][1] = f2tf(bs[(kk + lt + 4) * EG_BSTR + col]);
            }
#pragma unroll
            for (int i = 0; i < 4; i++)
#pragma unroll
                for (int j = 0; j < 4; j++)
                    mma_tf32(acc[i][j], af[i], bf[j]);
        }
    }

#pragma unroll
    for (int i = 0; i < 4; i++) {
        int mA = m0 + wy * 64 + i * 16 + lg;
        int mB = mA + 8;
#pragma unroll
        for (int j = 0; j < 4; j++) {
            int n = n0 + wx * 32 + j * 8 + lt * 2;
            float b0 = b2[n], b1v = b2[n + 1];
            C[(size_t)mA * QD + n]     = fmaxf(acc[i][j][0] + b0, 0.f);
            C[(size_t)mA * QD + n + 1] = fmaxf(acc[i][j][1] + b1v, 0.f);
            C[(size_t)mB * QD + n]     = fmaxf(acc[i][j][2] + b0, 0.f);
            C[(size_t)mB * QD + n + 1] = fmaxf(acc[i][j][3] + b1v, 0.f);
        }
    }
}

// =====================================================================
// Edge GEMM 2 (scatter): agg[tgt[e]] += m2[e] @ Wm3 + b3
//  Same tiling; A 3-stage cp.async; epilogue atomics.
// =====================================================================
#define ES_SMEM ((3*128*EG_ASTR + 3*32*EG_BSTR) * 4)

__global__ __launch_bounds__(256)
void egemm_scatter_k(const float* __restrict__ A, const int* __restrict__ ei,
                     const float* __restrict__ W, const float* __restrict__ b3,
                     float* __restrict__ agg)
{
    extern __shared__ float smem[];
    float* AsBase = smem;                        // 3 stages [128][36]
    float* BsBase = smem + 3 * 128 * EG_ASTR;    // 3 stages [32][136]

    const int tid  = threadIdx.x;
    const int wid  = tid >> 5;
    const int lane = tid & 31;
    const int wx   = wid & 3;
    const int wy   = wid >> 2;
    const int lg   = lane >> 2;
    const int lt   = lane & 3;
    const int m0   = blockIdx.y * 128;
    const int n0   = blockIdx.x * 128;

    auto load_stage = [&](int s, int k0) {
        float* as = AsBase + s * 128 * EG_ASTR;
#pragma unroll
        for (int j = 0; j < 4; j++) {
            int idx = tid + j * 256;
            int m = idx >> 3, k4 = idx & 7;
            cpasync16(&as[m * EG_ASTR + k4 * 4],
                      &A[(size_t)(m0 + m) * QD + k0 + k4 * 4]);
        }
        float* bs = BsBase + s * 32 * EG_BSTR;
#pragma unroll
        for (int j = 0; j < 4; j++) {
            int idx = tid + j * 256;
            int k = idx >> 5, n4 = idx & 31;
            cpasync16(&bs[k * EG_BSTR + n4 * 4],
                      &W[(size_t)(k0 + k) * HDIM + n0 + n4 * 4]);
        }
    };
    load_stage(0, 0);  CP_COMMIT();
    load_stage(1, 32); CP_COMMIT();

    float acc[4][4][4];
#pragma unroll
    for (int i = 0; i < 4; i++)
#pragma unroll
        for (int j = 0; j < 4; j++)
#pragma unroll
            for (int c = 0; c < 4; c++) acc[i][j][c] = 0.f;

    for (int t = 0; t < 8; t++) {
        asm volatile("cp.async.wait_group 1;\n" ::: "memory");
        __syncthreads();

        if (t + 2 < 8) load_stage((t + 2) % 3, (t + 2) * 32);
        CP_COMMIT();

        const float* as = AsBase + (t % 3) * 128 * EG_ASTR;
        const float* bs = BsBase + (t % 3) * 32 * EG_BSTR;
#pragma unroll
        for (int ks = 0; ks < 4; ks++) {
            const int kk = ks * 8;
            unsigned af[4][4], bf[4][2];
#pragma unroll
            for (int i = 0; i < 4; i++) {
                int row = wy * 64 + i * 16 + lg;
                af[i][0] = f2tf(as[row * EG_ASTR + kk + lt]);
                af[i][1] = f2tf(as[(row + 8) * EG_ASTR + kk + lt]);
                af[i][2] = f2tf(as[row * EG_ASTR + kk + lt + 4]);
                af[i][3] = f2tf(as[(row + 8) * EG_ASTR + kk + lt + 4]);
            }
#pragma unroll
            for (int j = 0; j < 4; j++) {
                int col = wx * 32 + j * 8 + lg;
                bf[j][0] = f2tf(bs[(kk + lt) * EG_BSTR + col]);
                bf[j][1] = f2tf(bs[(kk + lt + 4) * EG_BSTR + col]);
            }
#pragma unroll
            for (int i = 0; i < 4; i++)
#pragma unroll
                for (int j = 0; j < 4; j++)
                    mma_tf32(acc[i][j], af[i], bf[j]);
        }
        __syncthreads();
    }

#pragma unroll
    for (int i = 0; i < 4; i++) {
        int mA = m0 + wy * 64 + i * 16 + lg;
        int mB = mA + 8;
        int tA = ei[EE + mA];
        int tB = ei[EE + mB];
#pragma unroll
        for (int j = 0; j < 4; j++) {
            int n = n0 + wx * 32 + j * 8 + lt * 2;
            float b0 = b3[n], b1v = b3[n + 1];
            atomicAdd(&agg[(size_t)tA * HDIM + n],     acc[i][j][0] + b0);
            atomicAdd(&agg[(size_t)tA * HDIM + n + 1], acc[i][j][1] + b1v);
            atomicAdd(&agg[(size_t)tB * HDIM + n],     acc[i][j][2] + b0);
            atomicAdd(&agg[(size_t)tB * HDIM + n + 1], acc[i][j][3] + b1v);
        }
    }
}

// =====================================================================
// Flash MHA (proven, unchanged)
// =====================================================================
#define FBQ   128
#define FBKV  64
#define QSTR  36
#define KSTR  36
#define VSTR  40
#define PSTR  68
#define FLASH_SMEM ((FBQ*QSTR + 2*FBKV*KSTR + 2*FBKV*VSTR + 8*16*PSTR) * 4)

__global__ __launch_bounds__(256)
void flash_mha_k(const float* __restrict__ mq, const float* __restrict__ mk,
                 const float* __restrict__ mv, float* __restrict__ mo, float scale)
{
    extern __shared__ float sm[];
    float*    Qs = sm;
    float*    Ks = Qs + FBQ * QSTR;
    float*    Vs = Ks + 2 * FBKV * KSTR;
    unsigned* Ps = (unsigned*)(Vs + 2 * FBKV * VSTR);

    const int tid  = threadIdx.x;
    const int wid  = tid >> 5;
    const int lane = tid & 31;
    const int lg   = lane >> 2;
    const int lt   = lane & 3;
    const int hh   = blockIdx.y;
    const int q0   = blockIdx.x * FBQ;

    const float* Qg = mq + (size_t)q0 * QD + hh * HD;
    const float* Kg = mk + hh * HD;
    const float* Vg = mv + hh * HD;

#pragma unroll
    for (int j = 0; j < 4; j++) {
        int idx = tid + j * 256;
        int r = idx >> 3, c4 = idx & 7;
        cpasync16(&Qs[r * QSTR + c4 * 4], &Qg[(size_t)r * QD + c4 * 4]);
    }
    auto loadKV = [&](int s, int kv0) {
        float* ks = Ks + s * FBKV * KSTR;
        float* vs = Vs + s * FBKV * VSTR;
#pragma unroll
        for (int j = 0; j < 2; j++) {
            int idx = tid + j * 256;
            int r = idx >> 3, c4 = idx & 7;
            cpasync16(&ks[r * KSTR + c4 * 4], &Kg[(size_t)(kv0 + r) * QD + c4 * 4]);
        }
#pragma unroll
        for (int j = 0; j < 2; j++) {
            int idx = tid + j * 256;
            int r = idx >> 3, c4 = idx & 7;
            cpasync16(&vs[r * VSTR + c4 * 4], &Vg[(size_t)(kv0 + r) * QD + c4 * 4]);
        }
    };
    loadKV(0, 0);
    CP_COMMIT();

    float O[4][4];
#pragma unroll
    for (int j = 0; j < 4; j++)
#pragma unroll
        for (int c = 0; c < 4; c++) O[j][c] = 0.f;
    float m0r = -3.4e38f, m1r = -3.4e38f;
    float l0 = 0.f, l1 = 0.f;
    unsigned* Pw = Ps + wid * 16 * PSTR;
    const int qrow = wid * 16 + lg;

    const int NT = NN / FBKV;
    for (int t = 0; t < NT; t++) {
        if (t + 1 < NT) loadKV((t + 1) & 1, (t + 1) * FBKV);
        CP_COMMIT();
        asm volatile("cp.async.wait_group 1;\n" ::: "memory");
        __syncthreads();

        const float* ks = Ks + (t & 1) * FBKV * KSTR;
        const float* vs = Vs + (t & 1) * FBKV * VSTR;

        float Sacc[8][4];
#pragma unroll
        for (int n = 0; n < 8; n++)
#pragma unroll
            for (int c = 0; c < 4; c++) Sacc[n][c] = 0.f;
#pragma unroll
        for (int ks8 = 0; ks8 < 4; ks8++) {
            const int kk = ks8 * 8;
            unsigned af[4];
            af[0] = f2tf(Qs[qrow * QSTR + kk + lt]);
            af[1] = f2tf(Qs[(qrow + 8) * QSTR + kk + lt]);
            af[2] = f2tf(Qs[qrow * QSTR + kk + lt + 4]);
            af[3] = f2tf(Qs[(qrow + 8) * QSTR + kk + lt + 4]);
#pragma unroll
            for (int n = 0; n < 8; n++) {
                int col = n * 8 + lg;
                unsigned bf[2];
                bf[0] = f2tf(ks[col * KSTR + kk + lt]);
                bf[1] = f2tf(ks[col * KSTR + kk + lt + 4]);
                mma_tf32(Sacc[n], af, bf);
            }
        }

        float mx0 = -3.4e38f, mx1 = -3.4e38f;
#pragma unroll
        for (int n = 0; n < 8; n++) {
            Sacc[n][0] *= scale; Sacc[n][1] *= scale;
            Sacc[n][2] *= scale; Sacc[n][3] *= scale;
            mx0 = fmaxf(mx0, fmaxf(Sacc[n][0], Sacc[n][1]));
            mx1 = fmaxf(mx1, fmaxf(Sacc[n][2], Sacc[n][3]));
        }
        mx0 = fmaxf(mx0, __shfl_xor_sync(0xffffffffu, mx0, 1));
        mx0 = fmaxf(mx0, __shfl_xor_sync(0xffffffffu, mx0, 2));
        mx1 = fmaxf(mx1, __shfl_xor_sync(0xffffffffu, mx1, 1));
        mx1 = fmaxf(mx1, __shfl_xor_sync(0xffffffffu, mx1, 2));
        float mn0 = fmaxf(m0r, mx0), mn1 = fmaxf(m1r, mx1);
        float a0 = __expf(m0r - mn0), a1 = __expf(m1r - mn1);
        float rs0 = 0.f, rs1 = 0.f;
#pragma unroll
        for (int n = 0; n < 8; n++) {
            float p0 = __expf(Sacc[n][0] - mn0);
            float p1 = __expf(Sacc[n][1] - mn0);
            float p2 = __expf(Sacc[n][2] - mn1);
            float p3 = __expf(Sacc[n][3] - mn1);
            rs0 += p0 + p1; rs1 += p2 + p3;
            int c0 = n * 8 + lt * 2;
            Pw[lg * PSTR + c0]           = f2tf(p0);
            Pw[lg * PSTR + c0 + 1]       = f2tf(p1);
            Pw[(lg + 8) * PSTR + c0]     = f2tf(p2);
            Pw[(lg + 8) * PSTR + c0 + 1] = f2tf(p3);
        }
        rs0 += __shfl_xor_sync(0xffffffffu, rs0, 1);
        rs0 += __shfl_xor_sync(0xffffffffu, rs0, 2);
        rs1 += __shfl_xor_sync(0xffffffffu, rs1, 1);
        rs1 += __shfl_xor_sync(0xffffffffu, rs1, 2);
        l0 = l0 * a0 + rs0;
        l1 = l1 * a1 + rs1;
        m0r = mn0; m1r = mn1;
#pragma unroll
        for (int j = 0; j < 4; j++) {
            O[j][0] *= a0; O[j][1] *= a0;
            O[j][2] *= a1; O[j][3] *= a1;
        }
        __syncwarp();

#pragma unroll
        for (int ks8 = 0; ks8 < 8; ks8++) {
            const int kk = ks8 * 8;
            unsigned af[4];
            af[0] = Pw[lg * PSTR + kk + lt];
            af[1] = Pw[(lg + 8) * PSTR + kk + lt];
            af[2] = Pw[lg * PSTR + kk + lt + 4];
            af[3] = Pw[(lg + 8) * PSTR + kk + lt + 4];
#pragma unroll
            for (int j = 0; j < 4; j++) {
                int col = j * 8 + lg;
                unsigned bf[2];
                bf[0] = f2tf(vs[(kk + lt) * VSTR + col]);
                bf[1] = f2tf(vs[(kk + lt + 4) * VSTR + col]);
                mma_tf32(O[j], af, bf);
            }
        }
        __syncwarp();
        __syncthreads();
    }

    float inv0 = 1.f / l0, inv1 = 1.f / l1;
    const size_t rA = (size_t)(q0 + qrow) * QD + hh * HD;
    const size_t rB = rA + 8 * QD;
#pragma unroll
    for (int j = 0; j < 4; j++) {
        int c = j * 8 + lt * 2;
        mo[rA + c]     = O[j][0] * inv0;
        mo[rA + c + 1] = O[j][1] * inv0;
        mo[rB + c]     = O[j][2] * inv1;
        mo[rB + c + 1] = O[j][3] * inv1;
    }
}

// =====================================================================
// Sparse graph attention (proven, unchanged)
// =====================================================================
__global__ __launch_bounds__(128)
void sparse_gatt_k(const float* __restrict__ Q, const float* __restrict__ K,
                   const float* __restrict__ V, const unsigned* __restrict__ mask,
                   const float* __restrict__ vmean, float* __restrict__ gatt,
                   float scale)
{
    __shared__ int   idxs[NN];
    __shared__ float sc  [NN];
    __shared__ int   wbase[5];
    __shared__ float red[4];

    const int s    = blockIdx.x;
    const int tid  = threadIdx.x;
    const int wid  = tid >> 5;
    const int lane = tid & 31;

    unsigned w = mask[(size_t)s * MW + tid];
    int c = __popc(w);
    int pre = c;
#pragma unroll
    for (int o = 1; o < 32; o <<= 1) {
        int v = __shfl_up_sync(0xffffffffu, pre, o);
        if (lane >= o) pre += v;
    }
    if (lane == 31) wbase[wid + 1] = pre;
    __syncthreads();
    if (tid == 0) {
        wbase[0] = 0;
        wbase[2] += wbase[1];
        wbase[3] += wbase[2];
        wbase[4] += wbase[3];
    }
    __syncthreads();
    const int cnt = wbase[4];
    int p = wbase[wid] + pre - c;
    unsigned ww = w;
    while (ww) {
        int b = __ffs(ww) - 1;
        idxs[p++] = tid * 32 + b;
        ww &= ww - 1;
    }
    __syncthreads();

    const int c0 = tid * 2;
    if (cnt == 0) {
        gatt[(size_t)s * QD + c0]     = vmean[c0];
        gatt[(size_t)s * QD + c0 + 1] = vmean[c0 + 1];
        return;
    }

    float q[8];
    const float* Qr = Q + (size_t)s * QD;
#pragma unroll
    for (int i = 0; i < 8; i++) q[i] = Qr[lane * 8 + i];
    for (int e = wid; e < cnt; e += 4) {
        const float* Kr = K + (size_t)idxs[e] * QD;
        float d = 0.f;
#pragma unroll
        for (int i = 0; i < 8; i++) d = fmaf(q[i], Kr[lane * 8 + i], d);
#pragma unroll
        for (int o = 16; o; o >>= 1) d += __shfl_xor_sync(0xffffffffu, d, o);
        if (lane == 0) sc[e] = d * scale;
    }
    __syncthreads();

    float mx = -3.4e38f;
    for (int e = tid; e < cnt; e += 128) mx = fmaxf(mx, sc[e]);
#pragma unroll
    for (int o = 16; o; o >>= 1) mx = fmaxf(mx, __shfl_xor_sync(0xffffffffu, mx, o));
    if (lane == 0) red[wid] = mx;
    __syncthreads();
    mx = fmaxf(fmaxf(red[0], red[1]), fmaxf(red[2], red[3]));
    __syncthreads();

    float sum = 0.f;
    for (int e = tid; e < cnt; e += 128) {
        float pe = __expf(sc[e] - mx);
        sc[e] = pe;
        sum += pe;
    }
#pragma unroll
    for (int o = 16; o; o >>= 1) sum += __shfl_xor_sync(0xffffffffu, sum, o);
    if (lane == 0) red[wid] = sum;
    __syncthreads();
    float inv = 1.f / (red[0] + red[1] + red[2] + red[3]);

    float a0 = 0.f, a1 = 0.f;
    for (int e = 0; e < cnt; e++) {
        const float* Vr = V + (size_t)idxs[e] * QD;
        float pe = sc[e];
        a0 = fmaf(pe, Vr[c0], a0);
        a1 = fmaf(pe, Vr[c0 + 1], a1);
    }
    gatt[(size_t)s * QD + c0]     = a0 * inv;
    gatt[(size_t)s * QD + c0 + 1] = a1 * inv;
}

// ---------------- block reductions ----------------
__device__ __forceinline__ float blkMax(float v) {
    __shared__ float sh[8];
#pragma unroll
    for (int o = 16; o; o >>= 1) v = fmaxf(v, __shfl_xor_sync(0xffffffffu, v, o));
    if ((threadIdx.x & 31) == 0) sh[threadIdx.x >> 5] = v;
    __syncthreads();
    if (threadIdx.x < 32) {
        float w = (threadIdx.x < 8) ? sh[threadIdx.x] : -3.4e38f;
#pragma unroll
        for (int o = 4; o; o >>= 1) w = fmaxf(w, __shfl_xor_sync(0xffffffffu, w, o));
        if (threadIdx.x == 0) sh[0] = w;
    }
    __syncthreads();
    float r = sh[0];
    __syncthreads();
    return r;
}
__device__ __forceinline__ float blkSum(float v) {
    __shared__ float sh[8];
#pragma unroll
    for (int o = 16; o; o >>= 1) v += __shfl_xor_sync(0xffffffffu, v, o);
    if ((threadIdx.x & 31) == 0) sh[threadIdx.x >> 5] = v;
    __syncthreads();
    if (threadIdx.x < 32) {
        float w = (threadIdx.x < 8) ? sh[threadIdx.x] : 0.f;
#pragma unroll
        for (int o = 4; o; o >>= 1) w += __shfl_xor_sync(0xffffffffu, w, o);
        if (threadIdx.x == 0) sh[0] = w;
    }
    __syncthreads();
    float r = sh[0];
    __syncthreads();
    return r;
}

// ---------------- elementwise / small kernels ----------------
__global__ void zero_u32_k(unsigned* __restrict__ p, int n) {
    int i = blockIdx.x * blockDim.x + threadIdx.x;
    if (i < n) p[i] = 0u;
}
__global__ void zero_f32_k(float* __restrict__ p, int n) {
    int i = blockIdx.x * blockDim.x + threadIdx.x;
    if (i < n) p[i] = 0.f;
}
__global__ void build_mask_k(const int* __restrict__ ei, unsigned* __restrict__ mask) {
    int e = blockIdx.x * blockDim.x + threadIdx.x;
    if (e >= EE) return;
    int s = ei[e], t = ei[EE + e];
    atomicOr(&mask[(size_t)s * MW + (t >> 5)], 1u << (t & 31));
}
__global__ void stage_qkv_k(const float* __restrict__ Wq, const float* __restrict__ Wk,
                            const float* __restrict__ Wv, const float* __restrict__ bq,
                            const float* __restrict__ bk, const float* __restrict__ bv,
                            float* __restrict__ W3, float* __restrict__ b3) {
    int i = blockIdx.x * blockDim.x + threadIdx.x;
    const int per = HDIM * QD;
    if (i < 2 * per) {
        int l = i / per, r = i % per;
        W3[((size_t)l * 3 + 0) * per + r] = Wq[i];
        W3[((size_t)l * 3 + 1) * per + r] = Wk[i];
        W3[((size_t)l * 3 + 2) * per + r] = Wv[i];
    }
    if (i < 2 * QD) {
        int l = i / QD, r = i % QD;
        b3[(l * 3 + 0) * QD + r] = bq[i];
        b3[(l * 3 + 1) * QD + r] = bk[i];
        b3[(l * 3 + 2) * QD + r] = bv[i];
    }
}
// stage [Bc | BcT] contiguously per layer
__global__ void stage_bc_k(const float* __restrict__ Bc, float* __restrict__ Bc2) {
    int i = blockIdx.x * blockDim.x + threadIdx.x;
    if (i >= 2 * QD * QD) return;
    int l = i / (QD * QD), r = i % (QD * QD);
    int row = r / QD, col = r % QD;
    Bc2[((size_t)l * 2 + 0) * QD * QD + r] = Bc[i];
    Bc2[((size_t)l * 2 + 1) * QD * QD + (size_t)row * QD + col] = Bc[(size_t)l * QD * QD + (size_t)col * QD + row];
}
__global__ void copy4_k(const float4* __restrict__ src, float4* __restrict__ dst, int n) {
    int i = blockIdx.x * blockDim.x + threadIdx.x;
    if (i < n) dst[i] = src[i];
}
__global__ void vmean_k(const float* __restrict__ V, float* __restrict__ vm) {
    int c = blockIdx.x;
    float s = 0.f;
    for (int r = threadIdx.x; r < NN; r += 256) s += V[(size_t)r * QD + c];
    s = blkSum(s);
    if (threadIdx.x == 0) vm[c] = s * (1.f / NN);
}
__global__ void add_ce_k(float4* __restrict__ Q, float4* __restrict__ K,
                         const float4* __restrict__ ce, const int* __restrict__ ct) {
    int idx = blockIdx.x * blockDim.x + threadIdx.x;
    if (idx >= NN * (QD / 4)) return;
    int i = idx >> 6, j4 = idx & 63;
    float4 c = ce[ct[i] * (QD / 4) + j4];
    float4 q = Q[idx], k = K[idx];
    q.x += 0.1f * c.x; q.y += 0.1f * c.y; q.z += 0.1f * c.z; q.w += 0.1f * c.w;
    k.x += 0.1f * c.x; k.y += 0.1f * c.y; k.z += 0.1f * c.z; k.w += 0.1f * c.w;
    Q[idx] = q; K[idx] = k;
}
__global__ void combine_ln_k(float* __restrict__ h, const float* __restrict__ agg,
                             const float* __restrict__ mha, const float* __restrict__ gatt,
                             const float* __restrict__ g, const float* __restrict__ b) {
    int r = blockIdx.x, j = threadIdx.x;
    size_t idx = (size_t)r * HDIM + j;
    float v = h[idx] + agg[idx] + mha[idx] + gatt[idx];
    float mu = blkSum(v) * (1.f / HDIM);
    float d = v - mu;
    float var = blkSum(d * d) * (1.f / HDIM);
    h[idx] = d * rsqrtf(var + 1e-5f) * g[j] + b[j];
}
__global__ void pool_k(const float* __restrict__ h, float* __restrict__ pool) {
    int c = blockIdx.x, t = threadIdx.x;
    if (c < HDIM) {
        float s = 0.f;
        for (int r = t; r < NN; r += 256) s += h[(size_t)r * HDIM + c];
        s = blkSum(s);
        if (t == 0) pool[c] = s * (1.f / NN);
    } else {
        int cc = c - HDIM;
        float m = -3.4e38f;
        for (int r = t; r < NN; r += 256) m = fmaxf(m, h[(size_t)r * HDIM + cc]);
        m = blkMax(m);
        if (t == 0) pool[c] = m;
    }
}
__global__ void fc1_k(const float* __restrict__ pool, const float* __restrict__ W,
                      const float* __restrict__ b, float* __restrict__ z) {
    int o = blockIdx.x, t = threadIdx.x;
    float s = 0.f;
    for (int i = t; i < 2 * HDIM; i += 256) s += pool[i] * W[(size_t)i * HDIM + o];
    s = blkSum(s);
    if (t == 0) z[o] = fmaxf(s + b[o], 0.f);
}
__global__ void fc2_k(const float* __restrict__ z, const float* __restrict__ W,
                      const float* __restrict__ b, float* __restrict__ out) {
    int o = blockIdx.x, t = threadIdx.x;
    float s = 0.f;
    for (int i = t; i < HDIM; i += 256) s += z[i] * W[(size_t)i * OUTD + o];
    s = blkSum(s);
    if (t == 0) out[o] = s + b[o];
}

// ---------------- host side ----------------
static float* sym(const void* s) {
    void* p = nullptr;
    cudaGetSymbolAddress(&p, (const void*)s);
    return (float*)p;
}

#define NODE  64,128,32,32

template<int BM,int BN,int WM,int WN,int TRANSB,int STAGES>
static void launch_tg(dim3 grid,
                      const float* A, int lda, long long sA,
                      const float* B, int ldb, long long sB,
                      float* C, int ldc, long long sC, int K,
                      const float* bias, long long sBias, int act)
{
    constexpr size_t sm = tg_smem<BM, BN, TRANSB, STAGES>();
    static bool attr_done = false;
    if (!attr_done) {
        cudaFuncSetAttribute(tgemm_k<BM,BN,WM,WN,TRANSB,STAGES>,
                             cudaFuncAttributeMaxDynamicSharedMemorySize, (int)sm);
        attr_done = true;
    }
    tgemm_k<BM,BN,WM,WN,TRANSB,STAGES><<<grid, 256, sm>>>(
        A, lda, sA, B, ldb, sB, C, ldc, sC, K, bias, sBias, act);
}

extern "C" void kernel_launch(void* const* d_in, const int* in_sizes, int n_in,
                              void* d_out, int out_size) {
    const float* x    = (const float*)d_in[0];
    const int*   ei   = (const int*)  d_in[1];
    const int*   ct   = (const int*)  d_in[2];
    const float* Wi   = (const float*)d_in[3];
    const float* bi   = (const float*)d_in[4];
    const float* Wq   = (const float*)d_in[5];
    const float* bq   = (const float*)d_in[6];
    const float* Wk   = (const float*)d_in[7];
    const float* bk   = (const float*)d_in[8];
    const float* Wv   = (const float*)d_in[9];
    const float* bv   = (const float*)d_in[10];
    const float* Bc   = (const float*)d_in[11];
    const float* cemb = (const float*)d_in[12];
    const float* Win  = (const float*)d_in[13];
    const float* binp = (const float*)d_in[14];
    const float* Wo   = (const float*)d_in[15];
    const float* bo   = (const float*)d_in[16];
    const float* Wm1  = (const float*)d_in[17];
    const float* bm1  = (const float*)d_in[18];
    const float* Wm2  = (const float*)d_in[19];
    const float* bm2  = (const float*)d_in[20];
    const float* Wm3  = (const float*)d_in[21];
    const float* bm3  = (const float*)d_in[22];
    const float* lng  = (const float*)d_in[23];
    const float* lnb  = (const float*)d_in[24];
    const float* Wc1  = (const float*)d_in[25];
    const float* bc1  = (const float*)d_in[26];
    const float* Wc2  = (const float*)d_in[27];
    const float* bc2  = (const float*)d_in[28];
    float* out = (float*)d_out;

    float* h    = sym(g_h);
    float* bufA = sym(g_bufA);
    float* bufB = sym(g_bufB);
    float* bufC = sym(g_bufC);
    float* bufD = sym(g_bufD);
    float* W3   = sym(g_W3);
    float* b3s  = sym(g_b3);
    float* Bc2  = sym(g_Bc2);
    float* vm   = sym(g_vm);
    float* gatt = sym(g_gatt);
    float* mo   = sym(g_mo);
    float* mha  = sym(g_mha);
    float* m2   = sym(g_m2);
    float* agg  = sym(g_agg);
    float* pool = sym(g_pool);
    float* z    = sym(g_z);
    unsigned* mask = (unsigned*)sym(g_mask);

    const int TPB = 256;

    static bool attrs = false;
    if (!attrs) {
        cudaFuncSetAttribute(flash_mha_k,
                             cudaFuncAttributeMaxDynamicSharedMemorySize, FLASH_SMEM);
        cudaFuncSetAttribute(egemm_gather_k,
                             cudaFuncAttributeMaxDynamicSharedMemorySize, EG_SMEM);
        cudaFuncSetAttribute(egemm_scatter_k,
                             cudaFuncAttributeMaxDynamicSharedMemorySize, ES_SMEM);
        attrs = true;
    }

    // adjacency mask + staged weights
    zero_u32_k<<<(NN * MW + TPB - 1) / TPB, TPB>>>(mask, NN * MW);
    build_mask_k<<<(EE + TPB - 1) / TPB, TPB>>>(ei, mask);
    stage_qkv_k<<<(2 * HDIM * QD + TPB - 1) / TPB, TPB>>>(Wq, Wk, Wv, bq, bk, bv, W3, b3s);
    stage_bc_k<<<(2 * QD * QD + TPB - 1) / TPB, TPB>>>(Bc, Bc2);

    // h = relu(x @ Wi + bi)
    launch_tg<NODE,0,3>(dim3(HDIM/128, NN/64, 1),
        x, IND, 0, Wi, HDIM, 0, h, HDIM, 0, IND, bi, 0, 1);

    for (int l = 0; l < LL; l++) {
        const float* ce_l  = cemb + (size_t)l * 50 * QD;
        const float* Win_l = Win + (size_t)l * QD * 3 * QD;
        const float* bin_l = binp + (size_t)l * 3 * QD;
        const float* Wo_l  = Wo  + (size_t)l * QD * QD;
        const float* Wm1_l = Wm1 + (size_t)l * (2 * HDIM + QD) * QD;
        const float* Wm2_l = Wm2 + (size_t)l * QD * QD;
        const float* Wm3_l = Wm3 + (size_t)l * QD * HDIM;

        dim3 gNode(QD/128, NN/64, 1);

        // batched Q/K/V projections -> bufA {Qt, Kt, V}
        launch_tg<NODE,0,3>(dim3(QD/128, NN/64, 3),
            h, HDIM, 0, W3 + (size_t)l * 3 * HDIM * QD, QD, (long long)HDIM * QD,
            bufA, QD, NNQD, HDIM, b3s + l * 3 * QD, QD, 0);
        // batched biological constraint: {Q,K} = {Qt@Bc, Kt@BcT}
        launch_tg<NODE,0,3>(dim3(QD/128, NN/64, 2),
            bufA, QD, NNQD, Bc2 + (size_t)l * 2 * QD * QD, QD, (long long)QD * QD,
            bufB, QD, NNQD, QD, nullptr, 0, 0);
        copy4_k<<<(NN * QD / 4 + TPB - 1) / TPB, TPB>>>(
            (const float4*)(bufA + 2 * NNQD), (float4*)(bufB + 2 * NNQD), NN * QD / 4);
        add_ce_k<<<(NN * QD / 4 + TPB - 1) / TPB, TPB>>>(
            (float4*)bufB, (float4*)(bufB + NNQD), (const float4*)ce_l, ct);

        // sparse graph-masked attention (exact)
        vmean_k<<<QD, 256>>>(bufB + 2 * NNQD, vm);
        sparse_gatt_k<<<NN, 128>>>(bufB, bufB + NNQD, bufB + 2 * NNQD, mask, vm,
                                   gatt, 0.0625f);

        // batched MHA input projections: bufC {mq, mk, mv}
        launch_tg<NODE,0,3>(dim3(QD/128, NN/64, 3),
            bufB, QD, NNQD, Win_l, 3*QD, QD,
            bufC, QD, NNQD, QD, bin_l, QD, 0);

        // fused flash MHA
        flash_mha_k<<<dim3(NN/FBQ, NHD), 256, FLASH_SMEM>>>(
            bufC, bufC + NNQD, bufC + 2 * NNQD, mo, 0.17677669529663687f);

        launch_tg<NODE,0,3>(gNode, mo, QD, 0, Wo_l, QD, 0, mha, QD, 0,
                            QD, bo + l * QD, 0, 0);

        // batched edge-MLP first layer halves: bufD {eA, eB}
        launch_tg<NODE,0,3>(dim3(QD/128, NN/64, 2),
            h, HDIM, 0, Wm1_l, QD, (long long)HDIM * QD,
            bufD, QD, NNQD, HDIM, nullptr, 0, 0);
        // fused gather-GEMM: m2 = relu(relu(eA[tgt]+eB[src]+bm1) @ Wm2 + bm2)
        egemm_gather_k<<<dim3(QD/128, EE/128), 256, EG_SMEM>>>(
            bufD, bufD + NNQD, bm1 + l * QD, ei, Wm2_l, bm2 + l * QD, m2);
        // fused scatter-GEMM: agg[tgt] += m2 @ Wm3 + bm3
        zero_f32_k<<<(NN * HDIM + TPB - 1) / TPB, TPB>>>(agg, NN * HDIM);
        egemm_scatter_k<<<dim3(HDIM/128, EE/128), 256, ES_SMEM>>>(
            m2, ei, Wm3_l, bm3 + l * HDIM, agg);

        // residual + aggregate + LN
        combine_ln_k<<<NN, HDIM>>>(h, agg, mha, gatt, lng + l * HDIM, lnb + l * HDIM);
    }

    // readout
    pool_k<<<2 * HDIM, 256>>>(h, pool);
    fc1_k<<<HDIM, 256>>>(pool, Wc1, bc1, z);
    fc2_k<<<OUTD, 256>>>(z, Wc2, bc2, out);
}

// round 9
// speedup vs baseline: 1.4155x; 1.4155x over previous
#include <cuda_runtime.h>
#include <math.h>

// ---------------- problem constants ----------------
#define NN   4096
#define EE   65536
#define IND  512
#define HDIM 256
#define QD   256
#define NHD  8
#define HD   32
#define OUTD 10
#define LL   2
#define MW   (NN/32)
#define NNQD ((long long)NN*QD)

// ---------------- static scratch ----------------
__device__ float    g_h   [NN*HDIM];
__device__ float    g_bufA[2*NN*QD];     // Qt, Kt
__device__ float    g_bufB[3*NN*QD];     // Q, K, V
__device__ float    g_bufC[3*NN*QD];     // mq, mk, mv
__device__ float    g_bufD[2*NN*QD];     // eA, eB
__device__ float    g_W3  [2*3*HDIM*QD];
__device__ float    g_b3  [2*3*QD];
__device__ float    g_Bc2 [2*2*QD*QD];   // staged [Bc | BcT] per layer
__device__ float    g_vm  [QD];
__device__ float    g_gatt[NN*QD];
__device__ float    g_mo  [NN*QD];
__device__ float    g_mha [NN*QD];
__device__ float    g_m1  [(size_t)EE*QD];   // m3 output (64MB)
__device__ float    g_m2  [(size_t)EE*QD];   // 64MB
__device__ unsigned g_mask[(size_t)NN*MW];
__device__ float    g_agg [NN*HDIM];
__device__ float    g_pool[2*HDIM];
__device__ float    g_z   [HDIM];

// ---------------- TF32 helpers ----------------
__device__ __forceinline__ unsigned f2tf(float f) {
    unsigned u;
    asm("cvt.rna.tf32.f32 %0, %1;" : "=r"(u) : "f"(f));
    return u;
}
__device__ __forceinline__ void mma_tf32(float* c, const unsigned* a, const unsigned* b) {
    asm volatile(
        "mma.sync.aligned.m16n8k8.row.col.f32.tf32.tf32.f32 "
        "{%0,%1,%2,%3}, {%4,%5,%6,%7}, {%8,%9}, {%0,%1,%2,%3};"
        : "+f"(c[0]), "+f"(c[1]), "+f"(c[2]), "+f"(c[3])
        : "r"(a[0]), "r"(a[1]), "r"(a[2]), "r"(a[3]), "r"(b[0]), "r"(b[1]));
}
__device__ __forceinline__ void cpasync16(void* sdst, const void* gsrc) {
    unsigned sa = (unsigned)__cvta_generic_to_shared(sdst);
    asm volatile("cp.async.cg.shared.global [%0], [%1], 16;\n" :: "r"(sa), "l"(gsrc));
}
#define CP_COMMIT() asm volatile("cp.async.commit_group;\n" ::: "memory")

// =====================================================================
// Generic TF32 GEMM (proven; batched via blockIdx.z)
// =====================================================================
template<int BM, int BN, int TRANSB, int STAGES>
constexpr size_t tg_smem() {
    return (size_t)STAGES * ((size_t)BM * 36 + (TRANSB ? (size_t)BN * 36
                                                       : (size_t)32 * (BN + 8))) * 4;
}

template<int BM, int BN, int WM, int WN, int TRANSB, int STAGES>
__global__ __launch_bounds__(256)
void tgemm_k(const float* __restrict__ A, int lda, long long sA,
             const float* __restrict__ B, int ldb, long long sB,
             float* __restrict__ C, int ldc, long long sC,
             int K,
             const float* __restrict__ bias, long long sBias, int act)
{
    constexpr int BK   = 32;
    constexpr int WX   = BN / WN;
    constexpr int WY   = BM / WM;
    static_assert(WX * WY == 8, "8 warps");
    constexpr int MM   = WM / 16;
    constexpr int MN   = WN / 8;
    constexpr int AL   = BM * (BK / 4) / 256;
    constexpr int BLt  = BN * (BK / 4) / 256;
    constexpr int BLn  = BK * (BN / 4) / 256;
    constexpr int ASTR = BK + 4;
    constexpr int BNSTR= BN + 8;
    constexpr int ASZ  = BM * ASTR;
    constexpr int BSZ  = TRANSB ? BN * ASTR : BK * BNSTR;

    const int tid  = threadIdx.x;
    const int wid  = tid >> 5;
    const int lane = tid & 31;
    const int wx   = wid % WX;
    const int wy   = wid / WX;
    const int lg   = lane >> 2;
    const int lt   = lane & 3;
    const int m0   = blockIdx.y * BM;
    const int n0   = blockIdx.x * BN;

    const float* Ab    = A + sA * blockIdx.z;
    const float* Bb    = B + sB * blockIdx.z;
    float*       Cb    = C + sC * blockIdx.z;
    const float* biasb = bias ? bias + sBias * blockIdx.z : nullptr;

    extern __shared__ float smem[];
    float* AsBase = smem;
    float* BsBase = smem + (size_t)STAGES * ASZ;

    auto load_stage = [&](int s, int k0) {
        float* as = AsBase + (size_t)s * ASZ;
#pragma unroll
        for (int j = 0; j < AL; j++) {
            int idx = tid + j * 256;
            int m   = idx >> 3;
            int k4  = idx & 7;
            cpasync16(&as[m * ASTR + k4 * 4],
                      &Ab[(size_t)(m0 + m) * lda + k0 + k4 * 4]);
        }
        float* bs = BsBase + (size_t)s * BSZ;
        if (TRANSB) {
#pragma unroll
            for (int j = 0; j < BLt; j++) {
                int idx = tid + j * 256;
                int n   = idx >> 3;
                int k4  = idx & 7;
                cpasync16(&bs[n * ASTR + k4 * 4],
                          &Bb[(size_t)(n0 + n) * ldb + k0 + k4 * 4]);
            }
        } else {
#pragma unroll
            for (int j = 0; j < BLn; j++) {
                int idx = tid + j * 256;
                int k   = idx / (BN / 4);
                int n4  = idx % (BN / 4);
                cpasync16(&bs[k * BNSTR + n4 * 4],
                          &Bb[(size_t)(k0 + k) * ldb + n0 + n4 * 4]);
            }
        }
    };

    float acc[MM][MN][4];
#pragma unroll
    for (int i = 0; i < MM; i++)
#pragma unroll
        for (int j = 0; j < MN; j++)
#pragma unroll
            for (int c = 0; c < 4; c++) acc[i][j][c] = 0.f;

    const int ktiles = K / BK;
#pragma unroll
    for (int s = 0; s < STAGES - 1; s++) {
        if (s < ktiles) load_stage(s, s * BK);
        CP_COMMIT();
    }

    for (int t = 0; t < ktiles; t++) {
        asm volatile("cp.async.wait_group %0;\n" :: "n"(STAGES - 2) : "memory");
        __syncthreads();

        int nt = t + STAGES - 1;
        if (nt < ktiles) load_stage(nt % STAGES, nt * BK);
        CP_COMMIT();

        const float* as = AsBase + (size_t)(t % STAGES) * ASZ;
        const float* bs = BsBase + (size_t)(t % STAGES) * BSZ;

#pragma unroll
        for (int ks = 0; ks < BK / 8; ks++) {
            const int kk = ks * 8;
            unsigned af[MM][4], bf[MN][2];
#pragma unroll
            for (int i = 0; i < MM; i++) {
                int row = wy * WM + i * 16 + lg;
                af[i][0] = f2tf(as[row * ASTR + kk + lt]);
                af[i][1] = f2tf(as[(row + 8) * ASTR + kk + lt]);
                af[i][2] = f2tf(as[row * ASTR + kk + lt + 4]);
                af[i][3] = f2tf(as[(row + 8) * ASTR + kk + lt + 4]);
            }
#pragma unroll
            for (int j = 0; j < MN; j++) {
                int col = wx * WN + j * 8 + lg;
                if (TRANSB) {
                    bf[j][0] = f2tf(bs[col * ASTR + kk + lt]);
                    bf[j][1] = f2tf(bs[col * ASTR + kk + lt + 4]);
                } else {
                    bf[j][0] = f2tf(bs[(kk + lt) * BNSTR + col]);
                    bf[j][1] = f2tf(bs[(kk + lt + 4) * BNSTR + col]);
                }
            }
#pragma unroll
            for (int i = 0; i < MM; i++)
#pragma unroll
                for (int j = 0; j < MN; j++)
                    mma_tf32(acc[i][j], af[i], bf[j]);
        }
        __syncthreads();
    }

#pragma unroll
    for (int i = 0; i < MM; i++) {
        int mA = m0 + wy * WM + i * 16 + lg;
        int mB = mA + 8;
#pragma unroll
        for (int j = 0; j < MN; j++) {
            int n = n0 + wx * WN + j * 8 + lt * 2;
            float b0 = biasb ? biasb[n] : 0.f;
            float b1 = biasb ? biasb[n + 1] : 0.f;
            float v0 = acc[i][j][0] + b0;
            float v1 = acc[i][j][1] + b1;
            float v2 = acc[i][j][2] + b0;
            float v3 = acc[i][j][3] + b1;
            if (act == 1) {
                v0 = fmaxf(v0, 0.f); v1 = fmaxf(v1, 0.f);
                v2 = fmaxf(v2, 0.f); v3 = fmaxf(v3, 0.f);
            }
            Cb[(size_t)mA * ldc + n]     = v0;
            Cb[(size_t)mA * ldc + n + 1] = v1;
            Cb[(size_t)mB * ldc + n]     = v2;
            Cb[(size_t)mB * ldc + n + 1] = v3;
        }
    }
}

// =====================================================================
// Edge gather-GEMM v2: m2 = relu( relu(eA[tgt]+eB[src]+bm1) @ Wm2 + bm2 )
//  Gathered rows fetched via cp.async into DOUBLE-BUFFERED smem tiles;
//  relu(a+b+bias) applied at fragment load (registers) — no extra barrier.
//  BM=128, BN=128, BK=32, K=256. 8 warps (WM=64, WN=32).
// =====================================================================
#define EG_ASTR 36
#define EG_BSTR 136
#define EG_SMEM ((4*128*EG_ASTR + 2*32*EG_BSTR) * 4)   // 108544 B

__global__ __launch_bounds__(256)
void egemm_gather_k(const float* __restrict__ eA, const float* __restrict__ eB,
                    const float* __restrict__ b1, const int* __restrict__ ei,
                    const float* __restrict__ W, const float* __restrict__ b2,
                    float* __restrict__ C)
{
    __shared__ int   tgts[128], srcs[128];
    __shared__ float b1s[256];
    extern __shared__ float smem[];
    float* AsA = smem;                       // [2][128][36]  eA[tgt] tiles
    float* AsB = smem + 2 * 128 * EG_ASTR;   // [2][128][36]  eB[src] tiles
    float* Bs  = smem + 4 * 128 * EG_ASTR;   // [2][32][136]  W tiles

    const int tid  = threadIdx.x;
    const int wid  = tid >> 5;
    const int lane = tid & 31;
    const int wx   = wid & 3;
    const int wy   = wid >> 2;
    const int lg   = lane >> 2;
    const int lt   = lane & 3;
    const int m0   = blockIdx.y * 128;
    const int n0   = blockIdx.x * 128;

    if (tid < 128) { srcs[tid] = ei[m0 + tid]; tgts[tid] = ei[EE + m0 + tid]; }
    b1s[tid] = b1[tid];
    __syncthreads();

    auto load_stage = [&](int s, int k0) {
        float* aA = AsA + s * 128 * EG_ASTR;
        float* aB = AsB + s * 128 * EG_ASTR;
#pragma unroll
        for (int j = 0; j < 4; j++) {
            int idx = tid + j * 256;
            int m = idx >> 3, k4 = idx & 7;
            cpasync16(&aA[m * EG_ASTR + k4 * 4],
                      &eA[(size_t)tgts[m] * QD + k0 + k4 * 4]);
            cpasync16(&aB[m * EG_ASTR + k4 * 4],
                      &eB[(size_t)srcs[m] * QD + k0 + k4 * 4]);
        }
        float* bs = Bs + s * 32 * EG_BSTR;
#pragma unroll
        for (int j = 0; j < 4; j++) {
            int idx = tid + j * 256;
            int k = idx >> 5, n4 = idx & 31;
            cpasync16(&bs[k * EG_BSTR + n4 * 4],
                      &W[(size_t)(k0 + k) * QD + n0 + n4 * 4]);
        }
    };
    load_stage(0, 0);
    CP_COMMIT();

    float acc[4][4][4];
#pragma unroll
    for (int i = 0; i < 4; i++)
#pragma unroll
        for (int j = 0; j < 4; j++)
#pragma unroll
            for (int c = 0; c < 4; c++) acc[i][j][c] = 0.f;

    for (int t = 0; t < 8; t++) {
        if (t + 1 < 8) load_stage((t + 1) & 1, (t + 1) * 32);
        CP_COMMIT();
        asm volatile("cp.async.wait_group 1;\n" ::: "memory");
        __syncthreads();

        const float* aA = AsA + (t & 1) * 128 * EG_ASTR;
        const float* aB = AsB + (t & 1) * 128 * EG_ASTR;
        const float* bs = Bs  + (t & 1) * 32 * EG_BSTR;
        const int kg0 = t * 32;

#pragma unroll
        for (int ks = 0; ks < 4; ks++) {
            const int kk = ks * 8;
            const float bA0 = b1s[kg0 + kk + lt];
            const float bA1 = b1s[kg0 + kk + lt + 4];
            unsigned af[4][4], bf[4][2];
#pragma unroll
            for (int i = 0; i < 4; i++) {
                int row = wy * 64 + i * 16 + lg;
                af[i][0] = f2tf(fmaxf(aA[row * EG_ASTR + kk + lt] +
                                      aB[row * EG_ASTR + kk + lt] + bA0, 0.f));
                af[i][1] = f2tf(fmaxf(aA[(row + 8) * EG_ASTR + kk + lt] +
                                      aB[(row + 8) * EG_ASTR + kk + lt] + bA0, 0.f));
                af[i][2] = f2tf(fmaxf(aA[row * EG_ASTR + kk + lt + 4] +
                                      aB[row * EG_ASTR + kk + lt + 4] + bA1, 0.f));
                af[i][3] = f2tf(fmaxf(aA[(row + 8) * EG_ASTR + kk + lt + 4] +
                                      aB[(row + 8) * EG_ASTR + kk + lt + 4] + bA1, 0.f));
            }
#pragma unroll
            for (int j = 0; j < 4; j++) {
                int col = wx * 32 + j * 8 + lg;
                bf[j][0] = f2tf(bs[(kk + lt) * EG_BSTR + col]);
                bf[j][1] = f2tf(bs[(kk + lt + 4) * EG_BSTR + col]);
            }
#pragma unroll
            for (int i = 0; i < 4; i++)
#pragma unroll
                for (int j = 0; j < 4; j++)
                    mma_tf32(acc[i][j], af[i], bf[j]);
        }
        __syncthreads();
    }

#pragma unroll
    for (int i = 0; i < 4; i++) {
        int mA = m0 + wy * 64 + i * 16 + lg;
        int mB = mA + 8;
#pragma unroll
        for (int j = 0; j < 4; j++) {
            int n = n0 + wx * 32 + j * 8 + lt * 2;
            float b0 = b2[n], b1v = b2[n + 1];
            C[(size_t)mA * QD + n]     = fmaxf(acc[i][j][0] + b0, 0.f);
            C[(size_t)mA * QD + n + 1] = fmaxf(acc[i][j][1] + b1v, 0.f);
            C[(size_t)mB * QD + n]     = fmaxf(acc[i][j][2] + b0, 0.f);
            C[(size_t)mB * QD + n + 1] = fmaxf(acc[i][j][3] + b1v, 0.f);
        }
    }
}

// =====================================================================
// Flash MHA (proven, unchanged)
// =====================================================================
#define FBQ   128
#define FBKV  64
#define QSTR  36
#define KSTR  36
#define VSTR  40
#define PSTR  68
#define FLASH_SMEM ((FBQ*QSTR + 2*FBKV*KSTR + 2*FBKV*VSTR + 8*16*PSTR) * 4)

__global__ __launch_bounds__(256)
void flash_mha_k(const float* __restrict__ mq, const float* __restrict__ mk,
                 const float* __restrict__ mv, float* __restrict__ mo, float scale)
{
    extern __shared__ float sm[];
    float*    Qs = sm;
    float*    Ks = Qs + FBQ * QSTR;
    float*    Vs = Ks + 2 * FBKV * KSTR;
    unsigned* Ps = (unsigned*)(Vs + 2 * FBKV * VSTR);

    const int tid  = threadIdx.x;
    const int wid  = tid >> 5;
    const int lane = tid & 31;
    const int lg   = lane >> 2;
    const int lt   = lane & 3;
    const int hh   = blockIdx.y;
    const int q0   = blockIdx.x * FBQ;

    const float* Qg = mq + (size_t)q0 * QD + hh * HD;
    const float* Kg = mk + hh * HD;
    const float* Vg = mv + hh * HD;

#pragma unroll
    for (int j = 0; j < 4; j++) {
        int idx = tid + j * 256;
        int r = idx >> 3, c4 = idx & 7;
        cpasync16(&Qs[r * QSTR + c4 * 4], &Qg[(size_t)r * QD + c4 * 4]);
    }
    auto loadKV = [&](int s, int kv0) {
        float* ks = Ks + s * FBKV * KSTR;
        float* vs = Vs + s * FBKV * VSTR;
#pragma unroll
        for (int j = 0; j < 2; j++) {
            int idx = tid + j * 256;
            int r = idx >> 3, c4 = idx & 7;
            cpasync16(&ks[r * KSTR + c4 * 4], &Kg[(size_t)(kv0 + r) * QD + c4 * 4]);
        }
#pragma unroll
        for (int j = 0; j < 2; j++) {
            int idx = tid + j * 256;
            int r = idx >> 3, c4 = idx & 7;
            cpasync16(&vs[r * VSTR + c4 * 4], &Vg[(size_t)(kv0 + r) * QD + c4 * 4]);
        }
    };
    loadKV(0, 0);
    CP_COMMIT();

    float O[4][4];
#pragma unroll
    for (int j = 0; j < 4; j++)
#pragma unroll
        for (int c = 0; c < 4; c++) O[j][c] = 0.f;
    float m0r = -3.4e38f, m1r = -3.4e38f;
    float l0 = 0.f, l1 = 0.f;
    unsigned* Pw = Ps + wid * 16 * PSTR;
    const int qrow = wid * 16 + lg;

    const int NT = NN / FBKV;
    for (int t = 0; t < NT; t++) {
        if (t + 1 < NT) loadKV((t + 1) & 1, (t + 1) * FBKV);
        CP_COMMIT();
        asm volatile("cp.async.wait_group 1;\n" ::: "memory");
        __syncthreads();

        const float* ks = Ks + (t & 1) * FBKV * KSTR;
        const float* vs = Vs + (t & 1) * FBKV * VSTR;

        float Sacc[8][4];
#pragma unroll
        for (int n = 0; n < 8; n++)
#pragma unroll
            for (int c = 0; c < 4; c++) Sacc[n][c] = 0.f;
#pragma unroll
        for (int ks8 = 0; ks8 < 4; ks8++) {
            const int kk = ks8 * 8;
            unsigned af[4];
            af[0] = f2tf(Qs[qrow * QSTR + kk + lt]);
            af[1] = f2tf(Qs[(qrow + 8) * QSTR + kk + lt]);
            af[2] = f2tf(Qs[qrow * QSTR + kk + lt + 4]);
            af[3] = f2tf(Qs[(qrow + 8) * QSTR + kk + lt + 4]);
#pragma unroll
            for (int n = 0; n < 8; n++) {
                int col = n * 8 + lg;
                unsigned bf[2];
                bf[0] = f2tf(ks[col * KSTR + kk + lt]);
                bf[1] = f2tf(ks[col * KSTR + kk + lt + 4]);
                mma_tf32(Sacc[n], af, bf);
            }
        }

        float mx0 = -3.4e38f, mx1 = -3.4e38f;
#pragma unroll
        for (int n = 0; n < 8; n++) {
            Sacc[n][0] *= scale; Sacc[n][1] *= scale;
            Sacc[n][2] *= scale; Sacc[n][3] *= scale;
            mx0 = fmaxf(mx0, fmaxf(Sacc[n][0], Sacc[n][1]));
            mx1 = fmaxf(mx1, fmaxf(Sacc[n][2], Sacc[n][3]));
        }
        mx0 = fmaxf(mx0, __shfl_xor_sync(0xffffffffu, mx0, 1));
        mx0 = fmaxf(mx0, __shfl_xor_sync(0xffffffffu, mx0, 2));
        mx1 = fmaxf(mx1, __shfl_xor_sync(0xffffffffu, mx1, 1));
        mx1 = fmaxf(mx1, __shfl_xor_sync(0xffffffffu, mx1, 2));
        float mn0 = fmaxf(m0r, mx0), mn1 = fmaxf(m1r, mx1);
        float a0 = __expf(m0r - mn0), a1 = __expf(m1r - mn1);
        float rs0 = 0.f, rs1 = 0.f;
#pragma unroll
        for (int n = 0; n < 8; n++) {
            float p0 = __expf(Sacc[n][0] - mn0);
            float p1 = __expf(Sacc[n][1] - mn0);
            float p2 = __expf(Sacc[n][2] - mn1);
            float p3 = __expf(Sacc[n][3] - mn1);
            rs0 += p0 + p1; rs1 += p2 + p3;
            int c0 = n * 8 + lt * 2;
            Pw[lg * PSTR + c0]           = f2tf(p0);
            Pw[lg * PSTR + c0 + 1]       = f2tf(p1);
            Pw[(lg + 8) * PSTR + c0]     = f2tf(p2);
            Pw[(lg + 8) * PSTR + c0 + 1] = f2tf(p3);
        }
        rs0 += __shfl_xor_sync(0xffffffffu, rs0, 1);
        rs0 += __shfl_xor_sync(0xffffffffu, rs0, 2);
        rs1 += __shfl_xor_sync(0xffffffffu, rs1, 1);
        rs1 += __shfl_xor_sync(0xffffffffu, rs1, 2);
        l0 = l0 * a0 + rs0;
        l1 = l1 * a1 + rs1;
        m0r = mn0; m1r = mn1;
#pragma unroll
        for (int j = 0; j < 4; j++) {
            O[j][0] *= a0; O[j][1] *= a0;
            O[j][2] *= a1; O[j][3] *= a1;
        }
        __syncwarp();

#pragma unroll
        for (int ks8 = 0; ks8 < 8; ks8++) {
            const int kk = ks8 * 8;
            unsigned af[4];
            af[0] = Pw[lg * PSTR + kk + lt];
            af[1] = Pw[(lg + 8) * PSTR + kk + lt];
            af[2] = Pw[lg * PSTR + kk + lt + 4];
            af[3] = Pw[(lg + 8) * PSTR + kk + lt + 4];
#pragma unroll
            for (int j = 0; j < 4; j++) {
                int col = j * 8 + lg;
                unsigned bf[2];
                bf[0] = f2tf(vs[(kk + lt) * VSTR + col]);
                bf[1] = f2tf(vs[(kk + lt + 4) * VSTR + col]);
                mma_tf32(O[j], af, bf);
            }
        }
        __syncwarp();
        __syncthreads();
    }

    float inv0 = 1.f / l0, inv1 = 1.f / l1;
    const size_t rA = (size_t)(q0 + qrow) * QD + hh * HD;
    const size_t rB = rA + 8 * QD;
#pragma unroll
    for (int j = 0; j < 4; j++) {
        int c = j * 8 + lt * 2;
        mo[rA + c]     = O[j][0] * inv0;
        mo[rA + c + 1] = O[j][1] * inv0;
        mo[rB + c]     = O[j][2] * inv1;
        mo[rB + c + 1] = O[j][3] * inv1;
    }
}

// =====================================================================
// Sparse graph attention (proven, unchanged)
// =====================================================================
__global__ __launch_bounds__(128)
void sparse_gatt_k(const float* __restrict__ Q, const float* __restrict__ K,
                   const float* __restrict__ V, const unsigned* __restrict__ mask,
                   const float* __restrict__ vmean, float* __restrict__ gatt,
                   float scale)
{
    __shared__ int   idxs[NN];
    __shared__ float sc  [NN];
    __shared__ int   wbase[5];
    __shared__ float red[4];

    const int s    = blockIdx.x;
    const int tid  = threadIdx.x;
    const int wid  = tid >> 5;
    const int lane = tid & 31;

    unsigned w = mask[(size_t)s * MW + tid];
    int c = __popc(w);
    int pre = c;
#pragma unroll
    for (int o = 1; o < 32; o <<= 1) {
        int v = __shfl_up_sync(0xffffffffu, pre, o);
        if (lane >= o) pre += v;
    }
    if (lane == 31) wbase[wid + 1] = pre;
    __syncthreads();
    if (tid == 0) {
        wbase[0] = 0;
        wbase[2] += wbase[1];
        wbase[3] += wbase[2];
        wbase[4] += wbase[3];
    }
    __syncthreads();
    const int cnt = wbase[4];
    int p = wbase[wid] + pre - c;
    unsigned ww = w;
    while (ww) {
        int b = __ffs(ww) - 1;
        idxs[p++] = tid * 32 + b;
        ww &= ww - 1;
    }
    __syncthreads();

    const int c0 = tid * 2;
    if (cnt == 0) {
        gatt[(size_t)s * QD + c0]     = vmean[c0];
        gatt[(size_t)s * QD + c0 + 1] = vmean[c0 + 1];
        return;
    }

    float q[8];
    const float* Qr = Q + (size_t)s * QD;
#pragma unroll
    for (int i = 0; i < 8; i++) q[i] = Qr[lane * 8 + i];
    for (int e = wid; e < cnt; e += 4) {
        const float* Kr = K + (size_t)idxs[e] * QD;
        float d = 0.f;
#pragma unroll
        for (int i = 0; i < 8; i++) d = fmaf(q[i], Kr[lane * 8 + i], d);
#pragma unroll
        for (int o = 16; o; o >>= 1) d += __shfl_xor_sync(0xffffffffu, d, o);
        if (lane == 0) sc[e] = d * scale;
    }
    __syncthreads();

    float mx = -3.4e38f;
    for (int e = tid; e < cnt; e += 128) mx = fmaxf(mx, sc[e]);
#pragma unroll
    for (int o = 16; o; o >>= 1) mx = fmaxf(mx, __shfl_xor_sync(0xffffffffu, mx, o));
    if (lane == 0) red[wid] = mx;
    __syncthreads();
    mx = fmaxf(fmaxf(red[0], red[1]), fmaxf(red[2], red[3]));
    __syncthreads();

    float sum = 0.f;
    for (int e = tid; e < cnt; e += 128) {
        float pe = __expf(sc[e] - mx);
        sc[e] = pe;
        sum += pe;
    }
#pragma unroll
    for (int o = 16; o; o >>= 1) sum += __shfl_xor_sync(0xffffffffu, sum, o);
    if (lane == 0) red[wid] = sum;
    __syncthreads();
    float inv = 1.f / (red[0] + red[1] + red[2] + red[3]);

    float a0 = 0.f, a1 = 0.f;
    for (int e = 0; e < cnt; e++) {
        const float* Vr = V + (size_t)idxs[e] * QD;
        float pe = sc[e];
        a0 = fmaf(pe, Vr[c0], a0);
        a1 = fmaf(pe, Vr[c0 + 1], a1);
    }
    gatt[(size_t)s * QD + c0]     = a0 * inv;
    gatt[(size_t)s * QD + c0 + 1] = a1 * inv;
}

// ---------------- block reductions ----------------
__device__ __forceinline__ float blkMax(float v) {
    __shared__ float sh[8];
#pragma unroll
    for (int o = 16; o; o >>= 1) v = fmaxf(v, __shfl_xor_sync(0xffffffffu, v, o));
    if ((threadIdx.x & 31) == 0) sh[threadIdx.x >> 5] = v;
    __syncthreads();
    if (threadIdx.x < 32) {
        float w = (threadIdx.x < 8) ? sh[threadIdx.x] : -3.4e38f;
#pragma unroll
        for (int o = 4; o; o >>= 1) w = fmaxf(w, __shfl_xor_sync(0xffffffffu, w, o));
        if (threadIdx.x == 0) sh[0] = w;
    }
    __syncthreads();
    float r = sh[0];
    __syncthreads();
    return r;
}
__device__ __forceinline__ float blkSum(float v) {
    __shared__ float sh[8];
#pragma unroll
    for (int o = 16; o; o >>= 1) v += __shfl_xor_sync(0xffffffffu, v, o);
    if ((threadIdx.x & 31) == 0) sh[threadIdx.x >> 5] = v;
    __syncthreads();
    if (threadIdx.x < 32) {
        float w = (threadIdx.x < 8) ? sh[threadIdx.x] : 0.f;
#pragma unroll
        for (int o = 4; o; o >>= 1) w += __shfl_xor_sync(0xffffffffu, w, o);
        if (threadIdx.x == 0) sh[0] = w;
    }
    __syncthreads();
    float r = sh[0];
    __syncthreads();
    return r;
}

// ---------------- elementwise / small kernels ----------------
__global__ void zero_u32_k(unsigned* __restrict__ p, int n) {
    int i = blockIdx.x * blockDim.x + threadIdx.x;
    if (i < n) p[i] = 0u;
}
__global__ void zero_f32_k(float* __restrict__ p, int n) {
    int i = blockIdx.x * blockDim.x + threadIdx.x;
    if (i < n) p[i] = 0.f;
}
__global__ void build_mask_k(const int* __restrict__ ei, unsigned* __restrict__ mask) {
    int e = blockIdx.x * blockDim.x + threadIdx.x;
    if (e >= EE) return;
    int s = ei[e], t = ei[EE + e];
    atomicOr(&mask[(size_t)s * MW + (t >> 5)], 1u << (t & 31));
}
__global__ void stage_qkv_k(const float* __restrict__ Wq, const float* __restrict__ Wk,
                            const float* __restrict__ Wv, const float* __restrict__ bq,
                            const float* __restrict__ bk, const float* __restrict__ bv,
                            float* __restrict__ W3, float* __restrict__ b3) {
    int i = blockIdx.x * blockDim.x + threadIdx.x;
    const int per = HDIM * QD;
    if (i < 2 * per) {
        int l = i / per, r = i % per;
        W3[((size_t)l * 3 + 0) * per + r] = Wq[i];
        W3[((size_t)l * 3 + 1) * per + r] = Wk[i];
        W3[((size_t)l * 3 + 2) * per + r] = Wv[i];
    }
    if (i < 2 * QD) {
        int l = i / QD, r = i % QD;
        b3[(l * 3 + 0) * QD + r] = bq[i];
        b3[(l * 3 + 1) * QD + r] = bk[i];
        b3[(l * 3 + 2) * QD + r] = bv[i];
    }
}
__global__ void stage_bc_k(const float* __restrict__ Bc, float* __restrict__ Bc2) {
    int i = blockIdx.x * blockDim.x + threadIdx.x;
    if (i >= 2 * QD * QD) return;
    int l = i / (QD * QD), r = i % (QD * QD);
    int row = r / QD, col = r % QD;
    Bc2[((size_t)l * 2 + 0) * QD * QD + r] = Bc[i];
    Bc2[((size_t)l * 2 + 1) * QD * QD + (size_t)row * QD + col] =
        Bc[(size_t)l * QD * QD + (size_t)col * QD + row];
}
__global__ void vmean_k(const float* __restrict__ V, float* __restrict__ vm) {
    int c = blockIdx.x;
    float s = 0.f;
    for (int r = threadIdx.x; r < NN; r += 256) s += V[(size_t)r * QD + c];
    s = blkSum(s);
    if (threadIdx.x == 0) vm[c] = s * (1.f / NN);
}
__global__ void add_ce_k(float4* __restrict__ Q, float4* __restrict__ K,
                         const float4* __restrict__ ce, const int* __restrict__ ct) {
    int idx = blockIdx.x * blockDim.x + threadIdx.x;
    if (idx >= NN * (QD / 4)) return;
    int i = idx >> 6, j4 = idx & 63;
    float4 c = ce[ct[i] * (QD / 4) + j4];
    float4 q = Q[idx], k = K[idx];
    q.x += 0.1f * c.x; q.y += 0.1f * c.y; q.z += 0.1f * c.z; q.w += 0.1f * c.w;
    k.x += 0.1f * c.x; k.y += 0.1f * c.y; k.z += 0.1f * c.z; k.w += 0.1f * c.w;
    Q[idx] = q; K[idx] = k;
}
__global__ void scatter_k(const float4* __restrict__ m3, const int* __restrict__ ei,
                          float* __restrict__ agg) {
    int idx = blockIdx.x * blockDim.x + threadIdx.x;
    if (idx >= EE * (HDIM / 4)) return;
    int e = idx >> 6, j4 = idx & 63;
    float4 v = m3[idx];
    float* dst = agg + (size_t)ei[EE + e] * HDIM + j4 * 4;
    atomicAdd(dst + 0, v.x);
    atomicAdd(dst + 1, v.y);
    atomicAdd(dst + 2, v.z);
    atomicAdd(dst + 3, v.w);
}
__global__ void combine_ln_k(float* __restrict__ h, const float* __restrict__ agg,
                             const float* __restrict__ mha, const float* __restrict__ gatt,
                             const float* __restrict__ g, const float* __restrict__ b) {
    int r = blockIdx.x, j = threadIdx.x;
    size_t idx = (size_t)r * HDIM + j;
    float v = h[idx] + agg[idx] + mha[idx] + gatt[idx];
    float mu = blkSum(v) * (1.f / HDIM);
    float d = v - mu;
    float var = blkSum(d * d) * (1.f / HDIM);
    h[idx] = d * rsqrtf(var + 1e-5f) * g[j] + b[j];
}
__global__ void pool_k(const float* __restrict__ h, float* __restrict__ pool) {
    int c = blockIdx.x, t = threadIdx.x;
    if (c < HDIM) {
        float s = 0.f;
        for (int r = t; r < NN; r += 256) s += h[(size_t)r * HDIM + c];
        s = blkSum(s);
        if (t == 0) pool[c] = s * (1.f / NN);
    } else {
        int cc = c - HDIM;
        float m = -3.4e38f;
        for (int r = t; r < NN; r += 256) m = fmaxf(m, h[(size_t)r * HDIM + cc]);
        m = blkMax(m);
        if (t == 0) pool[c] = m;
    }
}
__global__ void fc1_k(const float* __restrict__ pool, const float* __restrict__ W,
                      const float* __restrict__ b, float* __restrict__ z) {
    int o = blockIdx.x, t = threadIdx.x;
    float s = 0.f;
    for (int i = t; i < 2 * HDIM; i += 256) s += pool[i] * W[(size_t)i * HDIM + o];
    s = blkSum(s);
    if (t == 0) z[o] = fmaxf(s + b[o], 0.f);
}
__global__ void fc2_k(const float* __restrict__ z, const float* __restrict__ W,
                      const float* __restrict__ b, float* __restrict__ out) {
    int o = blockIdx.x, t = threadIdx.x;
    float s = 0.f;
    for (int i = t; i < HDIM; i += 256) s += z[i] * W[(size_t)i * OUTD + o];
    s = blkSum(s);
    if (t == 0) out[o] = s + b[o];
}

// ---------------- host side ----------------
static float* sym(const void* s) {
    void* p = nullptr;
    cudaGetSymbolAddress(&p, (const void*)s);
    return (float*)p;
}

#define BIG   128,128,64,32
#define NODE  64,128,32,32

template<int BM,int BN,int WM,int WN,int TRANSB,int STAGES>
static void launch_tg(dim3 grid,
                      const float* A, int lda, long long sA,
                      const float* B, int ldb, long long sB,
                      float* C, int ldc, long long sC, int K,
                      const float* bias, long long sBias, int act)
{
    constexpr size_t sm = tg_smem<BM, BN, TRANSB, STAGES>();
    static bool attr_done = false;
    if (!attr_done) {
        cudaFuncSetAttribute(tgemm_k<BM,BN,WM,WN,TRANSB,STAGES>,
                             cudaFuncAttributeMaxDynamicSharedMemorySize, (int)sm);
        attr_done = true;
    }
    tgemm_k<BM,BN,WM,WN,TRANSB,STAGES><<<grid, 256, sm>>>(
        A, lda, sA, B, ldb, sB, C, ldc, sC, K, bias, sBias, act);
}

extern "C" void kernel_launch(void* const* d_in, const int* in_sizes, int n_in,
                              void* d_out, int out_size) {
    const float* x    = (const float*)d_in[0];
    const int*   ei   = (const int*)  d_in[1];
    const int*   ct   = (const int*)  d_in[2];
    const float* Wi   = (const float*)d_in[3];
    const float* bi   = (const float*)d_in[4];
    const float* Wq   = (const float*)d_in[5];
    const float* bq   = (const float*)d_in[6];
    const float* Wk   = (const float*)d_in[7];
    const float* bk   = (const float*)d_in[8];
    const float* Wv   = (const float*)d_in[9];
    const float* bv   = (const float*)d_in[10];
    const float* Bc   = (const float*)d_in[11];
    const float* cemb = (const float*)d_in[12];
    const float* Win  = (const float*)d_in[13];
    const float* binp = (const float*)d_in[14];
    const float* Wo   = (const float*)d_in[15];
    const float* bo   = (const float*)d_in[16];
    const float* Wm1  = (const float*)d_in[17];
    const float* bm1  = (const float*)d_in[18];
    const float* Wm2  = (const float*)d_in[19];
    const float* bm2  = (const float*)d_in[20];
    const float* Wm3  = (const float*)d_in[21];
    const float* bm3  = (const float*)d_in[22];
    const float* lng  = (const float*)d_in[23];
    const float* lnb  = (const float*)d_in[24];
    const float* Wc1  = (const float*)d_in[25];
    const float* bc1  = (const float*)d_in[26];
    const float* Wc2  = (const float*)d_in[27];
    const float* bc2  = (const float*)d_in[28];
    float* out = (float*)d_out;

    float* h    = sym(g_h);
    float* bufA = sym(g_bufA);
    float* bufB = sym(g_bufB);
    float* bufC = sym(g_bufC);
    float* bufD = sym(g_bufD);
    float* W3   = sym(g_W3);
    float* b3s  = sym(g_b3);
    float* Bc2  = sym(g_Bc2);
    float* vm   = sym(g_vm);
    float* gatt = sym(g_gatt);
    float* mo   = sym(g_mo);
    float* mha  = sym(g_mha);
    float* m1   = sym(g_m1);
    float* m2   = sym(g_m2);
    float* agg  = sym(g_agg);
    float* pool = sym(g_pool);
    float* z    = sym(g_z);
    unsigned* mask = (unsigned*)sym(g_mask);

    const int TPB = 256;
    const long long HQD = (long long)HDIM * QD;

    static bool attrs = false;
    if (!attrs) {
        cudaFuncSetAttribute(flash_mha_k,
                             cudaFuncAttributeMaxDynamicSharedMemorySize, FLASH_SMEM);
        cudaFuncSetAttribute(egemm_gather_k,
                             cudaFuncAttributeMaxDynamicSharedMemorySize, EG_SMEM);
        attrs = true;
    }

    // adjacency mask + staged weights
    zero_u32_k<<<(NN * MW + TPB - 1) / TPB, TPB>>>(mask, NN * MW);
    build_mask_k<<<(EE + TPB - 1) / TPB, TPB>>>(ei, mask);
    stage_qkv_k<<<(2 * HDIM * QD + TPB - 1) / TPB, TPB>>>(Wq, Wk, Wv, bq, bk, bv, W3, b3s);
    stage_bc_k<<<(2 * QD * QD + TPB - 1) / TPB, TPB>>>(Bc, Bc2);

    // h = relu(x @ Wi + bi)
    launch_tg<NODE,0,3>(dim3(HDIM/128, NN/64, 1),
        x, IND, 0, Wi, HDIM, 0, h, HDIM, 0, IND, bi, 0, 1);

    for (int l = 0; l < LL; l++) {
        const float* ce_l  = cemb + (size_t)l * 50 * QD;
        const float* Win_l = Win + (size_t)l * QD * 3 * QD;
        const float* bin_l = binp + (size_t)l * 3 * QD;
        const float* Wo_l  = Wo  + (size_t)l * QD * QD;
        const float* Wm1_l = Wm1 + (size_t)l * (2 * HDIM + QD) * QD;
        const float* Wm2_l = Wm2 + (size_t)l * QD * QD;
        const float* Wm3_l = Wm3 + (size_t)l * QD * HDIM;

        dim3 gNode(QD/128, NN/64, 1);

        // batched {Qt,Kt} projections -> bufA ; V directly -> bufB[2]
        launch_tg<NODE,0,3>(dim3(QD/128, NN/64, 2),
            h, HDIM, 0, W3 + (size_t)l * 3 * HQD, QD, HQD,
            bufA, QD, NNQD, HDIM, b3s + l * 3 * QD, QD, 0);
        launch_tg<NODE,0,3>(gNode,
            h, HDIM, 0, W3 + (size_t)l * 3 * HQD + 2 * HQD, QD, 0,
            bufB + 2 * NNQD, QD, 0, HDIM, b3s + l * 3 * QD + 2 * QD, 0, 0);
        // batched biological constraint: {Q,K} = {Qt@Bc, Kt@BcT}
        launch_tg<NODE,0,3>(dim3(QD/128, NN/64, 2),
            bufA, QD, NNQD, Bc2 + (size_t)l * 2 * QD * QD, QD, (long long)QD * QD,
            bufB, QD, NNQD, QD, nullptr, 0, 0);
        add_ce_k<<<(NN * QD / 4 + TPB - 1) / TPB, TPB>>>(
            (float4*)bufB, (float4*)(bufB + NNQD), (const float4*)ce_l, ct);

        // sparse graph-masked attention (exact)
        vmean_k<<<QD, 256>>>(bufB + 2 * NNQD, vm);
        sparse_gatt_k<<<NN, 128>>>(bufB, bufB + NNQD, bufB + 2 * NNQD, mask, vm,
                                   gatt, 0.0625f);

        // batched MHA input projections: bufC {mq, mk, mv}
        launch_tg<NODE,0,3>(dim3(QD/128, NN/64, 3),
            bufB, QD, NNQD, Win_l, 3*QD, QD,
            bufC, QD, NNQD, QD, bin_l, QD, 0);

        // fused flash MHA
        flash_mha_k<<<dim3(NN/FBQ, NHD), 256, FLASH_SMEM>>>(
            bufC, bufC + NNQD, bufC + 2 * NNQD, mo, 0.17677669529663687f);

        launch_tg<NODE,0,3>(gNode, mo, QD, 0, Wo_l, QD, 0, mha, QD, 0,
                            QD, bo + l * QD, 0, 0);

        // batched edge-MLP first layer halves: bufD {eA, eB}
        launch_tg<NODE,0,3>(dim3(QD/128, NN/64, 2),
            h, HDIM, 0, Wm1_l, QD, HQD,
            bufD, QD, NNQD, HDIM, nullptr, 0, 0);
        // fused gather-GEMM (cp.async double-buffered): m2 = relu(relu(gather)@Wm2+bm2)
        egemm_gather_k<<<dim3(QD/128, EE/128), 256, EG_SMEM>>>(
            bufD, bufD + NNQD, bm1 + l * QD, ei, Wm2_l, bm2 + l * QD, m2);
        // m3 = m2 @ Wm3 + bm3 (proven BIG tgemm) ; then scatter-add
        launch_tg<BIG,0,3>(dim3(HDIM/128, EE/128, 1),
            m2, QD, 0, Wm3_l, HDIM, 0, m1, HDIM, 0, QD, bm3 + l * HDIM, 0, 0);
        zero_f32_k<<<(NN * HDIM + TPB - 1) / TPB, TPB>>>(agg, NN * HDIM);
        scatter_k<<<(EE * HDIM / 4 + TPB - 1) / TPB, TPB>>>((const float4*)m1, ei, agg);

        // residual + aggregate + LN
        combine_ln_k<<<NN, HDIM>>>(h, agg, mha, gatt, lng + l * HDIM, lnb + l * HDIM);
    }

    // readout
    pool_k<<<2 * HDIM, 256>>>(h, pool);
    fc1_k<<<HDIM, 256>>>(pool, Wc1, bc1, z);
    fc2_k<<<OUTD, 256>>>(z, Wc2, bc2, out);
}

// round 13
// speedup vs baseline: 1.5171x; 1.0717x over previous
#include <cuda_runtime.h>
#include <math.h>

// ---------------- problem constants ----------------
#define NN   4096
#define EE   65536
#define IND  512
#define HDIM 256
#define QD   256
#define NHD  8
#define HD   32
#define OUTD 10
#define LL   2
#define MW   (NN/32)
#define NNQD ((long long)NN*QD)

// ---------------- static scratch ----------------
__device__ float    g_h   [NN*HDIM];
__device__ float    g_bufA[2*NN*QD];     // Qt, Kt
__device__ float    g_bufB[3*NN*QD];     // Q, K, V
__device__ float    g_bufC[3*NN*QD];     // mq, mk, mv
__device__ float    g_bufD[2*NN*QD];     // eA, eB
__device__ float    g_W3  [2*3*HDIM*QD];
__device__ float    g_b3  [2*3*QD];
__device__ float    g_Bc2 [2*2*QD*QD];   // staged [Bc | BcT] per layer
__device__ float    g_vm  [QD];
__device__ float    g_gatt[NN*QD];
__device__ float    g_mo  [NN*QD];
__device__ float    g_mha [NN*QD];
__device__ float    g_m2  [(size_t)EE*QD];   // 64MB (only edge intermediate)
__device__ unsigned g_mask[(size_t)NN*MW];
__device__ float    g_agg [NN*HDIM];
__device__ float    g_pool[2*HDIM];
__device__ float    g_z   [HDIM];

// ---------------- TF32 helpers ----------------
__device__ __forceinline__ unsigned f2tf(float f) {
    unsigned u;
    asm("cvt.rna.tf32.f32 %0, %1;" : "=r"(u) : "f"(f));
    return u;
}
__device__ __forceinline__ void mma_tf32(float* c, const unsigned* a, const unsigned* b) {
    asm volatile(
        "mma.sync.aligned.m16n8k8.row.col.f32.tf32.tf32.f32 "
        "{%0,%1,%2,%3}, {%4,%5,%6,%7}, {%8,%9}, {%0,%1,%2,%3};"
        : "+f"(c[0]), "+f"(c[1]), "+f"(c[2]), "+f"(c[3])
        : "r"(a[0]), "r"(a[1]), "r"(a[2]), "r"(a[3]), "r"(b[0]), "r"(b[1]));
}
__device__ __forceinline__ void cpasync16(void* sdst, const void* gsrc) {
    unsigned sa = (unsigned)__cvta_generic_to_shared(sdst);
    asm volatile("cp.async.cg.shared.global [%0], [%1], 16;\n" :: "r"(sa), "l"(gsrc));
}
#define CP_COMMIT() asm volatile("cp.async.commit_group;\n" ::: "memory")

// =====================================================================
// Generic TF32 GEMM (proven; batched via blockIdx.z)
// =====================================================================
template<int BM, int BN, int TRANSB, int STAGES>
constexpr size_t tg_smem() {
    return (size_t)STAGES * ((size_t)BM * 36 + (TRANSB ? (size_t)BN * 36
                                                       : (size_t)32 * (BN + 8))) * 4;
}

template<int BM, int BN, int WM, int WN, int TRANSB, int STAGES>
__global__ __launch_bounds__(256)
void tgemm_k(const float* __restrict__ A, int lda, long long sA,
             const float* __restrict__ B, int ldb, long long sB,
             float* __restrict__ C, int ldc, long long sC,
             int K,
             const float* __restrict__ bias, long long sBias, int act)
{
    constexpr int BK   = 32;
    constexpr int WX   = BN / WN;
    constexpr int WY   = BM / WM;
    static_assert(WX * WY == 8, "8 warps");
    constexpr int MM   = WM / 16;
    constexpr int MN   = WN / 8;
    constexpr int AL   = BM * (BK / 4) / 256;
    constexpr int BLt  = BN * (BK / 4) / 256;
    constexpr int BLn  = BK * (BN / 4) / 256;
    constexpr int ASTR = BK + 4;
    constexpr int BNSTR= BN + 8;
    constexpr int ASZ  = BM * ASTR;
    constexpr int BSZ  = TRANSB ? BN * ASTR : BK * BNSTR;

    const int tid  = threadIdx.x;
    const int wid  = tid >> 5;
    const int lane = tid & 31;
    const int wx   = wid % WX;
    const int wy   = wid / WX;
    const int lg   = lane >> 2;
    const int lt   = lane & 3;
    const int m0   = blockIdx.y * BM;
    const int n0   = blockIdx.x * BN;

    const float* Ab    = A + sA * blockIdx.z;
    const float* Bb    = B + sB * blockIdx.z;
    float*       Cb    = C + sC * blockIdx.z;
    const float* biasb = bias ? bias + sBias * blockIdx.z : nullptr;

    extern __shared__ float smem[];
    float* AsBase = smem;
    float* BsBase = smem + (size_t)STAGES * ASZ;

    auto load_stage = [&](int s, int k0) {
        float* as = AsBase + (size_t)s * ASZ;
#pragma unroll
        for (int j = 0; j < AL; j++) {
            int idx = tid + j * 256;
            int m   = idx >> 3;
            int k4  = idx & 7;
            cpasync16(&as[m * ASTR + k4 * 4],
                      &Ab[(size_t)(m0 + m) * lda + k0 + k4 * 4]);
        }
        float* bs = BsBase + (size_t)s * BSZ;
        if (TRANSB) {
#pragma unroll
            for (int j = 0; j < BLt; j++) {
                int idx = tid + j * 256;
                int n   = idx >> 3;
                int k4  = idx & 7;
                cpasync16(&bs[n * ASTR + k4 * 4],
                          &Bb[(size_t)(n0 + n) * ldb + k0 + k4 * 4]);
            }
        } else {
#pragma unroll
            for (int j = 0; j < BLn; j++) {
                int idx = tid + j * 256;
                int k   = idx / (BN / 4);
                int n4  = idx % (BN / 4);
                cpasync16(&bs[k * BNSTR + n4 * 4],
                          &Bb[(size_t)(k0 + k) * ldb + n0 + n4 * 4]);
            }
        }
    };

    float acc[MM][MN][4];
#pragma unroll
    for (int i = 0; i < MM; i++)
#pragma unroll
        for (int j = 0; j < MN; j++)
#pragma unroll
            for (int c = 0; c < 4; c++) acc[i][j][c] = 0.f;

    const int ktiles = K / BK;
#pragma unroll
    for (int s = 0; s < STAGES - 1; s++) {
        if (s < ktiles) load_stage(s, s * BK);
        CP_COMMIT();
    }

    for (int t = 0; t < ktiles; t++) {
        asm volatile("cp.async.wait_group %0;\n" :: "n"(STAGES - 2) : "memory");
        __syncthreads();

        int nt = t + STAGES - 1;
        if (nt < ktiles) load_stage(nt % STAGES, nt * BK);
        CP_COMMIT();

        const float* as = AsBase + (size_t)(t % STAGES) * ASZ;
        const float* bs = BsBase + (size_t)(t % STAGES) * BSZ;

#pragma unroll
        for (int ks = 0; ks < BK / 8; ks++) {
            const int kk = ks * 8;
            unsigned af[MM][4], bf[MN][2];
#pragma unroll
            for (int i = 0; i < MM; i++) {
                int row = wy * WM + i * 16 + lg;
                af[i][0] = f2tf(as[row * ASTR + kk + lt]);
                af[i][1] = f2tf(as[(row + 8) * ASTR + kk + lt]);
                af[i][2] = f2tf(as[row * ASTR + kk + lt + 4]);
                af[i][3] = f2tf(as[(row + 8) * ASTR + kk + lt + 4]);
            }
#pragma unroll
            for (int j = 0; j < MN; j++) {
                int col = wx * WN + j * 8 + lg;
                if (TRANSB) {
                    bf[j][0] = f2tf(bs[col * ASTR + kk + lt]);
                    bf[j][1] = f2tf(bs[col * ASTR + kk + lt + 4]);
                } else {
                    bf[j][0] = f2tf(bs[(kk + lt) * BNSTR + col]);
                    bf[j][1] = f2tf(bs[(kk + lt + 4) * BNSTR + col]);
                }
            }
#pragma unroll
            for (int i = 0; i < MM; i++)
#pragma unroll
                for (int j = 0; j < MN; j++)
                    mma_tf32(acc[i][j], af[i], bf[j]);
        }
        __syncthreads();
    }

#pragma unroll
    for (int i = 0; i < MM; i++) {
        int mA = m0 + wy * WM + i * 16 + lg;
        int mB = mA + 8;
#pragma unroll
        for (int j = 0; j < MN; j++) {
            int n = n0 + wx * WN + j * 8 + lt * 2;
            float b0 = biasb ? biasb[n] : 0.f;
            float b1 = biasb ? biasb[n + 1] : 0.f;
            float v0 = acc[i][j][0] + b0;
            float v1 = acc[i][j][1] + b1;
            float v2 = acc[i][j][2] + b0;
            float v3 = acc[i][j][3] + b1;
            if (act == 1) {
                v0 = fmaxf(v0, 0.f); v1 = fmaxf(v1, 0.f);
                v2 = fmaxf(v2, 0.f); v3 = fmaxf(v3, 0.f);
            }
            Cb[(size_t)mA * ldc + n]     = v0;
            Cb[(size_t)mA * ldc + n + 1] = v1;
            Cb[(size_t)mB * ldc + n]     = v2;
            Cb[(size_t)mB * ldc + n + 1] = v3;
        }
    }
}

// =====================================================================
// Edge gather-GEMM v2 (proven round 9): m2 = relu(relu(eA[tgt]+eB[src]+bm1)@Wm2+bm2)
// =====================================================================
#define EG_ASTR 36
#define EG_BSTR 136
#define EG_SMEM ((4*128*EG_ASTR + 2*32*EG_BSTR) * 4)   // 108544 B

__global__ __launch_bounds__(256)
void egemm_gather_k(const float* __restrict__ eA, const float* __restrict__ eB,
                    const float* __restrict__ b1, const int* __restrict__ ei,
                    const float* __restrict__ W, const float* __restrict__ b2,
                    float* __restrict__ C)
{
    __shared__ int   tgts[128], srcs[128];
    __shared__ float b1s[256];
    extern __shared__ float smem[];
    float* AsA = smem;
    float* AsB = smem + 2 * 128 * EG_ASTR;
    float* Bs  = smem + 4 * 128 * EG_ASTR;

    const int tid  = threadIdx.x;
    const int wid  = tid >> 5;
    const int lane = tid & 31;
    const int wx   = wid & 3;
    const int wy   = wid >> 2;
    const int lg   = lane >> 2;
    const int lt   = lane & 3;
    const int m0   = blockIdx.y * 128;
    const int n0   = blockIdx.x * 128;

    if (tid < 128) { srcs[tid] = ei[m0 + tid]; tgts[tid] = ei[EE + m0 + tid]; }
    b1s[tid] = b1[tid];
    __syncthreads();

    auto load_stage = [&](int s, int k0) {
        float* aA = AsA + s * 128 * EG_ASTR;
        float* aB = AsB + s * 128 * EG_ASTR;
#pragma unroll
        for (int j = 0; j < 4; j++) {
            int idx = tid + j * 256;
            int m = idx >> 3, k4 = idx & 7;
            cpasync16(&aA[m * EG_ASTR + k4 * 4],
                      &eA[(size_t)tgts[m] * QD + k0 + k4 * 4]);
            cpasync16(&aB[m * EG_ASTR + k4 * 4],
                      &eB[(size_t)srcs[m] * QD + k0 + k4 * 4]);
        }
        float* bs = Bs + s * 32 * EG_BSTR;
#pragma unroll
        for (int j = 0; j < 4; j++) {
            int idx = tid + j * 256;
            int k = idx >> 5, n4 = idx & 31;
            cpasync16(&bs[k * EG_BSTR + n4 * 4],
                      &W[(size_t)(k0 + k) * QD + n0 + n4 * 4]);
        }
    };
    load_stage(0, 0);
    CP_COMMIT();

    float acc[4][4][4];
#pragma unroll
    for (int i = 0; i < 4; i++)
#pragma unroll
        for (int j = 0; j < 4; j++)
#pragma unroll
            for (int c = 0; c < 4; c++) acc[i][j][c] = 0.f;

    for (int t = 0; t < 8; t++) {
        if (t + 1 < 8) load_stage((t + 1) & 1, (t + 1) * 32);
        CP_COMMIT();
        asm volatile("cp.async.wait_group 1;\n" ::: "memory");
        __syncthreads();

        const float* aA = AsA + (t & 1) * 128 * EG_ASTR;
        const float* aB = AsB + (t & 1) * 128 * EG_ASTR;
        const float* bs = Bs  + (t & 1) * 32 * EG_BSTR;
        const int kg0 = t * 32;

#pragma unroll
        for (int ks = 0; ks < 4; ks++) {
            const int kk = ks * 8;
            const float bA0 = b1s[kg0 + kk + lt];
            const float bA1 = b1s[kg0 + kk + lt + 4];
            unsigned af[4][4], bf[4][2];
#pragma unroll
            for (int i = 0; i < 4; i++) {
                int row = wy * 64 + i * 16 + lg;
                af[i][0] = f2tf(fmaxf(aA[row * EG_ASTR + kk + lt] +
                                      aB[row * EG_ASTR + kk + lt] + bA0, 0.f));
                af[i][1] = f2tf(fmaxf(aA[(row + 8) * EG_ASTR + kk + lt] +
                                      aB[(row + 8) * EG_ASTR + kk + lt] + bA0, 0.f));
                af[i][2] = f2tf(fmaxf(aA[row * EG_ASTR + kk + lt + 4] +
                                      aB[row * EG_ASTR + kk + lt + 4] + bA1, 0.f));
                af[i][3] = f2tf(fmaxf(aA[(row + 8) * EG_ASTR + kk + lt + 4] +
                                      aB[(row + 8) * EG_ASTR + kk + lt + 4] + bA1, 0.f));
            }
#pragma unroll
            for (int j = 0; j < 4; j++) {
                int col = wx * 32 + j * 8 + lg;
                bf[j][0] = f2tf(bs[(kk + lt) * EG_BSTR + col]);
                bf[j][1] = f2tf(bs[(kk + lt + 4) * EG_BSTR + col]);
            }
#pragma unroll
            for (int i = 0; i < 4; i++)
#pragma unroll
                for (int j = 0; j < 4; j++)
                    mma_tf32(acc[i][j], af[i], bf[j]);
        }
        __syncthreads();
    }

#pragma unroll
    for (int i = 0; i < 4; i++) {
        int mA = m0 + wy * 64 + i * 16 + lg;
        int mB = mA + 8;
#pragma unroll
        for (int j = 0; j < 4; j++) {
            int n = n0 + wx * 32 + j * 8 + lt * 2;
            float b0 = b2[n], b1v = b2[n + 1];
            C[(size_t)mA * QD + n]     = fmaxf(acc[i][j][0] + b0, 0.f);
            C[(size_t)mA * QD + n + 1] = fmaxf(acc[i][j][1] + b1v, 0.f);
            C[(size_t)mB * QD + n]     = fmaxf(acc[i][j][2] + b0, 0.f);
            C[(size_t)mB * QD + n + 1] = fmaxf(acc[i][j][3] + b1v, 0.f);
        }
    }
}

// =====================================================================
// Edge scatter-GEMM: agg[tgt[e]] += m2[e] @ Wm3 + bm3
//  3-stage cp.async pipeline (clone of tgemm), atomic epilogue.
// =====================================================================
#define ES_SMEM ((3*128*EG_ASTR + 3*32*EG_BSTR) * 4)   // 107520 B

__global__ __launch_bounds__(256)
void egemm_scatter_k(const float* __restrict__ A, const int* __restrict__ ei,
                     const float* __restrict__ W, const float* __restrict__ b3,
                     float* __restrict__ agg)
{
    extern __shared__ float smem[];
    float* AsBase = smem;
    float* BsBase = smem + 3 * 128 * EG_ASTR;

    const int tid  = threadIdx.x;
    const int wid  = tid >> 5;
    const int lane = tid & 31;
    const int wx   = wid & 3;
    const int wy   = wid >> 2;
    const int lg   = lane >> 2;
    const int lt   = lane & 3;
    const int m0   = blockIdx.y * 128;
    const int n0   = blockIdx.x * 128;

    auto load_stage = [&](int s, int k0) {
        float* as = AsBase + s * 128 * EG_ASTR;
#pragma unroll
        for (int j = 0; j < 4; j++) {
            int idx = tid + j * 256;
            int m = idx >> 3, k4 = idx & 7;
            cpasync16(&as[m * EG_ASTR + k4 * 4],
                      &A[(size_t)(m0 + m) * QD + k0 + k4 * 4]);
        }
        float* bs = BsBase + s * 32 * EG_BSTR;
#pragma unroll
        for (int j = 0; j < 4; j++) {
            int idx = tid + j * 256;
            int k = idx >> 5, n4 = idx & 31;
            cpasync16(&bs[k * EG_BSTR + n4 * 4],
                      &W[(size_t)(k0 + k) * HDIM + n0 + n4 * 4]);
        }
    };
    load_stage(0, 0);  CP_COMMIT();
    load_stage(1, 32); CP_COMMIT();

    float acc[4][4][4];
#pragma unroll
    for (int i = 0; i < 4; i++)
#pragma unroll
        for (int j = 0; j < 4; j++)
#pragma unroll
            for (int c = 0; c < 4; c++) acc[i][j][c] = 0.f;

    for (int t = 0; t < 8; t++) {
        asm volatile("cp.async.wait_group 1;\n" ::: "memory");
        __syncthreads();

        if (t + 2 < 8) load_stage((t + 2) % 3, (t + 2) * 32);
        CP_COMMIT();

        const float* as = AsBase + (t % 3) * 128 * EG_ASTR;
        const float* bs = BsBase + (t % 3) * 32 * EG_BSTR;
#pragma unroll
        for (int ks = 0; ks < 4; ks++) {
            const int kk = ks * 8;
            unsigned af[4][4], bf[4][2];
#pragma unroll
            for (int i = 0; i < 4; i++) {
                int row = wy * 64 + i * 16 + lg;
                af[i][0] = f2tf(as[row * EG_ASTR + kk + lt]);
                af[i][1] = f2tf(as[(row + 8) * EG_ASTR + kk + lt]);
                af[i][2] = f2tf(as[row * EG_ASTR + kk + lt + 4]);
                af[i][3] = f2tf(as[(row + 8) * EG_ASTR + kk + lt + 4]);
            }
#pragma unroll
            for (int j = 0; j < 4; j++) {
                int col = wx * 32 + j * 8 + lg;
                bf[j][0] = f2tf(bs[(kk + lt) * EG_BSTR + col]);
                bf[j][1] = f2tf(bs[(kk + lt + 4) * EG_BSTR + col]);
            }
#pragma unroll
            for (int i = 0; i < 4; i++)
#pragma unroll
                for (int j = 0; j < 4; j++)
                    mma_tf32(acc[i][j], af[i], bf[j]);
        }
        __syncthreads();
    }

#pragma unroll
    for (int i = 0; i < 4; i++) {
        int mA = m0 + wy * 64 + i * 16 + lg;
        int mB = mA + 8;
        int tA = ei[EE + mA];
        int tB = ei[EE + mB];
#pragma unroll
        for (int j = 0; j < 4; j++) {
            int n = n0 + wx * 32 + j * 8 + lt * 2;
            float b0 = b3[n], b1v = b3[n + 1];
            atomicAdd(&agg[(size_t)tA * HDIM + n],     acc[i][j][0] + b0);
            atomicAdd(&agg[(size_t)tA * HDIM + n + 1], acc[i][j][1] + b1v);
            atomicAdd(&agg[(size_t)tB * HDIM + n],     acc[i][j][2] + b0);
            atomicAdd(&agg[(size_t)tB * HDIM + n + 1], acc[i][j][3] + b1v);
        }
    }
}

// =====================================================================
// Flash MHA (proven, unchanged)
// =====================================================================
#define FBQ   128
#define FBKV  64
#define QSTR  36
#define KSTR  36
#define VSTR  40
#define PSTR  68
#define FLASH_SMEM ((FBQ*QSTR + 2*FBKV*KSTR + 2*FBKV*VSTR + 8*16*PSTR) * 4)

__global__ __launch_bounds__(256)
void flash_mha_k(const float* __restrict__ mq, const float* __restrict__ mk,
                 const float* __restrict__ mv, float* __restrict__ mo, float scale)
{
    extern __shared__ float sm[];
    float*    Qs = sm;
    float*    Ks = Qs + FBQ * QSTR;
    float*    Vs = Ks + 2 * FBKV * KSTR;
    unsigned* Ps = (unsigned*)(Vs + 2 * FBKV * VSTR);

    const int tid  = threadIdx.x;
    const int wid  = tid >> 5;
    const int lane = tid & 31;
    const int lg   = lane >> 2;
    const int lt   = lane & 3;
    const int hh   = blockIdx.y;
    const int q0   = blockIdx.x * FBQ;

    const float* Qg = mq + (size_t)q0 * QD + hh * HD;
    const float* Kg = mk + hh * HD;
    const float* Vg = mv + hh * HD;

#pragma unroll
    for (int j = 0; j < 4; j++) {
        int idx = tid + j * 256;
        int r = idx >> 3, c4 = idx & 7;
        cpasync16(&Qs[r * QSTR + c4 * 4], &Qg[(size_t)r * QD + c4 * 4]);
    }
    auto loadKV = [&](int s, int kv0) {
        float* ks = Ks + s * FBKV * KSTR;
        float* vs = Vs + s * FBKV * VSTR;
#pragma unroll
        for (int j = 0; j < 2; j++) {
            int idx = tid + j * 256;
            int r = idx >> 3, c4 = idx & 7;
            cpasync16(&ks[r * KSTR + c4 * 4], &Kg[(size_t)(kv0 + r) * QD + c4 * 4]);
        }
#pragma unroll
        for (int j = 0; j < 2; j++) {
            int idx = tid + j * 256;
            int r = idx >> 3, c4 = idx & 7;
            cpasync16(&vs[r * VSTR + c4 * 4], &Vg[(size_t)(kv0 + r) * QD + c4 * 4]);
        }
    };
    loadKV(0, 0);
    CP_COMMIT();

    float O[4][4];
#pragma unroll
    for (int j = 0; j < 4; j++)
#pragma unroll
        for (int c = 0; c < 4; c++) O[j][c] = 0.f;
    float m0r = -3.4e38f, m1r = -3.4e38f;
    float l0 = 0.f, l1 = 0.f;
    unsigned* Pw = Ps + wid * 16 * PSTR;
    const int qrow = wid * 16 + lg;

    const int NT = NN / FBKV;
    for (int t = 0; t < NT; t++) {
        if (t + 1 < NT) loadKV((t + 1) & 1, (t + 1) * FBKV);
        CP_COMMIT();
        asm volatile("cp.async.wait_group 1;\n" ::: "memory");
        __syncthreads();

        const float* ks = Ks + (t & 1) * FBKV * KSTR;
        const float* vs = Vs + (t & 1) * FBKV * VSTR;

        float Sacc[8][4];
#pragma unroll
        for (int n = 0; n < 8; n++)
#pragma unroll
            for (int c = 0; c < 4; c++) Sacc[n][c] = 0.f;
#pragma unroll
        for (int ks8 = 0; ks8 < 4; ks8++) {
            const int kk = ks8 * 8;
            unsigned af[4];
            af[0] = f2tf(Qs[qrow * QSTR + kk + lt]);
            af[1] = f2tf(Qs[(qrow + 8) * QSTR + kk + lt]);
            af[2] = f2tf(Qs[qrow * QSTR + kk + lt + 4]);
            af[3] = f2tf(Qs[(qrow + 8) * QSTR + kk + lt + 4]);
#pragma unroll
            for (int n = 0; n < 8; n++) {
                int col = n * 8 + lg;
                unsigned bf[2];
                bf[0] = f2tf(ks[col * KSTR + kk + lt]);
                bf[1] = f2tf(ks[col * KSTR + kk + lt + 4]);
                mma_tf32(Sacc[n], af, bf);
            }
        }

        float mx0 = -3.4e38f, mx1 = -3.4e38f;
#pragma unroll
        for (int n = 0; n < 8; n++) {
            Sacc[n][0] *= scale; Sacc[n][1] *= scale;
            Sacc[n][2] *= scale; Sacc[n][3] *= scale;
            mx0 = fmaxf(mx0, fmaxf(Sacc[n][0], Sacc[n][1]));
            mx1 = fmaxf(mx1, fmaxf(Sacc[n][2], Sacc[n][3]));
        }
        mx0 = fmaxf(mx0, __shfl_xor_sync(0xffffffffu, mx0, 1));
        mx0 = fmaxf(mx0, __shfl_xor_sync(0xffffffffu, mx0, 2));
        mx1 = fmaxf(mx1, __shfl_xor_sync(0xffffffffu, mx1, 1));
        mx1 = fmaxf(mx1, __shfl_xor_sync(0xffffffffu, mx1, 2));
        float mn0 = fmaxf(m0r, mx0), mn1 = fmaxf(m1r, mx1);
        float a0 = __expf(m0r - mn0), a1 = __expf(m1r - mn1);
        float rs0 = 0.f, rs1 = 0.f;
#pragma unroll
        for (int n = 0; n < 8; n++) {
            float p0 = __expf(Sacc[n][0] - mn0);
            float p1 = __expf(Sacc[n][1] - mn0);
            float p2 = __expf(Sacc[n][2] - mn1);
            float p3 = __expf(Sacc[n][3] - mn1);
            rs0 += p0 + p1; rs1 += p2 + p3;
            int c0 = n * 8 + lt * 2;
            Pw[lg * PSTR + c0]           = f2tf(p0);
            Pw[lg * PSTR + c0 + 1]       = f2tf(p1);
            Pw[(lg + 8) * PSTR + c0]     = f2tf(p2);
            Pw[(lg + 8) * PSTR + c0 + 1] = f2tf(p3);
        }
        rs0 += __shfl_xor_sync(0xffffffffu, rs0, 1);
        rs0 += __shfl_xor_sync(0xffffffffu, rs0, 2);
        rs1 += __shfl_xor_sync(0xffffffffu, rs1, 1);
        rs1 += __shfl_xor_sync(0xffffffffu, rs1, 2);
        l0 = l0 * a0 + rs0;
        l1 = l1 * a1 + rs1;
        m0r = mn0; m1r = mn1;
#pragma unroll
        for (int j = 0; j < 4; j++) {
            O[j][0] *= a0; O[j][1] *= a0;
            O[j][2] *= a1; O[j][3] *= a1;
        }
        __syncwarp();

#pragma unroll
        for (int ks8 = 0; ks8 < 8; ks8++) {
            const int kk = ks8 * 8;
            unsigned af[4];
            af[0] = Pw[lg * PSTR + kk + lt];
            af[1] = Pw[(lg + 8) * PSTR + kk + lt];
            af[2] = Pw[lg * PSTR + kk + lt + 4];
            af[3] = Pw[(lg + 8) * PSTR + kk + lt + 4];
#pragma unroll
            for (int j = 0; j < 4; j++) {
                int col = j * 8 + lg;
                unsigned bf[2];
                bf[0] = f2tf(vs[(kk + lt) * VSTR + col]);
                bf[1] = f2tf(vs[(kk + lt + 4) * VSTR + col]);
                mma_tf32(O[j], af, bf);
            }
        }
        __syncwarp();
        __syncthreads();
    }

    float inv0 = 1.f / l0, inv1 = 1.f / l1;
    const size_t rA = (size_t)(q0 + qrow) * QD + hh * HD;
    const size_t rB = rA + 8 * QD;
#pragma unroll
    for (int j = 0; j < 4; j++) {
        int c = j * 8 + lt * 2;
        mo[rA + c]     = O[j][0] * inv0;
        mo[rA + c + 1] = O[j][1] * inv0;
        mo[rB + c]     = O[j][2] * inv1;
        mo[rB + c + 1] = O[j][3] * inv1;
    }
}

// =====================================================================
// Sparse graph attention (proven, unchanged)
// =====================================================================
__global__ __launch_bounds__(128)
void sparse_gatt_k(const float* __restrict__ Q, const float* __restrict__ K,
                   const float* __restrict__ V, const unsigned* __restrict__ mask,
                   const float* __restrict__ vmean, float* __restrict__ gatt,
                   float scale)
{
    __shared__ int   idxs[NN];
    __shared__ float sc  [NN];
    __shared__ int   wbase[5];
    __shared__ float red[4];

    const int s    = blockIdx.x;
    const int tid  = threadIdx.x;
    const int wid  = tid >> 5;
    const int lane = tid & 31;

    unsigned w = mask[(size_t)s * MW + tid];
    int c = __popc(w);
    int pre = c;
#pragma unroll
    for (int o = 1; o < 32; o <<= 1) {
        int v = __shfl_up_sync(0xffffffffu, pre, o);
        if (lane >= o) pre += v;
    }
    if (lane == 31) wbase[wid + 1] = pre;
    __syncthreads();
    if (tid == 0) {
        wbase[0] = 0;
        wbase[2] += wbase[1];
        wbase[3] += wbase[2];
        wbase[4] += wbase[3];
    }
    __syncthreads();
    const int cnt = wbase[4];
    int p = wbase[wid] + pre - c;
    unsigned ww = w;
    while (ww) {
        int b = __ffs(ww) - 1;
        idxs[p++] = tid * 32 + b;
        ww &= ww - 1;
    }
    __syncthreads();

    const int c0 = tid * 2;
    if (cnt == 0) {
        gatt[(size_t)s * QD + c0]     = vmean[c0];
        gatt[(size_t)s * QD + c0 + 1] = vmean[c0 + 1];
        return;
    }

    float q[8];
    const float* Qr = Q + (size_t)s * QD;
#pragma unroll
    for (int i = 0; i < 8; i++) q[i] = Qr[lane * 8 + i];
    for (int e = wid; e < cnt; e += 4) {
        const float* Kr = K + (size_t)idxs[e] * QD;
        float d = 0.f;
#pragma unroll
        for (int i = 0; i < 8; i++) d = fmaf(q[i], Kr[lane * 8 + i], d);
#pragma unroll
        for (int o = 16; o; o >>= 1) d += __shfl_xor_sync(0xffffffffu, d, o);
        if (lane == 0) sc[e] = d * scale;
    }
    __syncthreads();

    float mx = -3.4e38f;
    for (int e = tid; e < cnt; e += 128) mx = fmaxf(mx, sc[e]);
#pragma unroll
    for (int o = 16; o; o >>= 1) mx = fmaxf(mx, __shfl_xor_sync(0xffffffffu, mx, o));
    if (lane == 0) red[wid] = mx;
    __syncthreads();
    mx = fmaxf(fmaxf(red[0], red[1]), fmaxf(red[2], red[3]));
    __syncthreads();

    float sum = 0.f;
    for (int e = tid; e < cnt; e += 128) {
        float pe = __expf(sc[e] - mx);
        sc[e] = pe;
        sum += pe;
    }
#pragma unroll
    for (int o = 16; o; o >>= 1) sum += __shfl_xor_sync(0xffffffffu, sum, o);
    if (lane == 0) red[wid] = sum;
    __syncthreads();
    float inv = 1.f / (red[0] + red[1] + red[2] + red[3]);

    float a0 = 0.f, a1 = 0.f;
    for (int e = 0; e < cnt; e++) {
        const float* Vr = V + (size_t)idxs[e] * QD;
        float pe = sc[e];
        a0 = fmaf(pe, Vr[c0], a0);
        a1 = fmaf(pe, Vr[c0 + 1], a1);
    }
    gatt[(size_t)s * QD + c0]     = a0 * inv;
    gatt[(size_t)s * QD + c0 + 1] = a1 * inv;
}

// ---------------- block reductions ----------------
__device__ __forceinline__ float blkMax(float v) {
    __shared__ float sh[8];
#pragma unroll
    for (int o = 16; o; o >>= 1) v = fmaxf(v, __shfl_xor_sync(0xffffffffu, v, o));
    if ((threadIdx.x & 31) == 0) sh[threadIdx.x >> 5] = v;
    __syncthreads();
    if (threadIdx.x < 32) {
        float w = (threadIdx.x < 8) ? sh[threadIdx.x] : -3.4e38f;
#pragma unroll
        for (int o = 4; o; o >>= 1) w = fmaxf(w, __shfl_xor_sync(0xffffffffu, w, o));
        if (threadIdx.x == 0) sh[0] = w;
    }
    __syncthreads();
    float r = sh[0];
    __syncthreads();
    return r;
}
__device__ __forceinline__ float blkSum(float v) {
    __shared__ float sh[8];
#pragma unroll
    for (int o = 16; o; o >>= 1) v += __shfl_xor_sync(0xffffffffu, v, o);
    if ((threadIdx.x & 31) == 0) sh[threadIdx.x >> 5] = v;
    __syncthreads();
    if (threadIdx.x < 32) {
        float w = (threadIdx.x < 8) ? sh[threadIdx.x] : 0.f;
#pragma unroll
        for (int o = 4; o; o >>= 1) w += __shfl_xor_sync(0xffffffffu, w, o);
        if (threadIdx.x == 0) sh[0] = w;
    }
    __syncthreads();
    float r = sh[0];
    __syncthreads();
    return r;
}

// ---------------- elementwise / small kernels ----------------
__global__ void zero_u32_k(unsigned* __restrict__ p, int n) {
    int i = blockIdx.x * blockDim.x + threadIdx.x;
    if (i < n) p[i] = 0u;
}
__global__ void zero_f32_k(float* __restrict__ p, int n) {
    int i = blockIdx.x * blockDim.x + threadIdx.x;
    if (i < n) p[i] = 0.f;
}
__global__ void build_mask_k(const int* __restrict__ ei, unsigned* __restrict__ mask) {
    int e = blockIdx.x * blockDim.x + threadIdx.x;
    if (e >= EE) return;
    int s = ei[e], t = ei[EE + e];
    atomicOr(&mask[(size_t)s * MW + (t >> 5)], 1u << (t & 31));
}
__global__ void stage_qkv_k(const float* __restrict__ Wq, const float* __restrict__ Wk,
                            const float* __restrict__ Wv, const float* __restrict__ bq,
                            const float* __restrict__ bk, const float* __restrict__ bv,
                            float* __restrict__ W3, float* __restrict__ b3) {
    int i = blockIdx.x * blockDim.x + threadIdx.x;
    const int per = HDIM * QD;
    if (i < 2 * per) {
        int l = i / per, r = i % per;
        W3[((size_t)l * 3 + 0) * per + r] = Wq[i];
        W3[((size_t)l * 3 + 1) * per + r] = Wk[i];
        W3[((size_t)l * 3 + 2) * per + r] = Wv[i];
    }
    if (i < 2 * QD) {
        int l = i / QD, r = i % QD;
        b3[(l * 3 + 0) * QD + r] = bq[i];
        b3[(l * 3 + 1) * QD + r] = bk[i];
        b3[(l * 3 + 2) * QD + r] = bv[i];
    }
}
__global__ void stage_bc_k(const float* __restrict__ Bc, float* __restrict__ Bc2) {
    int i = blockIdx.x * blockDim.x + threadIdx.x;
    if (i >= 2 * QD * QD) return;
    int l = i / (QD * QD), r = i % (QD * QD);
    int row = r / QD, col = r % QD;
    Bc2[((size_t)l * 2 + 0) * QD * QD + r] = Bc[i];
    Bc2[((size_t)l * 2 + 1) * QD * QD + (size_t)row * QD + col] =
        Bc[(size_t)l * QD * QD + (size_t)col * QD + row];
}
__global__ void vmean_k(const float* __restrict__ V, float* __restrict__ vm) {
    int c = blockIdx.x;
    float s = 0.f;
    for (int r = threadIdx.x; r < NN; r += 256) s += V[(size_t)r * QD + c];
    s = blkSum(s);
    if (threadIdx.x == 0) vm[c] = s * (1.f / NN);
}
__global__ void add_ce_k(float4* __restrict__ Q, float4* __restrict__ K,
                         const float4* __restrict__ ce, const int* __restrict__ ct) {
    int idx = blockIdx.x * blockDim.x + threadIdx.x;
    if (idx >= NN * (QD / 4)) return;
    int i = idx >> 6, j4 = idx & 63;
    float4 c = ce[ct[i] * (QD / 4) + j4];
    float4 q = Q[idx], k = K[idx];
    q.x += 0.1f * c.x; q.y += 0.1f * c.y; q.z += 0.1f * c.z; q.w += 0.1f * c.w;
    k.x += 0.1f * c.x; k.y += 0.1f * c.y; k.z += 0.1f * c.z; k.w += 0.1f * c.w;
    Q[idx] = q; K[idx] = k;
}
__global__ void combine_ln_k(float* __restrict__ h, const float* __restrict__ agg,
                             const float* __restrict__ mha, const float* __restrict__ gatt,
                             const float* __restrict__ g, const float* __restrict__ b) {
    int r = blockIdx.x, j = threadIdx.x;
    size_t idx = (size_t)r * HDIM + j;
    float v = h[idx] + agg[idx] + mha[idx] + gatt[idx];
    float mu = blkSum(v) * (1.f / HDIM);
    float d = v - mu;
    float var = blkSum(d * d) * (1.f / HDIM);
    h[idx] = d * rsqrtf(var + 1e-5f) * g[j] + b[j];
}
__global__ void pool_k(const float* __restrict__ h, float* __restrict__ pool) {
    int c = blockIdx.x, t = threadIdx.x;
    if (c < HDIM) {
        float s = 0.f;
        for (int r = t; r < NN; r += 256) s += h[(size_t)r * HDIM + c];
        s = blkSum(s);
        if (t == 0) pool[c] = s * (1.f / NN);
    } else {
        int cc = c - HDIM;
        float m = -3.4e38f;
        for (int r = t; r < NN; r += 256) m = fmaxf(m, h[(size_t)r * HDIM + cc]);
        m = blkMax(m);
        if (t == 0) pool[c] = m;
    }
}
__global__ void fc1_k(const float* __restrict__ pool, const float* __restrict__ W,
                      const float* __restrict__ b, float* __restrict__ z) {
    int o = blockIdx.x, t = threadIdx.x;
    float s = 0.f;
    for (int i = t; i < 2 * HDIM; i += 256) s += pool[i] * W[(size_t)i * HDIM + o];
    s = blkSum(s);
    if (t == 0) z[o] = fmaxf(s + b[o], 0.f);
}
__global__ void fc2_k(const float* __restrict__ z, const float* __restrict__ W,
                      const float* __restrict__ b, float* __restrict__ out) {
    int o = blockIdx.x, t = threadIdx.x;
    float s = 0.f;
    for (int i = t; i < HDIM; i += 256) s += z[i] * W[(size_t)i * OUTD + o];
    s = blkSum(s);
    if (t == 0) out[o] = s + b[o];
}

// ---------------- host side ----------------
static float* sym(const void* s) {
    void* p = nullptr;
    cudaGetSymbolAddress(&p, (const void*)s);
    return (float*)p;
}

#define NODE  64,128,32,32

template<int BM,int BN,int WM,int WN,int TRANSB,int STAGES>
static void launch_tg(dim3 grid,
                      const float* A, int lda, long long sA,
                      const float* B, int ldb, long long sB,
                      float* C, int ldc, long long sC, int K,
                      const float* bias, long long sBias, int act)
{
    constexpr size_t sm = tg_smem<BM, BN, TRANSB, STAGES>();
    static bool attr_done = false;
    if (!attr_done) {
        cudaFuncSetAttribute(tgemm_k<BM,BN,WM,WN,TRANSB,STAGES>,
                             cudaFuncAttributeMaxDynamicSharedMemorySize, (int)sm);
        attr_done = true;
    }
    tgemm_k<BM,BN,WM,WN,TRANSB,STAGES><<<grid, 256, sm>>>(
        A, lda, sA, B, ldb, sB, C, ldc, sC, K, bias, sBias, act);
}

extern "C" void kernel_launch(void* const* d_in, const int* in_sizes, int n_in,
                              void* d_out, int out_size) {
    const float* x    = (const float*)d_in[0];
    const int*   ei   = (const int*)  d_in[1];
    const int*   ct   = (const int*)  d_in[2];
    const float* Wi   = (const float*)d_in[3];
    const float* bi   = (const float*)d_in[4];
    const float* Wq   = (const float*)d_in[5];
    const float* bq   = (const float*)d_in[6];
    const float* Wk   = (const float*)d_in[7];
    const float* bk   = (const float*)d_in[8];
    const float* Wv   = (const float*)d_in[9];
    const float* bv   = (const float*)d_in[10];
    const float* Bc   = (const float*)d_in[11];
    const float* cemb = (const float*)d_in[12];
    const float* Win  = (const float*)d_in[13];
    const float* binp = (const float*)d_in[14];
    const float* Wo   = (const float*)d_in[15];
    const float* bo   = (const float*)d_in[16];
    const float* Wm1  = (const float*)d_in[17];
    const float* bm1  = (const float*)d_in[18];
    const float* Wm2  = (const float*)d_in[19];
    const float* bm2  = (const float*)d_in[20];
    const float* Wm3  = (const float*)d_in[21];
    const float* bm3  = (const float*)d_in[22];
    const float* lng  = (const float*)d_in[23];
    const float* lnb  = (const float*)d_in[24];
    const float* Wc1  = (const float*)d_in[25];
    const float* bc1  = (const float*)d_in[26];
    const float* Wc2  = (const float*)d_in[27];
    const float* bc2  = (const float*)d_in[28];
    float* out = (float*)d_out;

    float* h    = sym(g_h);
    float* bufA = sym(g_bufA);
    float* bufB = sym(g_bufB);
    float* bufC = sym(g_bufC);
    float* bufD = sym(g_bufD);
    float* W3   = sym(g_W3);
    float* b3s  = sym(g_b3);
    float* Bc2  = sym(g_Bc2);
    float* vm   = sym(g_vm);
    float* gatt = sym(g_gatt);
    float* mo   = sym(g_mo);
    float* mha  = sym(g_mha);
    float* m2   = sym(g_m2);
    float* agg  = sym(g_agg);
    float* pool = sym(g_pool);
    float* z    = sym(g_z);
    unsigned* mask = (unsigned*)sym(g_mask);

    const int TPB = 256;
    const long long HQD = (long long)HDIM * QD;

    static bool attrs = false;
    if (!attrs) {
        cudaFuncSetAttribute(flash_mha_k,
                             cudaFuncAttributeMaxDynamicSharedMemorySize, FLASH_SMEM);
        cudaFuncSetAttribute(egemm_gather_k,
                             cudaFuncAttributeMaxDynamicSharedMemorySize, EG_SMEM);
        cudaFuncSetAttribute(egemm_scatter_k,
                             cudaFuncAttributeMaxDynamicSharedMemorySize, ES_SMEM);
        attrs = true;
    }

    // adjacency mask + staged weights
    zero_u32_k<<<(NN * MW + TPB - 1) / TPB, TPB>>>(mask, NN * MW);
    build_mask_k<<<(EE + TPB - 1) / TPB, TPB>>>(ei, mask);
    stage_qkv_k<<<(2 * HDIM * QD + TPB - 1) / TPB, TPB>>>(Wq, Wk, Wv, bq, bk, bv, W3, b3s);
    stage_bc_k<<<(2 * QD * QD + TPB - 1) / TPB, TPB>>>(Bc, Bc2);

    // h = relu(x @ Wi + bi)
    launch_tg<NODE,0,3>(dim3(HDIM/128, NN/64, 1),
        x, IND, 0, Wi, HDIM, 0, h, HDIM, 0, IND, bi, 0, 1);

    for (int l = 0; l < LL; l++) {
        const float* ce_l  = cemb + (size_t)l * 50 * QD;
        const float* Win_l = Win + (size_t)l * QD * 3 * QD;
        const float* bin_l = binp + (size_t)l * 3 * QD;
        const float* Wo_l  = Wo  + (size_t)l * QD * QD;
        const float* Wm1_l = Wm1 + (size_t)l * (2 * HDIM + QD) * QD;
        const float* Wm2_l = Wm2 + (size_t)l * QD * QD;
        const float* Wm3_l = Wm3 + (size_t)l * QD * HDIM;

        dim3 gNode(QD/128, NN/64, 1);

        // batched {Qt,Kt} projections -> bufA ; V directly -> bufB[2]
        launch_tg<NODE,0,3>(dim3(QD/128, NN/64, 2),
            h, HDIM, 0, W3 + (size_t)l * 3 * HQD, QD, HQD,
            bufA, QD, NNQD, HDIM, b3s + l * 3 * QD, QD, 0);
        launch_tg<NODE,0,3>(gNode,
            h, HDIM, 0, W3 + (size_t)l * 3 * HQD + 2 * HQD, QD, 0,
            bufB + 2 * NNQD, QD, 0, HDIM, b3s + l * 3 * QD + 2 * QD, 0, 0);
        // batched biological constraint: {Q,K} = {Qt@Bc, Kt@BcT}
        launch_tg<NODE,0,3>(dim3(QD/128, NN/64, 2),
            bufA, QD, NNQD, Bc2 + (size_t)l * 2 * QD * QD, QD, (long long)QD * QD,
            bufB, QD, NNQD, QD, nullptr, 0, 0);
        add_ce_k<<<(NN * QD / 4 + TPB - 1) / TPB, TPB>>>(
            (float4*)bufB, (float4*)(bufB + NNQD), (const float4*)ce_l, ct);

        // sparse graph-masked attention (exact)
        vmean_k<<<QD, 256>>>(bufB + 2 * NNQD, vm);
        sparse_gatt_k<<<NN, 128>>>(bufB, bufB + NNQD, bufB + 2 * NNQD, mask, vm,
                                   gatt, 0.0625f);

        // batched MHA input projections: bufC {mq, mk, mv}
        launch_tg<NODE,0,3>(dim3(QD/128, NN/64, 3),
            bufB, QD, NNQD, Win_l, 3*QD, QD,
            bufC, QD, NNQD, QD, bin_l, QD, 0);

        // fused flash MHA
        flash_mha_k<<<dim3(NN/FBQ, NHD), 256, FLASH_SMEM>>>(
            bufC, bufC + NNQD, bufC + 2 * NNQD, mo, 0.17677669529663687f);

        launch_tg<NODE,0,3>(gNode, mo, QD, 0, Wo_l, QD, 0, mha, QD, 0,
                            QD, bo + l * QD, 0, 0);

        // batched edge-MLP first layer halves: bufD {eA, eB}
        launch_tg<NODE,0,3>(dim3(QD/128, NN/64, 2),
            h, HDIM, 0, Wm1_l, QD, HQD,
            bufD, QD, NNQD, HDIM, nullptr, 0, 0);
        // fused gather-GEMM: m2 = relu(relu(eA[tgt]+eB[src]+bm1) @ Wm2 + bm2)
        egemm_gather_k<<<dim3(QD/128, EE/128), 256, EG_SMEM>>>(
            bufD, bufD + NNQD, bm1 + l * QD, ei, Wm2_l, bm2 + l * QD, m2);
        // fused scatter-GEMM: agg[tgt] += m2 @ Wm3 + bm3
        zero_f32_k<<<(NN * HDIM + TPB - 1) / TPB, TPB>>>(agg, NN * HDIM);
        egemm_scatter_k<<<dim3(HDIM/128, EE/128), 256, ES_SMEM>>>(
            m2, ei, Wm3_l, bm3 + l * HDIM, agg);

        // residual + aggregate + LN
        combine_ln_k<<<NN, HDIM>>>(h, agg, mha, gatt, lng + l * HDIM, lnb + l * HDIM);
    }

    // readout
    pool_k<<<2 * HDIM, 256>>>(h, pool);
    fc1_k<<<HDIM, 256>>>(pool, Wc1, bc1, z);
    fc2_k<<<OUTD, 256>>>(z, Wc2, bc2, out);
}

// round 14
// speedup vs baseline: 1.5636x; 1.0307x over previous
#include <cuda_runtime.h>
#include <math.h>

// ---------------- problem constants ----------------
#define NN   4096
#define EE   65536
#define IND  512
#define HDIM 256
#define QD   256
#define NHD  8
#define HD   32
#define OUTD 10
#define LL   2
#define MW   (NN/32)
#define NNQD ((long long)NN*QD)

// ---------------- static scratch ----------------
__device__ float    g_h   [NN*HDIM];
__device__ float    g_bufA[2*NN*QD];     // Qt, Kt
__device__ float    g_bufB[3*NN*QD];     // Q, K, V
__device__ float    g_bufC[3*NN*QD];     // mq, mk, mv
__device__ float    g_bufD[2*NN*QD];     // eA, eB
__device__ float    g_W3  [2*3*HDIM*QD];
__device__ float    g_b3  [2*3*QD];
__device__ float    g_Bc2 [2*2*QD*QD];   // staged [Bc | BcT] per layer
__device__ float    g_vm  [QD];
__device__ float    g_gatt[NN*QD];
__device__ float    g_mo  [NN*QD];
__device__ float    g_mha [NN*QD];
__device__ float    g_m2  [(size_t)EE*QD];   // 64MB (only edge intermediate)
__device__ unsigned g_mask[(size_t)NN*MW];
__device__ float    g_agg [NN*HDIM];
__device__ float    g_pool[2*HDIM];
__device__ float    g_z   [HDIM];

// ---------------- TF32 helpers ----------------
__device__ __forceinline__ unsigned f2tf(float f) {
    unsigned u;
    asm("cvt.rna.tf32.f32 %0, %1;" : "=r"(u) : "f"(f));
    return u;
}
__device__ __forceinline__ void mma_tf32(float* c, const unsigned* a, const unsigned* b) {
    asm volatile(
        "mma.sync.aligned.m16n8k8.row.col.f32.tf32.tf32.f32 "
        "{%0,%1,%2,%3}, {%4,%5,%6,%7}, {%8,%9}, {%0,%1,%2,%3};"
        : "+f"(c[0]), "+f"(c[1]), "+f"(c[2]), "+f"(c[3])
        : "r"(a[0]), "r"(a[1]), "r"(a[2]), "r"(a[3]), "r"(b[0]), "r"(b[1]));
}
__device__ __forceinline__ void cpasync16(void* sdst, const void* gsrc) {
    unsigned sa = (unsigned)__cvta_generic_to_shared(sdst);
    asm volatile("cp.async.cg.shared.global [%0], [%1], 16;\n" :: "r"(sa), "l"(gsrc));
}
#define CP_COMMIT() asm volatile("cp.async.commit_group;\n" ::: "memory")

// =====================================================================
// Generic TF32 GEMM (proven; batched via blockIdx.z)
// =====================================================================
template<int BM, int BN, int TRANSB, int STAGES>
constexpr size_t tg_smem() {
    return (size_t)STAGES * ((size_t)BM * 36 + (TRANSB ? (size_t)BN * 36
                                                       : (size_t)32 * (BN + 8))) * 4;
}

template<int BM, int BN, int WM, int WN, int TRANSB, int STAGES>
__global__ __launch_bounds__(256)
void tgemm_k(const float* __restrict__ A, int lda, long long sA,
             const float* __restrict__ B, int ldb, long long sB,
             float* __restrict__ C, int ldc, long long sC,
             int K,
             const float* __restrict__ bias, long long sBias, int act)
{
    constexpr int BK   = 32;
    constexpr int WX   = BN / WN;
    constexpr int WY   = BM / WM;
    static_assert(WX * WY == 8, "8 warps");
    constexpr int MM   = WM / 16;
    constexpr int MN   = WN / 8;
    constexpr int AL   = BM * (BK / 4) / 256;
    constexpr int BLt  = BN * (BK / 4) / 256;
    constexpr int BLn  = BK * (BN / 4) / 256;
    constexpr int ASTR = BK + 4;
    constexpr int BNSTR= BN + 8;
    constexpr int ASZ  = BM * ASTR;
    constexpr int BSZ  = TRANSB ? BN * ASTR : BK * BNSTR;

    const int tid  = threadIdx.x;
    const int wid  = tid >> 5;
    const int lane = tid & 31;
    const int wx   = wid % WX;
    const int wy   = wid / WX;
    const int lg   = lane >> 2;
    const int lt   = lane & 3;
    const int m0   = blockIdx.y * BM;
    const int n0   = blockIdx.x * BN;

    const float* Ab    = A + sA * blockIdx.z;
    const float* Bb    = B + sB * blockIdx.z;
    float*       Cb    = C + sC * blockIdx.z;
    const float* biasb = bias ? bias + sBias * blockIdx.z : nullptr;

    extern __shared__ float smem[];
    float* AsBase = smem;
    float* BsBase = smem + (size_t)STAGES * ASZ;

    auto load_stage = [&](int s, int k0) {
        float* as = AsBase + (size_t)s * ASZ;
#pragma unroll
        for (int j = 0; j < AL; j++) {
            int idx = tid + j * 256;
            int m   = idx >> 3;
            int k4  = idx & 7;
            cpasync16(&as[m * ASTR + k4 * 4],
                      &Ab[(size_t)(m0 + m) * lda + k0 + k4 * 4]);
        }
        float* bs = BsBase + (size_t)s * BSZ;
        if (TRANSB) {
#pragma unroll
            for (int j = 0; j < BLt; j++) {
                int idx = tid + j * 256;
                int n   = idx >> 3;
                int k4  = idx & 7;
                cpasync16(&bs[n * ASTR + k4 * 4],
                          &Bb[(size_t)(n0 + n) * ldb + k0 + k4 * 4]);
            }
        } else {
#pragma unroll
            for (int j = 0; j < BLn; j++) {
                int idx = tid + j * 256;
                int k   = idx / (BN / 4);
                int n4  = idx % (BN / 4);
                cpasync16(&bs[k * BNSTR + n4 * 4],
                          &Bb[(size_t)(k0 + k) * ldb + n0 + n4 * 4]);
            }
        }
    };

    float acc[MM][MN][4];
#pragma unroll
    for (int i = 0; i < MM; i++)
#pragma unroll
        for (int j = 0; j < MN; j++)
#pragma unroll
            for (int c = 0; c < 4; c++) acc[i][j][c] = 0.f;

    const int ktiles = K / BK;
#pragma unroll
    for (int s = 0; s < STAGES - 1; s++) {
        if (s < ktiles) load_stage(s, s * BK);
        CP_COMMIT();
    }

    for (int t = 0; t < ktiles; t++) {
        asm volatile("cp.async.wait_group %0;\n" :: "n"(STAGES - 2) : "memory");
        __syncthreads();

        int nt = t + STAGES - 1;
        if (nt < ktiles) load_stage(nt % STAGES, nt * BK);
        CP_COMMIT();

        const float* as = AsBase + (size_t)(t % STAGES) * ASZ;
        const float* bs = BsBase + (size_t)(t % STAGES) * BSZ;

#pragma unroll
        for (int ks = 0; ks < BK / 8; ks++) {
            const int kk = ks * 8;
            unsigned af[MM][4], bf[MN][2];
#pragma unroll
            for (int i = 0; i < MM; i++) {
                int row = wy * WM + i * 16 + lg;
                af[i][0] = f2tf(as[row * ASTR + kk + lt]);
                af[i][1] = f2tf(as[(row + 8) * ASTR + kk + lt]);
                af[i][2] = f2tf(as[row * ASTR + kk + lt + 4]);
                af[i][3] = f2tf(as[(row + 8) * ASTR + kk + lt + 4]);
            }
#pragma unroll
            for (int j = 0; j < MN; j++) {
                int col = wx * WN + j * 8 + lg;
                if (TRANSB) {
                    bf[j][0] = f2tf(bs[col * ASTR + kk + lt]);
                    bf[j][1] = f2tf(bs[col * ASTR + kk + lt + 4]);
                } else {
                    bf[j][0] = f2tf(bs[(kk + lt) * BNSTR + col]);
                    bf[j][1] = f2tf(bs[(kk + lt + 4) * BNSTR + col]);
                }
            }
#pragma unroll
            for (int i = 0; i < MM; i++)
#pragma unroll
                for (int j = 0; j < MN; j++)
                    mma_tf32(acc[i][j], af[i], bf[j]);
        }
        __syncthreads();
    }

#pragma unroll
    for (int i = 0; i < MM; i++) {
        int mA = m0 + wy * WM + i * 16 + lg;
        int mB = mA + 8;
#pragma unroll
        for (int j = 0; j < MN; j++) {
            int n = n0 + wx * WN + j * 8 + lt * 2;
            float b0 = biasb ? biasb[n] : 0.f;
            float b1 = biasb ? biasb[n + 1] : 0.f;
            float v0 = acc[i][j][0] + b0;
            float v1 = acc[i][j][1] + b1;
            float v2 = acc[i][j][2] + b0;
            float v3 = acc[i][j][3] + b1;
            if (act == 1) {
                v0 = fmaxf(v0, 0.f); v1 = fmaxf(v1, 0.f);
                v2 = fmaxf(v2, 0.f); v3 = fmaxf(v3, 0.f);
            }
            Cb[(size_t)mA * ldc + n]     = v0;
            Cb[(size_t)mA * ldc + n + 1] = v1;
            Cb[(size_t)mB * ldc + n]     = v2;
            Cb[(size_t)mB * ldc + n + 1] = v3;
        }
    }
}

// =====================================================================
// Edge gather-GEMM v2 (proven): m2 = relu(relu(eA[tgt]+eB[src]+bm1)@Wm2+bm2)
// =====================================================================
#define EG_ASTR 36
#define EG_BSTR 136
#define EG_SMEM ((4*128*EG_ASTR + 2*32*EG_BSTR) * 4)   // 108544 B

__global__ __launch_bounds__(256)
void egemm_gather_k(const float* __restrict__ eA, const float* __restrict__ eB,
                    const float* __restrict__ b1, const int* __restrict__ ei,
                    const float* __restrict__ W, const float* __restrict__ b2,
                    float* __restrict__ C)
{
    __shared__ int   tgts[128], srcs[128];
    __shared__ float b1s[256];
    extern __shared__ float smem[];
    float* AsA = smem;
    float* AsB = smem + 2 * 128 * EG_ASTR;
    float* Bs  = smem + 4 * 128 * EG_ASTR;

    const int tid  = threadIdx.x;
    const int wid  = tid >> 5;
    const int lane = tid & 31;
    const int wx   = wid & 3;
    const int wy   = wid >> 2;
    const int lg   = lane >> 2;
    const int lt   = lane & 3;
    const int m0   = blockIdx.y * 128;
    const int n0   = blockIdx.x * 128;

    if (tid < 128) { srcs[tid] = ei[m0 + tid]; tgts[tid] = ei[EE + m0 + tid]; }
    b1s[tid] = b1[tid];
    __syncthreads();

    auto load_stage = [&](int s, int k0) {
        float* aA = AsA + s * 128 * EG_ASTR;
        float* aB = AsB + s * 128 * EG_ASTR;
#pragma unroll
        for (int j = 0; j < 4; j++) {
            int idx = tid + j * 256;
            int m = idx >> 3, k4 = idx & 7;
            cpasync16(&aA[m * EG_ASTR + k4 * 4],
                      &eA[(size_t)tgts[m] * QD + k0 + k4 * 4]);
            cpasync16(&aB[m * EG_ASTR + k4 * 4],
                      &eB[(size_t)srcs[m] * QD + k0 + k4 * 4]);
        }
        float* bs = Bs + s * 32 * EG_BSTR;
#pragma unroll
        for (int j = 0; j < 4; j++) {
            int idx = tid + j * 256;
            int k = idx >> 5, n4 = idx & 31;
            cpasync16(&bs[k * EG_BSTR + n4 * 4],
                      &W[(size_t)(k0 + k) * QD + n0 + n4 * 4]);
        }
    };
    load_stage(0, 0);
    CP_COMMIT();

    float acc[4][4][4];
#pragma unroll
    for (int i = 0; i < 4; i++)
#pragma unroll
        for (int j = 0; j < 4; j++)
#pragma unroll
            for (int c = 0; c < 4; c++) acc[i][j][c] = 0.f;

    for (int t = 0; t < 8; t++) {
        if (t + 1 < 8) load_stage((t + 1) & 1, (t + 1) * 32);
        CP_COMMIT();
        asm volatile("cp.async.wait_group 1;\n" ::: "memory");
        __syncthreads();

        const float* aA = AsA + (t & 1) * 128 * EG_ASTR;
        const float* aB = AsB + (t & 1) * 128 * EG_ASTR;
        const float* bs = Bs  + (t & 1) * 32 * EG_BSTR;
        const int kg0 = t * 32;

#pragma unroll
        for (int ks = 0; ks < 4; ks++) {
            const int kk = ks * 8;
            const float bA0 = b1s[kg0 + kk + lt];
            const float bA1 = b1s[kg0 + kk + lt + 4];
            unsigned af[4][4], bf[4][2];
#pragma unroll
            for (int i = 0; i < 4; i++) {
                int row = wy * 64 + i * 16 + lg;
                af[i][0] = f2tf(fmaxf(aA[row * EG_ASTR + kk + lt] +
                                      aB[row * EG_ASTR + kk + lt] + bA0, 0.f));
                af[i][1] = f2tf(fmaxf(aA[(row + 8) * EG_ASTR + kk + lt] +
                                      aB[(row + 8) * EG_ASTR + kk + lt] + bA0, 0.f));
                af[i][2] = f2tf(fmaxf(aA[row * EG_ASTR + kk + lt + 4] +
                                      aB[row * EG_ASTR + kk + lt + 4] + bA1, 0.f));
                af[i][3] = f2tf(fmaxf(aA[(row + 8) * EG_ASTR + kk + lt + 4] +
                                      aB[(row + 8) * EG_ASTR + kk + lt + 4] + bA1, 0.f));
            }
#pragma unroll
            for (int j = 0; j < 4; j++) {
                int col = wx * 32 + j * 8 + lg;
                bf[j][0] = f2tf(bs[(kk + lt) * EG_BSTR + col]);
                bf[j][1] = f2tf(bs[(kk + lt + 4) * EG_BSTR + col]);
            }
#pragma unroll
            for (int i = 0; i < 4; i++)
#pragma unroll
                for (int j = 0; j < 4; j++)
                    mma_tf32(acc[i][j], af[i], bf[j]);
        }
        __syncthreads();
    }

#pragma unroll
    for (int i = 0; i < 4; i++) {
        int mA = m0 + wy * 64 + i * 16 + lg;
        int mB = mA + 8;
#pragma unroll
        for (int j = 0; j < 4; j++) {
            int n = n0 + wx * 32 + j * 8 + lt * 2;
            float b0 = b2[n], b1v = b2[n + 1];
            C[(size_t)mA * QD + n]     = fmaxf(acc[i][j][0] + b0, 0.f);
            C[(size_t)mA * QD + n + 1] = fmaxf(acc[i][j][1] + b1v, 0.f);
            C[(size_t)mB * QD + n]     = fmaxf(acc[i][j][2] + b0, 0.f);
            C[(size_t)mB * QD + n + 1] = fmaxf(acc[i][j][3] + b1v, 0.f);
        }
    }
}

// =====================================================================
// Edge scatter-GEMM (proven): agg[tgt[e]] += m2[e] @ Wm3 + bm3
// =====================================================================
#define ES_SMEM ((3*128*EG_ASTR + 3*32*EG_BSTR) * 4)   // 107520 B

__global__ __launch_bounds__(256)
void egemm_scatter_k(const float* __restrict__ A, const int* __restrict__ ei,
                     const float* __restrict__ W, const float* __restrict__ b3,
                     float* __restrict__ agg)
{
    extern __shared__ float smem[];
    float* AsBase = smem;
    float* BsBase = smem + 3 * 128 * EG_ASTR;

    const int tid  = threadIdx.x;
    const int wid  = tid >> 5;
    const int lane = tid & 31;
    const int wx   = wid & 3;
    const int wy   = wid >> 2;
    const int lg   = lane >> 2;
    const int lt   = lane & 3;
    const int m0   = blockIdx.y * 128;
    const int n0   = blockIdx.x * 128;

    auto load_stage = [&](int s, int k0) {
        float* as = AsBase + s * 128 * EG_ASTR;
#pragma unroll
        for (int j = 0; j < 4; j++) {
            int idx = tid + j * 256;
            int m = idx >> 3, k4 = idx & 7;
            cpasync16(&as[m * EG_ASTR + k4 * 4],
                      &A[(size_t)(m0 + m) * QD + k0 + k4 * 4]);
        }
        float* bs = BsBase + s * 32 * EG_BSTR;
#pragma unroll
        for (int j = 0; j < 4; j++) {
            int idx = tid + j * 256;
            int k = idx >> 5, n4 = idx & 31;
            cpasync16(&bs[k * EG_BSTR + n4 * 4],
                      &W[(size_t)(k0 + k) * HDIM + n0 + n4 * 4]);
        }
    };
    load_stage(0, 0);  CP_COMMIT();
    load_stage(1, 32); CP_COMMIT();

    float acc[4][4][4];
#pragma unroll
    for (int i = 0; i < 4; i++)
#pragma unroll
        for (int j = 0; j < 4; j++)
#pragma unroll
            for (int c = 0; c < 4; c++) acc[i][j][c] = 0.f;

    for (int t = 0; t < 8; t++) {
        asm volatile("cp.async.wait_group 1;\n" ::: "memory");
        __syncthreads();

        if (t + 2 < 8) load_stage((t + 2) % 3, (t + 2) * 32);
        CP_COMMIT();

        const float* as = AsBase + (t % 3) * 128 * EG_ASTR;
        const float* bs = BsBase + (t % 3) * 32 * EG_BSTR;
#pragma unroll
        for (int ks = 0; ks < 4; ks++) {
            const int kk = ks * 8;
            unsigned af[4][4], bf[4][2];
#pragma unroll
            for (int i = 0; i < 4; i++) {
                int row = wy * 64 + i * 16 + lg;
                af[i][0] = f2tf(as[row * EG_ASTR + kk + lt]);
                af[i][1] = f2tf(as[(row + 8) * EG_ASTR + kk + lt]);
                af[i][2] = f2tf(as[row * EG_ASTR + kk + lt + 4]);
                af[i][3] = f2tf(as[(row + 8) * EG_ASTR + kk + lt + 4]);
            }
#pragma unroll
            for (int j = 0; j < 4; j++) {
                int col = wx * 32 + j * 8 + lg;
                bf[j][0] = f2tf(bs[(kk + lt) * EG_BSTR + col]);
                bf[j][1] = f2tf(bs[(kk + lt + 4) * EG_BSTR + col]);
            }
#pragma unroll
            for (int i = 0; i < 4; i++)
#pragma unroll
                for (int j = 0; j < 4; j++)
                    mma_tf32(acc[i][j], af[i], bf[j]);
        }
        __syncthreads();
    }

#pragma unroll
    for (int i = 0; i < 4; i++) {
        int mA = m0 + wy * 64 + i * 16 + lg;
        int mB = mA + 8;
        int tA = ei[EE + mA];
        int tB = ei[EE + mB];
#pragma unroll
        for (int j = 0; j < 4; j++) {
            int n = n0 + wx * 32 + j * 8 + lt * 2;
            float b0 = b3[n], b1v = b3[n + 1];
            atomicAdd(&agg[(size_t)tA * HDIM + n],     acc[i][j][0] + b0);
            atomicAdd(&agg[(size_t)tA * HDIM + n + 1], acc[i][j][1] + b1v);
            atomicAdd(&agg[(size_t)tB * HDIM + n],     acc[i][j][2] + b0);
            atomicAdd(&agg[(size_t)tB * HDIM + n + 1], acc[i][j][3] + b1v);
        }
    }
}

// =====================================================================
// Flash MHA (proven, unchanged)
// =====================================================================
#define FBQ   128
#define FBKV  64
#define QSTR  36
#define KSTR  36
#define VSTR  40
#define PSTR  68
#define FLASH_SMEM ((FBQ*QSTR + 2*FBKV*KSTR + 2*FBKV*VSTR + 8*16*PSTR) * 4)

__global__ __launch_bounds__(256)
void flash_mha_k(const float* __restrict__ mq, const float* __restrict__ mk,
                 const float* __restrict__ mv, float* __restrict__ mo, float scale)
{
    extern __shared__ float sm[];
    float*    Qs = sm;
    float*    Ks = Qs + FBQ * QSTR;
    float*    Vs = Ks + 2 * FBKV * KSTR;
    unsigned* Ps = (unsigned*)(Vs + 2 * FBKV * VSTR);

    const int tid  = threadIdx.x;
    const int wid  = tid >> 5;
    const int lane = tid & 31;
    const int lg   = lane >> 2;
    const int lt   = lane & 3;
    const int hh   = blockIdx.y;
    const int q0   = blockIdx.x * FBQ;

    const float* Qg = mq + (size_t)q0 * QD + hh * HD;
    const float* Kg = mk + hh * HD;
    const float* Vg = mv + hh * HD;

#pragma unroll
    for (int j = 0; j < 4; j++) {
        int idx = tid + j * 256;
        int r = idx >> 3, c4 = idx & 7;
        cpasync16(&Qs[r * QSTR + c4 * 4], &Qg[(size_t)r * QD + c4 * 4]);
    }
    auto loadKV = [&](int s, int kv0) {
        float* ks = Ks + s * FBKV * KSTR;
        float* vs = Vs + s * FBKV * VSTR;
#pragma unroll
        for (int j = 0; j < 2; j++) {
            int idx = tid + j * 256;
            int r = idx >> 3, c4 = idx & 7;
            cpasync16(&ks[r * KSTR + c4 * 4], &Kg[(size_t)(kv0 + r) * QD + c4 * 4]);
        }
#pragma unroll
        for (int j = 0; j < 2; j++) {
            int idx = tid + j * 256;
            int r = idx >> 3, c4 = idx & 7;
            cpasync16(&vs[r * VSTR + c4 * 4], &Vg[(size_t)(kv0 + r) * QD + c4 * 4]);
        }
    };
    loadKV(0, 0);
    CP_COMMIT();

    float O[4][4];
#pragma unroll
    for (int j = 0; j < 4; j++)
#pragma unroll
        for (int c = 0; c < 4; c++) O[j][c] = 0.f;
    float m0r = -3.4e38f, m1r = -3.4e38f;
    float l0 = 0.f, l1 = 0.f;
    unsigned* Pw = Ps + wid * 16 * PSTR;
    const int qrow = wid * 16 + lg;

    const int NT = NN / FBKV;
    for (int t = 0; t < NT; t++) {
        if (t + 1 < NT) loadKV((t + 1) & 1, (t + 1) * FBKV);
        CP_COMMIT();
        asm volatile("cp.async.wait_group 1;\n" ::: "memory");
        __syncthreads();

        const float* ks = Ks + (t & 1) * FBKV * KSTR;
        const float* vs = Vs + (t & 1) * FBKV * VSTR;

        float Sacc[8][4];
#pragma unroll
        for (int n = 0; n < 8; n++)
#pragma unroll
            for (int c = 0; c < 4; c++) Sacc[n][c] = 0.f;
#pragma unroll
        for (int ks8 = 0; ks8 < 4; ks8++) {
            const int kk = ks8 * 8;
            unsigned af[4];
            af[0] = f2tf(Qs[qrow * QSTR + kk + lt]);
            af[1] = f2tf(Qs[(qrow + 8) * QSTR + kk + lt]);
            af[2] = f2tf(Qs[qrow * QSTR + kk + lt + 4]);
            af[3] = f2tf(Qs[(qrow + 8) * QSTR + kk + lt + 4]);
#pragma unroll
            for (int n = 0; n < 8; n++) {
                int col = n * 8 + lg;
                unsigned bf[2];
                bf[0] = f2tf(ks[col * KSTR + kk + lt]);
                bf[1] = f2tf(ks[col * KSTR + kk + lt + 4]);
                mma_tf32(Sacc[n], af, bf);
            }
        }

        float mx0 = -3.4e38f, mx1 = -3.4e38f;
#pragma unroll
        for (int n = 0; n < 8; n++) {
            Sacc[n][0] *= scale; Sacc[n][1] *= scale;
            Sacc[n][2] *= scale; Sacc[n][3] *= scale;
            mx0 = fmaxf(mx0, fmaxf(Sacc[n][0], Sacc[n][1]));
            mx1 = fmaxf(mx1, fmaxf(Sacc[n][2], Sacc[n][3]));
        }
        mx0 = fmaxf(mx0, __shfl_xor_sync(0xffffffffu, mx0, 1));
        mx0 = fmaxf(mx0, __shfl_xor_sync(0xffffffffu, mx0, 2));
        mx1 = fmaxf(mx1, __shfl_xor_sync(0xffffffffu, mx1, 1));
        mx1 = fmaxf(mx1, __shfl_xor_sync(0xffffffffu, mx1, 2));
        float mn0 = fmaxf(m0r, mx0), mn1 = fmaxf(m1r, mx1);
        float a0 = __expf(m0r - mn0), a1 = __expf(m1r - mn1);
        float rs0 = 0.f, rs1 = 0.f;
#pragma unroll
        for (int n = 0; n < 8; n++) {
            float p0 = __expf(Sacc[n][0] - mn0);
            float p1 = __expf(Sacc[n][1] - mn0);
            float p2 = __expf(Sacc[n][2] - mn1);
            float p3 = __expf(Sacc[n][3] - mn1);
            rs0 += p0 + p1; rs1 += p2 + p3;
            int c0 = n * 8 + lt * 2;
            Pw[lg * PSTR + c0]           = f2tf(p0);
            Pw[lg * PSTR + c0 + 1]       = f2tf(p1);
            Pw[(lg + 8) * PSTR + c0]     = f2tf(p2);
            Pw[(lg + 8) * PSTR + c0 + 1] = f2tf(p3);
        }
        rs0 += __shfl_xor_sync(0xffffffffu, rs0, 1);
        rs0 += __shfl_xor_sync(0xffffffffu, rs0, 2);
        rs1 += __shfl_xor_sync(0xffffffffu, rs1, 1);
        rs1 += __shfl_xor_sync(0xffffffffu, rs1, 2);
        l0 = l0 * a0 + rs0;
        l1 = l1 * a1 + rs1;
        m0r = mn0; m1r = mn1;
#pragma unroll
        for (int j = 0; j < 4; j++) {
            O[j][0] *= a0; O[j][1] *= a0;
            O[j][2] *= a1; O[j][3] *= a1;
        }
        __syncwarp();

#pragma unroll
        for (int ks8 = 0; ks8 < 8; ks8++) {
            const int kk = ks8 * 8;
            unsigned af[4];
            af[0] = Pw[lg * PSTR + kk + lt];
            af[1] = Pw[(lg + 8) * PSTR + kk + lt];
            af[2] = Pw[lg * PSTR + kk + lt + 4];
            af[3] = Pw[(lg + 8) * PSTR + kk + lt + 4];
#pragma unroll
            for (int j = 0; j < 4; j++) {
                int col = j * 8 + lg;
                unsigned bf[2];
                bf[0] = f2tf(vs[(kk + lt) * VSTR + col]);
                bf[1] = f2tf(vs[(kk + lt + 4) * VSTR + col]);
                mma_tf32(O[j], af, bf);
            }
        }
        __syncwarp();
        __syncthreads();
    }

    float inv0 = 1.f / l0, inv1 = 1.f / l1;
    const size_t rA = (size_t)(q0 + qrow) * QD + hh * HD;
    const size_t rB = rA + 8 * QD;
#pragma unroll
    for (int j = 0; j < 4; j++) {
        int c = j * 8 + lt * 2;
        mo[rA + c]     = O[j][0] * inv0;
        mo[rA + c + 1] = O[j][1] * inv0;
        mo[rB + c]     = O[j][2] * inv1;
        mo[rB + c + 1] = O[j][3] * inv1;
    }
}

// =====================================================================
// Sparse graph attention (proven, unchanged)
// =====================================================================
__global__ __launch_bounds__(128)
void sparse_gatt_k(const float* __restrict__ Q, const float* __restrict__ K,
                   const float* __restrict__ V, const unsigned* __restrict__ mask,
                   const float* __restrict__ vmean, float* __restrict__ gatt,
                   float scale)
{
    __shared__ int   idxs[NN];
    __shared__ float sc  [NN];
    __shared__ int   wbase[5];
    __shared__ float red[4];

    const int s    = blockIdx.x;
    const int tid  = threadIdx.x;
    const int wid  = tid >> 5;
    const int lane = tid & 31;

    unsigned w = mask[(size_t)s * MW + tid];
    int c = __popc(w);
    int pre = c;
#pragma unroll
    for (int o = 1; o < 32; o <<= 1) {
        int v = __shfl_up_sync(0xffffffffu, pre, o);
        if (lane >= o) pre += v;
    }
    if (lane == 31) wbase[wid + 1] = pre;
    __syncthreads();
    if (tid == 0) {
        wbase[0] = 0;
        wbase[2] += wbase[1];
        wbase[3] += wbase[2];
        wbase[4] += wbase[3];
    }
    __syncthreads();
    const int cnt = wbase[4];
    int p = wbase[wid] + pre - c;
    unsigned ww = w;
    while (ww) {
        int b = __ffs(ww) - 1;
        idxs[p++] = tid * 32 + b;
        ww &= ww - 1;
    }
    __syncthreads();

    const int c0 = tid * 2;
    if (cnt == 0) {
        gatt[(size_t)s * QD + c0]     = vmean[c0];
        gatt[(size_t)s * QD + c0 + 1] = vmean[c0 + 1];
        return;
    }

    float q[8];
    const float* Qr = Q + (size_t)s * QD;
#pragma unroll
    for (int i = 0; i < 8; i++) q[i] = Qr[lane * 8 + i];
    for (int e = wid; e < cnt; e += 4) {
        const float* Kr = K + (size_t)idxs[e] * QD;
        float d = 0.f;
#pragma unroll
        for (int i = 0; i < 8; i++) d = fmaf(q[i], Kr[lane * 8 + i], d);
#pragma unroll
        for (int o = 16; o; o >>= 1) d += __shfl_xor_sync(0xffffffffu, d, o);
        if (lane == 0) sc[e] = d * scale;
    }
    __syncthreads();

    float mx = -3.4e38f;
    for (int e = tid; e < cnt; e += 128) mx = fmaxf(mx, sc[e]);
#pragma unroll
    for (int o = 16; o; o >>= 1) mx = fmaxf(mx, __shfl_xor_sync(0xffffffffu, mx, o));
    if (lane == 0) red[wid] = mx;
    __syncthreads();
    mx = fmaxf(fmaxf(red[0], red[1]), fmaxf(red[2], red[3]));
    __syncthreads();

    float sum = 0.f;
    for (int e = tid; e < cnt; e += 128) {
        float pe = __expf(sc[e] - mx);
        sc[e] = pe;
        sum += pe;
    }
#pragma unroll
    for (int o = 16; o; o >>= 1) sum += __shfl_xor_sync(0xffffffffu, sum, o);
    if (lane == 0) red[wid] = sum;
    __syncthreads();
    float inv = 1.f / (red[0] + red[1] + red[2] + red[3]);

    float a0 = 0.f, a1 = 0.f;
    for (int e = 0; e < cnt; e++) {
        const float* Vr = V + (size_t)idxs[e] * QD;
        float pe = sc[e];
        a0 = fmaf(pe, Vr[c0], a0);
        a1 = fmaf(pe, Vr[c0 + 1], a1);
    }
    gatt[(size_t)s * QD + c0]     = a0 * inv;
    gatt[(size_t)s * QD + c0 + 1] = a1 * inv;
}

// ---------------- block reductions ----------------
__device__ __forceinline__ float blkMax(float v) {
    __shared__ float sh[8];
#pragma unroll
    for (int o = 16; o; o >>= 1) v = fmaxf(v, __shfl_xor_sync(0xffffffffu, v, o));
    if ((threadIdx.x & 31) == 0) sh[threadIdx.x >> 5] = v;
    __syncthreads();
    if (threadIdx.x < 32) {
        float w = (threadIdx.x < 8) ? sh[threadIdx.x] : -3.4e38f;
#pragma unroll
        for (int o = 4; o; o >>= 1) w = fmaxf(w, __shfl_xor_sync(0xffffffffu, w, o));
        if (threadIdx.x == 0) sh[0] = w;
    }
    __syncthreads();
    float r = sh[0];
    __syncthreads();
    return r;
}
__device__ __forceinline__ float blkSum(float v) {
    __shared__ float sh[8];
#pragma unroll
    for (int o = 16; o; o >>= 1) v += __shfl_xor_sync(0xffffffffu, v, o);
    if ((threadIdx.x & 31) == 0) sh[threadIdx.x >> 5] = v;
    __syncthreads();
    if (threadIdx.x < 32) {
        float w = (threadIdx.x < 8) ? sh[threadIdx.x] : 0.f;
#pragma unroll
        for (int o = 4; o; o >>= 1) w += __shfl_xor_sync(0xffffffffu, w, o);
        if (threadIdx.x == 0) sh[0] = w;
    }
    __syncthreads();
    float r = sh[0];
    __syncthreads();
    return r;
}

// ---------------- elementwise / small kernels ----------------
__global__ void zero_u32_k(unsigned* __restrict__ p, int n) {
    int i = blockIdx.x * blockDim.x + threadIdx.x;
    if (i < n) p[i] = 0u;
}
__global__ void zero_f32_k(float* __restrict__ p, int n) {
    int i = blockIdx.x * blockDim.x + threadIdx.x;
    if (i < n) p[i] = 0.f;
}
__global__ void build_mask_k(const int* __restrict__ ei, unsigned* __restrict__ mask) {
    int e = blockIdx.x * blockDim.x + threadIdx.x;
    if (e >= EE) return;
    int s = ei[e], t = ei[EE + e];
    atomicOr(&mask[(size_t)s * MW + (t >> 5)], 1u << (t & 31));
}
__global__ void stage_qkv_k(const float* __restrict__ Wq, const float* __restrict__ Wk,
                            const float* __restrict__ Wv, const float* __restrict__ bq,
                            const float* __restrict__ bk, const float* __restrict__ bv,
                            float* __restrict__ W3, float* __restrict__ b3) {
    int i = blockIdx.x * blockDim.x + threadIdx.x;
    const int per = HDIM * QD;
    if (i < 2 * per) {
        int l = i / per, r = i % per;
        W3[((size_t)l * 3 + 0) * per + r] = Wq[i];
        W3[((size_t)l * 3 + 1) * per + r] = Wk[i];
        W3[((size_t)l * 3 + 2) * per + r] = Wv[i];
    }
    if (i < 2 * QD) {
        int l = i / QD, r = i % QD;
        b3[(l * 3 + 0) * QD + r] = bq[i];
        b3[(l * 3 + 1) * QD + r] = bk[i];
        b3[(l * 3 + 2) * QD + r] = bv[i];
    }
}
__global__ void stage_bc_k(const float* __restrict__ Bc, float* __restrict__ Bc2) {
    int i = blockIdx.x * blockDim.x + threadIdx.x;
    if (i >= 2 * QD * QD) return;
    int l = i / (QD * QD), r = i % (QD * QD);
    int row = r / QD, col = r % QD;
    Bc2[((size_t)l * 2 + 0) * QD * QD + r] = Bc[i];
    Bc2[((size_t)l * 2 + 1) * QD * QD + (size_t)row * QD + col] =
        Bc[(size_t)l * QD * QD + (size_t)col * QD + row];
}
__global__ void vmean_k(const float* __restrict__ V, float* __restrict__ vm) {
    int c = blockIdx.x;
    float s = 0.f;
    for (int r = threadIdx.x; r < NN; r += 256) s += V[(size_t)r * QD + c];
    s = blkSum(s);
    if (threadIdx.x == 0) vm[c] = s * (1.f / NN);
}
__global__ void add_ce_k(float4* __restrict__ Q, float4* __restrict__ K,
                         const float4* __restrict__ ce, const int* __restrict__ ct) {
    int idx = blockIdx.x * blockDim.x + threadIdx.x;
    if (idx >= NN * (QD / 4)) return;
    int i = idx >> 6, j4 = idx & 63;
    float4 c = ce[ct[i] * (QD / 4) + j4];
    float4 q = Q[idx], k = K[idx];
    q.x += 0.1f * c.x; q.y += 0.1f * c.y; q.z += 0.1f * c.z; q.w += 0.1f * c.w;
    k.x += 0.1f * c.x; k.y += 0.1f * c.y; k.z += 0.1f * c.z; k.w += 0.1f * c.w;
    Q[idx] = q; K[idx] = k;
}
__global__ void combine_ln_k(float* __restrict__ h, const float* __restrict__ agg,
                             const float* __restrict__ mha, const float* __restrict__ gatt,
                             const float* __restrict__ g, const float* __restrict__ b) {
    int r = blockIdx.x, j = threadIdx.x;
    size_t idx = (size_t)r * HDIM + j;
    float v = h[idx] + agg[idx] + mha[idx] + gatt[idx];
    float mu = blkSum(v) * (1.f / HDIM);
    float d = v - mu;
    float var = blkSum(d * d) * (1.f / HDIM);
    h[idx] = d * rsqrtf(var + 1e-5f) * g[j] + b[j];
}
__global__ void pool_k(const float* __restrict__ h, float* __restrict__ pool) {
    int c = blockIdx.x, t = threadIdx.x;
    if (c < HDIM) {
        float s = 0.f;
        for (int r = t; r < NN; r += 256) s += h[(size_t)r * HDIM + c];
        s = blkSum(s);
        if (t == 0) pool[c] = s * (1.f / NN);
    } else {
        int cc = c - HDIM;
        float m = -3.4e38f;
        for (int r = t; r < NN; r += 256) m = fmaxf(m, h[(size_t)r * HDIM + cc]);
        m = blkMax(m);
        if (t == 0) pool[c] = m;
    }
}
__global__ void fc1_k(const float* __restrict__ pool, const float* __restrict__ W,
                      const float* __restrict__ b, float* __restrict__ z) {
    int o = blockIdx.x, t = threadIdx.x;
    float s = 0.f;
    for (int i = t; i < 2 * HDIM; i += 256) s += pool[i] * W[(size_t)i * HDIM + o];
    s = blkSum(s);
    if (t == 0) z[o] = fmaxf(s + b[o], 0.f);
}
__global__ void fc2_k(const float* __restrict__ z, const float* __restrict__ W,
                      const float* __restrict__ b, float* __restrict__ out) {
    int o = blockIdx.x, t = threadIdx.x;
    float s = 0.f;
    for (int i = t; i < HDIM; i += 256) s += z[i] * W[(size_t)i * OUTD + o];
    s = blkSum(s);
    if (t == 0) out[o] = s + b[o];
}

// ---------------- host side ----------------
static float* sym(const void* s) {
    void* p = nullptr;
    cudaGetSymbolAddress(&p, (const void*)s);
    return (float*)p;
}

#define NODE  64,128,32,32

template<int BM,int BN,int WM,int WN,int TRANSB,int STAGES>
static void launch_tg(dim3 grid, cudaStream_t st,
                      const float* A, int lda, long long sA,
                      const float* B, int ldb, long long sB,
                      float* C, int ldc, long long sC, int K,
                      const float* bias, long long sBias, int act)
{
    constexpr size_t sm = tg_smem<BM, BN, TRANSB, STAGES>();
    static bool attr_done = false;
    if (!attr_done) {
        cudaFuncSetAttribute(tgemm_k<BM,BN,WM,WN,TRANSB,STAGES>,
                             cudaFuncAttributeMaxDynamicSharedMemorySize, (int)sm);
        attr_done = true;
    }
    tgemm_k<BM,BN,WM,WN,TRANSB,STAGES><<<grid, 256, sm, st>>>(
        A, lda, sA, B, ldb, sB, C, ldc, sC, K, bias, sBias, act);
}

extern "C" void kernel_launch(void* const* d_in, const int* in_sizes, int n_in,
                              void* d_out, int out_size) {
    const float* x    = (const float*)d_in[0];
    const int*   ei   = (const int*)  d_in[1];
    const int*   ct   = (const int*)  d_in[2];
    const float* Wi   = (const float*)d_in[3];
    const float* bi   = (const float*)d_in[4];
    const float* Wq   = (const float*)d_in[5];
    const float* bq   = (const float*)d_in[6];
    const float* Wk   = (const float*)d_in[7];
    const float* bk   = (const float*)d_in[8];
    const float* Wv   = (const float*)d_in[9];
    const float* bv   = (const float*)d_in[10];
    const float* Bc   = (const float*)d_in[11];
    const float* cemb = (const float*)d_in[12];
    const float* Win  = (const float*)d_in[13];
    const float* binp = (const float*)d_in[14];
    const float* Wo   = (const float*)d_in[15];
    const float* bo   = (const float*)d_in[16];
    const float* Wm1  = (const float*)d_in[17];
    const float* bm1  = (const float*)d_in[18];
    const float* Wm2  = (const float*)d_in[19];
    const float* bm2  = (const float*)d_in[20];
    const float* Wm3  = (const float*)d_in[21];
    const float* bm3  = (const float*)d_in[22];
    const float* lng  = (const float*)d_in[23];
    const float* lnb  = (const float*)d_in[24];
    const float* Wc1  = (const float*)d_in[25];
    const float* bc1  = (const float*)d_in[26];
    const float* Wc2  = (const float*)d_in[27];
    const float* bc2  = (const float*)d_in[28];
    float* out = (float*)d_out;

    float* h    = sym(g_h);
    float* bufA = sym(g_bufA);
    float* bufB = sym(g_bufB);
    float* bufC = sym(g_bufC);
    float* bufD = sym(g_bufD);
    float* W3   = sym(g_W3);
    float* b3s  = sym(g_b3);
    float* Bc2  = sym(g_Bc2);
    float* vm   = sym(g_vm);
    float* gatt = sym(g_gatt);
    float* mo   = sym(g_mo);
    float* mha  = sym(g_mha);
    float* m2   = sym(g_m2);
    float* agg  = sym(g_agg);
    float* pool = sym(g_pool);
    float* z    = sym(g_z);
    unsigned* mask = (unsigned*)sym(g_mask);

    const int TPB = 256;
    const long long HQD = (long long)HDIM * QD;
    cudaStream_t s0 = 0;   // captured stream (legacy default)

    static cudaStream_t s2 = nullptr;
    static cudaEvent_t  evR[LL], evB[LL];
    static bool attrs = false;
    if (!attrs) {
        cudaFuncSetAttribute(flash_mha_k,
                             cudaFuncAttributeMaxDynamicSharedMemorySize, FLASH_SMEM);
        cudaFuncSetAttribute(egemm_gather_k,
                             cudaFuncAttributeMaxDynamicSharedMemorySize, EG_SMEM);
        cudaFuncSetAttribute(egemm_scatter_k,
                             cudaFuncAttributeMaxDynamicSharedMemorySize, ES_SMEM);
        cudaStreamCreateWithFlags(&s2, cudaStreamNonBlocking);
        for (int i = 0; i < LL; i++) {
            cudaEventCreateWithFlags(&evR[i], cudaEventDisableTiming);
            cudaEventCreateWithFlags(&evB[i], cudaEventDisableTiming);
        }
        attrs = true;
    }

    // adjacency mask + staged weights (main stream)
    zero_u32_k<<<(NN * MW + TPB - 1) / TPB, TPB>>>(mask, NN * MW);
    build_mask_k<<<(EE + TPB - 1) / TPB, TPB>>>(ei, mask);
    stage_qkv_k<<<(2 * HDIM * QD + TPB - 1) / TPB, TPB>>>(Wq, Wk, Wv, bq, bk, bv, W3, b3s);
    stage_bc_k<<<(2 * QD * QD + TPB - 1) / TPB, TPB>>>(Bc, Bc2);

    // h = relu(x @ Wi + bi)
    launch_tg<NODE,0,3>(dim3(HDIM/128, NN/64, 1), s0,
        x, IND, 0, Wi, HDIM, 0, h, HDIM, 0, IND, bi, 0, 1);

    for (int l = 0; l < LL; l++) {
        const float* ce_l  = cemb + (size_t)l * 50 * QD;
        const float* Win_l = Win + (size_t)l * QD * 3 * QD;
        const float* bin_l = binp + (size_t)l * 3 * QD;
        const float* Wo_l  = Wo  + (size_t)l * QD * QD;
        const float* Wm1_l = Wm1 + (size_t)l * (2 * HDIM + QD) * QD;
        const float* Wm2_l = Wm2 + (size_t)l * QD * QD;
        const float* Wm3_l = Wm3 + (size_t)l * QD * HDIM;

        dim3 gNode(QD/128, NN/64, 1);

        // ---- fork: edge branch (B) on side stream, depends only on h ----
        cudaEventRecord(evR[l], s0);
        cudaStreamWaitEvent(s2, evR[l], 0);
        launch_tg<NODE,0,3>(dim3(QD/128, NN/64, 2), s2,
            h, HDIM, 0, Wm1_l, QD, HQD,
            bufD, QD, NNQD, HDIM, nullptr, 0, 0);
        zero_f32_k<<<(NN * HDIM + TPB - 1) / TPB, TPB, 0, s2>>>(agg, NN * HDIM);
        egemm_gather_k<<<dim3(QD/128, EE/128), 256, EG_SMEM, s2>>>(
            bufD, bufD + NNQD, bm1 + l * QD, ei, Wm2_l, bm2 + l * QD, m2);
        egemm_scatter_k<<<dim3(HDIM/128, EE/128), 256, ES_SMEM, s2>>>(
            m2, ei, Wm3_l, bm3 + l * HDIM, agg);
        cudaEventRecord(evB[l], s2);

        // ---- branch A on main stream ----
        // batched {Qt,Kt} projections -> bufA ; V directly -> bufB[2]
        launch_tg<NODE,0,3>(dim3(QD/128, NN/64, 2), s0,
            h, HDIM, 0, W3 + (size_t)l * 3 * HQD, QD, HQD,
            bufA, QD, NNQD, HDIM, b3s + l * 3 * QD, QD, 0);
        launch_tg<NODE,0,3>(gNode, s0,
            h, HDIM, 0, W3 + (size_t)l * 3 * HQD + 2 * HQD, QD, 0,
            bufB + 2 * NNQD, QD, 0, HDIM, b3s + l * 3 * QD + 2 * QD, 0, 0);
        // batched biological constraint: {Q,K} = {Qt@Bc, Kt@BcT}
        launch_tg<NODE,0,3>(dim3(QD/128, NN/64, 2), s0,
            bufA, QD, NNQD, Bc2 + (size_t)l * 2 * QD * QD, QD, (long long)QD * QD,
            bufB, QD, NNQD, QD, nullptr, 0, 0);
        add_ce_k<<<(NN * QD / 4 + TPB - 1) / TPB, TPB, 0, s0>>>(
            (float4*)bufB, (float4*)(bufB + NNQD), (const float4*)ce_l, ct);

        // sparse graph-masked attention (exact)
        vmean_k<<<QD, 256, 0, s0>>>(bufB + 2 * NNQD, vm);
        sparse_gatt_k<<<NN, 128, 0, s0>>>(bufB, bufB + NNQD, bufB + 2 * NNQD, mask, vm,
                                          gatt, 0.0625f);

        // batched MHA input projections: bufC {mq, mk, mv}
        launch_tg<NODE,0,3>(dim3(QD/128, NN/64, 3), s0,
            bufB, QD, NNQD, Win_l, 3*QD, QD,
            bufC, QD, NNQD, QD, bin_l, QD, 0);

        // fused flash MHA
        flash_mha_k<<<dim3(NN/FBQ, NHD), 256, FLASH_SMEM, s0>>>(
            bufC, bufC + NNQD, bufC + 2 * NNQD, mo, 0.17677669529663687f);

        launch_tg<NODE,0,3>(gNode, s0, mo, QD, 0, Wo_l, QD, 0, mha, QD, 0,
                            QD, bo + l * QD, 0, 0);

        // ---- join, then residual + aggregate + LN ----
        cudaStreamWaitEvent(s0, evB[l], 0);
        combine_ln_k<<<NN, HDIM, 0, s0>>>(h, agg, mha, gatt,
                                          lng + l * HDIM, lnb + l * HDIM);
    }

    // readout
    pool_k<<<2 * HDIM, 256, 0, s0>>>(h, pool);
    fc1_k<<<HDIM, 256, 0, s0>>>(pool, Wc1, bc1, z);
    fc2_k<<<OUTD, 256, 0, s0>>>(z, Wc2, bc2, out);
}

// round 17
// speedup vs baseline: 1.6080x; 1.0284x over previous
#include <cuda_runtime.h>
#include <math.h>

// ---------------- problem constants ----------------
#define NN   4096
#define EE   65536
#define IND  512
#define HDIM 256
#define QD   256
#define NHD  8
#define HD   32
#define OUTD 10
#define LL   2
#define MW   (NN/32)
#define NNQD ((long long)NN*QD)

// ---------------- static scratch ----------------
__device__ float    g_h   [NN*HDIM];
__device__ float    g_bufA[2*NN*QD];     // Qt, Kt
__device__ float    g_bufB[3*NN*QD];     // Q, K, V
__device__ float    g_bufC[3*NN*QD];     // mq, mk, mv
__device__ float    g_bufD[2*NN*QD];     // eA, eB
__device__ float    g_W3  [2*3*HDIM*QD];
__device__ float    g_b3  [2*3*QD];
__device__ float    g_Bc2 [2*2*QD*QD];   // staged [Bc | BcT] per layer
__device__ float    g_vm  [QD];
__device__ float    g_gatt[NN*QD];
__device__ float    g_mo  [NN*QD];
__device__ float    g_mha [NN*QD];
__device__ float    g_m2  [(size_t)EE*QD];   // 64MB (only edge intermediate)
__device__ unsigned g_mask[(size_t)NN*MW];
__device__ float    g_agg [NN*HDIM];
__device__ float    g_pool[2*HDIM];
__device__ float    g_z   [HDIM];

// ---------------- TF32 helpers ----------------
__device__ __forceinline__ unsigned f2tf(float f) {
    unsigned u;
    asm("cvt.rna.tf32.f32 %0, %1;" : "=r"(u) : "f"(f));
    return u;
}
__device__ __forceinline__ void mma_tf32(float* c, const unsigned* a, const unsigned* b) {
    asm volatile(
        "mma.sync.aligned.m16n8k8.row.col.f32.tf32.tf32.f32 "
        "{%0,%1,%2,%3}, {%4,%5,%6,%7}, {%8,%9}, {%0,%1,%2,%3};"
        : "+f"(c[0]), "+f"(c[1]), "+f"(c[2]), "+f"(c[3])
        : "r"(a[0]), "r"(a[1]), "r"(a[2]), "r"(a[3]), "r"(b[0]), "r"(b[1]));
}
__device__ __forceinline__ void cpasync16(void* sdst, const void* gsrc) {
    unsigned sa = (unsigned)__cvta_generic_to_shared(sdst);
    asm volatile("cp.async.cg.shared.global [%0], [%1], 16;\n" :: "r"(sa), "l"(gsrc));
}
#define CP_COMMIT() asm volatile("cp.async.commit_group;\n" ::: "memory")

// =====================================================================
// Generic TF32 GEMM (proven; batched via blockIdx.z)
// =====================================================================
template<int BM, int BN, int TRANSB, int STAGES>
constexpr size_t tg_smem() {
    return (size_t)STAGES * ((size_t)BM * 36 + (TRANSB ? (size_t)BN * 36
                                                       : (size_t)32 * (BN + 8))) * 4;
}

template<int BM, int BN, int WM, int WN, int TRANSB, int STAGES>
__global__ __launch_bounds__(256)
void tgemm_k(const float* __restrict__ A, int lda, long long sA,
             const float* __restrict__ B, int ldb, long long sB,
             float* __restrict__ C, int ldc, long long sC,
             int K,
             const float* __restrict__ bias, long long sBias, int act)
{
    constexpr int BK   = 32;
    constexpr int WX   = BN / WN;
    constexpr int WY   = BM / WM;
    static_assert(WX * WY == 8, "8 warps");
    constexpr int MM   = WM / 16;
    constexpr int MN   = WN / 8;
    constexpr int AL   = BM * (BK / 4) / 256;
    constexpr int BLt  = BN * (BK / 4) / 256;
    constexpr int BLn  = BK * (BN / 4) / 256;
    constexpr int ASTR = BK + 4;
    constexpr int BNSTR= BN + 8;
    constexpr int ASZ  = BM * ASTR;
    constexpr int BSZ  = TRANSB ? BN * ASTR : BK * BNSTR;

    const int tid  = threadIdx.x;
    const int wid  = tid >> 5;
    const int lane = tid & 31;
    const int wx   = wid % WX;
    const int wy   = wid / WX;
    const int lg   = lane >> 2;
    const int lt   = lane & 3;
    const int m0   = blockIdx.y * BM;
    const int n0   = blockIdx.x * BN;

    const float* Ab    = A + sA * blockIdx.z;
    const float* Bb    = B + sB * blockIdx.z;
    float*       Cb    = C + sC * blockIdx.z;
    const float* biasb = bias ? bias + sBias * blockIdx.z : nullptr;

    extern __shared__ float smem[];
    float* AsBase = smem;
    float* BsBase = smem + (size_t)STAGES * ASZ;

    auto load_stage = [&](int s, int k0) {
        float* as = AsBase + (size_t)s * ASZ;
#pragma unroll
        for (int j = 0; j < AL; j++) {
            int idx = tid + j * 256;
            int m   = idx >> 3;
            int k4  = idx & 7;
            cpasync16(&as[m * ASTR + k4 * 4],
                      &Ab[(size_t)(m0 + m) * lda + k0 + k4 * 4]);
        }
        float* bs = BsBase + (size_t)s * BSZ;
        if (TRANSB) {
#pragma unroll
            for (int j = 0; j < BLt; j++) {
                int idx = tid + j * 256;
                int n   = idx >> 3;
                int k4  = idx & 7;
                cpasync16(&bs[n * ASTR + k4 * 4],
                          &Bb[(size_t)(n0 + n) * ldb + k0 + k4 * 4]);
            }
        } else {
#pragma unroll
            for (int j = 0; j < BLn; j++) {
                int idx = tid + j * 256;
                int k   = idx / (BN / 4);
                int n4  = idx % (BN / 4);
                cpasync16(&bs[k * BNSTR + n4 * 4],
                          &Bb[(size_t)(k0 + k) * ldb + n0 + n4 * 4]);
            }
        }
    };

    float acc[MM][MN][4];
#pragma unroll
    for (int i = 0; i < MM; i++)
#pragma unroll
        for (int j = 0; j < MN; j++)
#pragma unroll
            for (int c = 0; c < 4; c++) acc[i][j][c] = 0.f;

    const int ktiles = K / BK;
#pragma unroll
    for (int s = 0; s < STAGES - 1; s++) {
        if (s < ktiles) load_stage(s, s * BK);
        CP_COMMIT();
    }

    for (int t = 0; t < ktiles; t++) {
        asm volatile("cp.async.wait_group %0;\n" :: "n"(STAGES - 2) : "memory");
        __syncthreads();

        int nt = t + STAGES - 1;
        if (nt < ktiles) load_stage(nt % STAGES, nt * BK);
        CP_COMMIT();

        const float* as = AsBase + (size_t)(t % STAGES) * ASZ;
        const float* bs = BsBase + (size_t)(t % STAGES) * BSZ;

#pragma unroll
        for (int ks = 0; ks < BK / 8; ks++) {
            const int kk = ks * 8;
            unsigned af[MM][4], bf[MN][2];
#pragma unroll
            for (int i = 0; i < MM; i++) {
                int row = wy * WM + i * 16 + lg;
                af[i][0] = f2tf(as[row * ASTR + kk + lt]);
                af[i][1] = f2tf(as[(row + 8) * ASTR + kk + lt]);
                af[i][2] = f2tf(as[row * ASTR + kk + lt + 4]);
                af[i][3] = f2tf(as[(row + 8) * ASTR + kk + lt + 4]);
            }
#pragma unroll
            for (int j = 0; j < MN; j++) {
                int col = wx * WN + j * 8 + lg;
                if (TRANSB) {
                    bf[j][0] = f2tf(bs[col * ASTR + kk + lt]);
                    bf[j][1] = f2tf(bs[col * ASTR + kk + lt + 4]);
                } else {
                    bf[j][0] = f2tf(bs[(kk + lt) * BNSTR + col]);
                    bf[j][1] = f2tf(bs[(kk + lt + 4) * BNSTR + col]);
                }
            }
#pragma unroll
            for (int i = 0; i < MM; i++)
#pragma unroll
                for (int j = 0; j < MN; j++)
                    mma_tf32(acc[i][j], af[i], bf[j]);
        }
        __syncthreads();
    }

#pragma unroll
    for (int i = 0; i < MM; i++) {
        int mA = m0 + wy * WM + i * 16 + lg;
        int mB = mA + 8;
#pragma unroll
        for (int j = 0; j < MN; j++) {
            int n = n0 + wx * WN + j * 8 + lt * 2;
            float b0 = biasb ? biasb[n] : 0.f;
            float b1 = biasb ? biasb[n + 1] : 0.f;
            float v0 = acc[i][j][0] + b0;
            float v1 = acc[i][j][1] + b1;
            float v2 = acc[i][j][2] + b0;
            float v3 = acc[i][j][3] + b1;
            if (act == 1) {
                v0 = fmaxf(v0, 0.f); v1 = fmaxf(v1, 0.f);
                v2 = fmaxf(v2, 0.f); v3 = fmaxf(v3, 0.f);
            }
            Cb[(size_t)mA * ldc + n]     = v0;
            Cb[(size_t)mA * ldc + n + 1] = v1;
            Cb[(size_t)mB * ldc + n]     = v2;
            Cb[(size_t)mB * ldc + n + 1] = v3;
        }
    }
}

// =====================================================================
// Edge gather-GEMM v2 (proven): m2 = relu(relu(eA[tgt]+eB[src]+bm1)@Wm2+bm2)
// =====================================================================
#define EG_ASTR 36
#define EG_BSTR 136
#define EG_SMEM ((4*128*EG_ASTR + 2*32*EG_BSTR) * 4)   // 108544 B

__global__ __launch_bounds__(256)
void egemm_gather_k(const float* __restrict__ eA, const float* __restrict__ eB,
                    const float* __restrict__ b1, const int* __restrict__ ei,
                    const float* __restrict__ W, const float* __restrict__ b2,
                    float* __restrict__ C)
{
    __shared__ int   tgts[128], srcs[128];
    __shared__ float b1s[256];
    extern __shared__ float smem[];
    float* AsA = smem;
    float* AsB = smem + 2 * 128 * EG_ASTR;
    float* Bs  = smem + 4 * 128 * EG_ASTR;

    const int tid  = threadIdx.x;
    const int wid  = tid >> 5;
    const int lane = tid & 31;
    const int wx   = wid & 3;
    const int wy   = wid >> 2;
    const int lg   = lane >> 2;
    const int lt   = lane & 3;
    const int m0   = blockIdx.y * 128;
    const int n0   = blockIdx.x * 128;

    if (tid < 128) { srcs[tid] = ei[m0 + tid]; tgts[tid] = ei[EE + m0 + tid]; }
    b1s[tid] = b1[tid];
    __syncthreads();

    auto load_stage = [&](int s, int k0) {
        float* aA = AsA + s * 128 * EG_ASTR;
        float* aB = AsB + s * 128 * EG_ASTR;
#pragma unroll
        for (int j = 0; j < 4; j++) {
            int idx = tid + j * 256;
            int m = idx >> 3, k4 = idx & 7;
            cpasync16(&aA[m * EG_ASTR + k4 * 4],
                      &eA[(size_t)tgts[m] * QD + k0 + k4 * 4]);
            cpasync16(&aB[m * EG_ASTR + k4 * 4],
                      &eB[(size_t)srcs[m] * QD + k0 + k4 * 4]);
        }
        float* bs = Bs + s * 32 * EG_BSTR;
#pragma unroll
        for (int j = 0; j < 4; j++) {
            int idx = tid + j * 256;
            int k = idx >> 5, n4 = idx & 31;
            cpasync16(&bs[k * EG_BSTR + n4 * 4],
                      &W[(size_t)(k0 + k) * QD + n0 + n4 * 4]);
        }
    };
    load_stage(0, 0);
    CP_COMMIT();

    float acc[4][4][4];
#pragma unroll
    for (int i = 0; i < 4; i++)
#pragma unroll
        for (int j = 0; j < 4; j++)
#pragma unroll
            for (int c = 0; c < 4; c++) acc[i][j][c] = 0.f;

    for (int t = 0; t < 8; t++) {
        if (t + 1 < 8) load_stage((t + 1) & 1, (t + 1) * 32);
        CP_COMMIT();
        asm volatile("cp.async.wait_group 1;\n" ::: "memory");
        __syncthreads();

        const float* aA = AsA + (t & 1) * 128 * EG_ASTR;
        const float* aB = AsB + (t & 1) * 128 * EG_ASTR;
        const float* bs = Bs  + (t & 1) * 32 * EG_BSTR;
        const int kg0 = t * 32;

#pragma unroll
        for (int ks = 0; ks < 4; ks++) {
            const int kk = ks * 8;
            const float bA0 = b1s[kg0 + kk + lt];
            const float bA1 = b1s[kg0 + kk + lt + 4];
            unsigned af[4][4], bf[4][2];
#pragma unroll
            for (int i = 0; i < 4; i++) {
                int row = wy * 64 + i * 16 + lg;
                af[i][0] = f2tf(fmaxf(aA[row * EG_ASTR + kk + lt] +
                                      aB[row * EG_ASTR + kk + lt] + bA0, 0.f));
                af[i][1] = f2tf(fmaxf(aA[(row + 8) * EG_ASTR + kk + lt] +
                                      aB[(row + 8) * EG_ASTR + kk + lt] + bA0, 0.f));
                af[i][2] = f2tf(fmaxf(aA[row * EG_ASTR + kk + lt + 4] +
                                      aB[row * EG_ASTR + kk + lt + 4] + bA1, 0.f));
                af[i][3] = f2tf(fmaxf(aA[(row + 8) * EG_ASTR + kk + lt + 4] +
                                      aB[(row + 8) * EG_ASTR + kk + lt + 4] + bA1, 0.f));
            }
#pragma unroll
            for (int j = 0; j < 4; j++) {
                int col = wx * 32 + j * 8 + lg;
                bf[j][0] = f2tf(bs[(kk + lt) * EG_BSTR + col]);
                bf[j][1] = f2tf(bs[(kk + lt + 4) * EG_BSTR + col]);
            }
#pragma unroll
            for (int i = 0; i < 4; i++)
#pragma unroll
                for (int j = 0; j < 4; j++)
                    mma_tf32(acc[i][j], af[i], bf[j]);
        }
        __syncthreads();
    }

#pragma unroll
    for (int i = 0; i < 4; i++) {
        int mA = m0 + wy * 64 + i * 16 + lg;
        int mB = mA + 8;
#pragma unroll
        for (int j = 0; j < 4; j++) {
            int n = n0 + wx * 32 + j * 8 + lt * 2;
            float b0 = b2[n], b1v = b2[n + 1];
            C[(size_t)mA * QD + n]     = fmaxf(acc[i][j][0] + b0, 0.f);
            C[(size_t)mA * QD + n + 1] = fmaxf(acc[i][j][1] + b1v, 0.f);
            C[(size_t)mB * QD + n]     = fmaxf(acc[i][j][2] + b0, 0.f);
            C[(size_t)mB * QD + n + 1] = fmaxf(acc[i][j][3] + b1v, 0.f);
        }
    }
}

// =====================================================================
// Edge scatter-GEMM (proven): agg[tgt[e]] += m2[e] @ Wm3 + bm3
// =====================================================================
#define ES_SMEM ((3*128*EG_ASTR + 3*32*EG_BSTR) * 4)   // 107520 B

__global__ __launch_bounds__(256)
void egemm_scatter_k(const float* __restrict__ A, const int* __restrict__ ei,
                     const float* __restrict__ W, const float* __restrict__ b3,
                     float* __restrict__ agg)
{
    extern __shared__ float smem[];
    float* AsBase = smem;
    float* BsBase = smem + 3 * 128 * EG_ASTR;

    const int tid  = threadIdx.x;
    const int wid  = tid >> 5;
    const int lane = tid & 31;
    const int wx   = wid & 3;
    const int wy   = wid >> 2;
    const int lg   = lane >> 2;
    const int lt   = lane & 3;
    const int m0   = blockIdx.y * 128;
    const int n0   = blockIdx.x * 128;

    auto load_stage = [&](int s, int k0) {
        float* as = AsBase + s * 128 * EG_ASTR;
#pragma unroll
        for (int j = 0; j < 4; j++) {
            int idx = tid + j * 256;
            int m = idx >> 3, k4 = idx & 7;
            cpasync16(&as[m * EG_ASTR + k4 * 4],
                      &A[(size_t)(m0 + m) * QD + k0 + k4 * 4]);
        }
        float* bs = BsBase + s * 32 * EG_BSTR;
#pragma unroll
        for (int j = 0; j < 4; j++) {
            int idx = tid + j * 256;
            int k = idx >> 5, n4 = idx & 31;
            cpasync16(&bs[k * EG_BSTR + n4 * 4],
                      &W[(size_t)(k0 + k) * HDIM + n0 + n4 * 4]);
        }
    };
    load_stage(0, 0);  CP_COMMIT();
    load_stage(1, 32); CP_COMMIT();

    float acc[4][4][4];
#pragma unroll
    for (int i = 0; i < 4; i++)
#pragma unroll
        for (int j = 0; j < 4; j++)
#pragma unroll
            for (int c = 0; c < 4; c++) acc[i][j][c] = 0.f;

    for (int t = 0; t < 8; t++) {
        asm volatile("cp.async.wait_group 1;\n" ::: "memory");
        __syncthreads();

        if (t + 2 < 8) load_stage((t + 2) % 3, (t + 2) * 32);
        CP_COMMIT();

        const float* as = AsBase + (t % 3) * 128 * EG_ASTR;
        const float* bs = BsBase + (t % 3) * 32 * EG_BSTR;
#pragma unroll
        for (int ks = 0; ks < 4; ks++) {
            const int kk = ks * 8;
            unsigned af[4][4], bf[4][2];
#pragma unroll
            for (int i = 0; i < 4; i++) {
                int row = wy * 64 + i * 16 + lg;
                af[i][0] = f2tf(as[row * EG_ASTR + kk + lt]);
                af[i][1] = f2tf(as[(row + 8) * EG_ASTR + kk + lt]);
                af[i][2] = f2tf(as[row * EG_ASTR + kk + lt + 4]);
                af[i][3] = f2tf(as[(row + 8) * EG_ASTR + kk + lt + 4]);
            }
#pragma unroll
            for (int j = 0; j < 4; j++) {
                int col = wx * 32 + j * 8 + lg;
                bf[j][0] = f2tf(bs[(kk + lt) * EG_BSTR + col]);
                bf[j][1] = f2tf(bs[(kk + lt + 4) * EG_BSTR + col]);
            }
#pragma unroll
            for (int i = 0; i < 4; i++)
#pragma unroll
                for (int j = 0; j < 4; j++)
                    mma_tf32(acc[i][j], af[i], bf[j]);
        }
        __syncthreads();
    }

#pragma unroll
    for (int i = 0; i < 4; i++) {
        int mA = m0 + wy * 64 + i * 16 + lg;
        int mB = mA + 8;
        int tA = ei[EE + mA];
        int tB = ei[EE + mB];
#pragma unroll
        for (int j = 0; j < 4; j++) {
            int n = n0 + wx * 32 + j * 8 + lt * 2;
            float b0 = b3[n], b1v = b3[n + 1];
            atomicAdd(&agg[(size_t)tA * HDIM + n],     acc[i][j][0] + b0);
            atomicAdd(&agg[(size_t)tA * HDIM + n + 1], acc[i][j][1] + b1v);
            atomicAdd(&agg[(size_t)tB * HDIM + n],     acc[i][j][2] + b0);
            atomicAdd(&agg[(size_t)tB * HDIM + n + 1], acc[i][j][3] + b1v);
        }
    }
}

// =====================================================================
// Flash MHA (proven, unchanged)
// =====================================================================
#define FBQ   128
#define FBKV  64
#define QSTR  36
#define KSTR  36
#define VSTR  40
#define PSTR  68
#define FLASH_SMEM ((FBQ*QSTR + 2*FBKV*KSTR + 2*FBKV*VSTR + 8*16*PSTR) * 4)

__global__ __launch_bounds__(256)
void flash_mha_k(const float* __restrict__ mq, const float* __restrict__ mk,
                 const float* __restrict__ mv, float* __restrict__ mo, float scale)
{
    extern __shared__ float sm[];
    float*    Qs = sm;
    float*    Ks = Qs + FBQ * QSTR;
    float*    Vs = Ks + 2 * FBKV * KSTR;
    unsigned* Ps = (unsigned*)(Vs + 2 * FBKV * VSTR);

    const int tid  = threadIdx.x;
    const int wid  = tid >> 5;
    const int lane = tid & 31;
    const int lg   = lane >> 2;
    const int lt   = lane & 3;
    const int hh   = blockIdx.y;
    const int q0   = blockIdx.x * FBQ;

    const float* Qg = mq + (size_t)q0 * QD + hh * HD;
    const float* Kg = mk + hh * HD;
    const float* Vg = mv + hh * HD;

#pragma unroll
    for (int j = 0; j < 4; j++) {
        int idx = tid + j * 256;
        int r = idx >> 3, c4 = idx & 7;
        cpasync16(&Qs[r * QSTR + c4 * 4], &Qg[(size_t)r * QD + c4 * 4]);
    }
    auto loadKV = [&](int s, int kv0) {
        float* ks = Ks + s * FBKV * KSTR;
        float* vs = Vs + s * FBKV * VSTR;
#pragma unroll
        for (int j = 0; j < 2; j++) {
            int idx = tid + j * 256;
            int r = idx >> 3, c4 = idx & 7;
            cpasync16(&ks[r * KSTR + c4 * 4], &Kg[(size_t)(kv0 + r) * QD + c4 * 4]);
        }
#pragma unroll
        for (int j = 0; j < 2; j++) {
            int idx = tid + j * 256;
            int r = idx >> 3, c4 = idx & 7;
            cpasync16(&vs[r * VSTR + c4 * 4], &Vg[(size_t)(kv0 + r) * QD + c4 * 4]);
        }
    };
    loadKV(0, 0);
    CP_COMMIT();

    float O[4][4];
#pragma unroll
    for (int j = 0; j < 4; j++)
#pragma unroll
        for (int c = 0; c < 4; c++) O[j][c] = 0.f;
    float m0r = -3.4e38f, m1r = -3.4e38f;
    float l0 = 0.f, l1 = 0.f;
    unsigned* Pw = Ps + wid * 16 * PSTR;
    const int qrow = wid * 16 + lg;

    const int NT = NN / FBKV;
    for (int t = 0; t < NT; t++) {
        if (t + 1 < NT) loadKV((t + 1) & 1, (t + 1) * FBKV);
        CP_COMMIT();
        asm volatile("cp.async.wait_group 1;\n" ::: "memory");
        __syncthreads();

        const float* ks = Ks + (t & 1) * FBKV * KSTR;
        const float* vs = Vs + (t & 1) * FBKV * VSTR;

        float Sacc[8][4];
#pragma unroll
        for (int n = 0; n < 8; n++)
#pragma unroll
            for (int c = 0; c < 4; c++) Sacc[n][c] = 0.f;
#pragma unroll
        for (int ks8 = 0; ks8 < 4; ks8++) {
            const int kk = ks8 * 8;
            unsigned af[4];
            af[0] = f2tf(Qs[qrow * QSTR + kk + lt]);
            af[1] = f2tf(Qs[(qrow + 8) * QSTR + kk + lt]);
            af[2] = f2tf(Qs[qrow * QSTR + kk + lt + 4]);
            af[3] = f2tf(Qs[(qrow + 8) * QSTR + kk + lt + 4]);
#pragma unroll
            for (int n = 0; n < 8; n++) {
                int col = n * 8 + lg;
                unsigned bf[2];
                bf[0] = f2tf(ks[col * KSTR + kk + lt]);
                bf[1] = f2tf(ks[col * KSTR + kk + lt + 4]);
                mma_tf32(Sacc[n], af, bf);
            }
        }

        float mx0 = -3.4e38f, mx1 = -3.4e38f;
#pragma unroll
        for (int n = 0; n < 8; n++) {
            Sacc[n][0] *= scale; Sacc[n][1] *= scale;
            Sacc[n][2] *= scale; Sacc[n][3] *= scale;
            mx0 = fmaxf(mx0, fmaxf(Sacc[n][0], Sacc[n][1]));
            mx1 = fmaxf(mx1, fmaxf(Sacc[n][2], Sacc[n][3]));
        }
        mx0 = fmaxf(mx0, __shfl_xor_sync(0xffffffffu, mx0, 1));
        mx0 = fmaxf(mx0, __shfl_xor_sync(0xffffffffu, mx0, 2));
        mx1 = fmaxf(mx1, __shfl_xor_sync(0xffffffffu, mx1, 1));
        mx1 = fmaxf(mx1, __shfl_xor_sync(0xffffffffu, mx1, 2));
        float mn0 = fmaxf(m0r, mx0), mn1 = fmaxf(m1r, mx1);
        float a0 = __expf(m0r - mn0), a1 = __expf(m1r - mn1);
        float rs0 = 0.f, rs1 = 0.f;
#pragma unroll
        for (int n = 0; n < 8; n++) {
            float p0 = __expf(Sacc[n][0] - mn0);
            float p1 = __expf(Sacc[n][1] - mn0);
            float p2 = __expf(Sacc[n][2] - mn1);
            float p3 = __expf(Sacc[n][3] - mn1);
            rs0 += p0 + p1; rs1 += p2 + p3;
            int c0 = n * 8 + lt * 2;
            Pw[lg * PSTR + c0]           = f2tf(p0);
            Pw[lg * PSTR + c0 + 1]       = f2tf(p1);
            Pw[(lg + 8) * PSTR + c0]     = f2tf(p2);
            Pw[(lg + 8) * PSTR + c0 + 1] = f2tf(p3);
        }
        rs0 += __shfl_xor_sync(0xffffffffu, rs0, 1);
        rs0 += __shfl_xor_sync(0xffffffffu, rs0, 2);
        rs1 += __shfl_xor_sync(0xffffffffu, rs1, 1);
        rs1 += __shfl_xor_sync(0xffffffffu, rs1, 2);
        l0 = l0 * a0 + rs0;
        l1 = l1 * a1 + rs1;
        m0r = mn0; m1r = mn1;
#pragma unroll
        for (int j = 0; j < 4; j++) {
            O[j][0] *= a0; O[j][1] *= a0;
            O[j][2] *= a1; O[j][3] *= a1;
        }
        __syncwarp();

#pragma unroll
        for (int ks8 = 0; ks8 < 8; ks8++) {
            const int kk = ks8 * 8;
            unsigned af[4];
            af[0] = Pw[lg * PSTR + kk + lt];
            af[1] = Pw[(lg + 8) * PSTR + kk + lt];
            af[2] = Pw[lg * PSTR + kk + lt + 4];
            af[3] = Pw[(lg + 8) * PSTR + kk + lt + 4];
#pragma unroll
            for (int j = 0; j < 4; j++) {
                int col = j * 8 + lg;
                unsigned bf[2];
                bf[0] = f2tf(vs[(kk + lt) * VSTR + col]);
                bf[1] = f2tf(vs[(kk + lt + 4) * VSTR + col]);
                mma_tf32(O[j], af, bf);
            }
        }
        __syncwarp();
        __syncthreads();
    }

    float inv0 = 1.f / l0, inv1 = 1.f / l1;
    const size_t rA = (size_t)(q0 + qrow) * QD + hh * HD;
    const size_t rB = rA + 8 * QD;
#pragma unroll
    for (int j = 0; j < 4; j++) {
        int c = j * 8 + lt * 2;
        mo[rA + c]     = O[j][0] * inv0;
        mo[rA + c + 1] = O[j][1] * inv0;
        mo[rB + c]     = O[j][2] * inv1;
        mo[rB + c + 1] = O[j][3] * inv1;
    }
}

// =====================================================================
// Sparse graph attention (proven, unchanged)
// =====================================================================
__global__ __launch_bounds__(128)
void sparse_gatt_k(const float* __restrict__ Q, const float* __restrict__ K,
                   const float* __restrict__ V, const unsigned* __restrict__ mask,
                   const float* __restrict__ vmean, float* __restrict__ gatt,
                   float scale)
{
    __shared__ int   idxs[NN];
    __shared__ float sc  [NN];
    __shared__ int   wbase[5];
    __shared__ float red[4];

    const int s    = blockIdx.x;
    const int tid  = threadIdx.x;
    const int wid  = tid >> 5;
    const int lane = tid & 31;

    unsigned w = mask[(size_t)s * MW + tid];
    int c = __popc(w);
    int pre = c;
#pragma unroll
    for (int o = 1; o < 32; o <<= 1) {
        int v = __shfl_up_sync(0xffffffffu, pre, o);
        if (lane >= o) pre += v;
    }
    if (lane == 31) wbase[wid + 1] = pre;
    __syncthreads();
    if (tid == 0) {
        wbase[0] = 0;
        wbase[2] += wbase[1];
        wbase[3] += wbase[2];
        wbase[4] += wbase[3];
    }
    __syncthreads();
    const int cnt = wbase[4];
    int p = wbase[wid] + pre - c;
    unsigned ww = w;
    while (ww) {
        int b = __ffs(ww) - 1;
        idxs[p++] = tid * 32 + b;
        ww &= ww - 1;
    }
    __syncthreads();

    const int c0 = tid * 2;
    if (cnt == 0) {
        gatt[(size_t)s * QD + c0]     = vmean[c0];
        gatt[(size_t)s * QD + c0 + 1] = vmean[c0 + 1];
        return;
    }

    float q[8];
    const float* Qr = Q + (size_t)s * QD;
#pragma unroll
    for (int i = 0; i < 8; i++) q[i] = Qr[lane * 8 + i];
    for (int e = wid; e < cnt; e += 4) {
        const float* Kr = K + (size_t)idxs[e] * QD;
        float d = 0.f;
#pragma unroll
        for (int i = 0; i < 8; i++) d = fmaf(q[i], Kr[lane * 8 + i], d);
#pragma unroll
        for (int o = 16; o; o >>= 1) d += __shfl_xor_sync(0xffffffffu, d, o);
        if (lane == 0) sc[e] = d * scale;
    }
    __syncthreads();

    float mx = -3.4e38f;
    for (int e = tid; e < cnt; e += 128) mx = fmaxf(mx, sc[e]);
#pragma unroll
    for (int o = 16; o; o >>= 1) mx = fmaxf(mx, __shfl_xor_sync(0xffffffffu, mx, o));
    if (lane == 0) red[wid] = mx;
    __syncthreads();
    mx = fmaxf(fmaxf(red[0], red[1]), fmaxf(red[2], red[3]));
    __syncthreads();

    float sum = 0.f;
    for (int e = tid; e < cnt; e += 128) {
        float pe = __expf(sc[e] - mx);
        sc[e] = pe;
        sum += pe;
    }
#pragma unroll
    for (int o = 16; o; o >>= 1) sum += __shfl_xor_sync(0xffffffffu, sum, o);
    if (lane == 0) red[wid] = sum;
    __syncthreads();
    float inv = 1.f / (red[0] + red[1] + red[2] + red[3]);

    float a0 = 0.f, a1 = 0.f;
    for (int e = 0; e < cnt; e++) {
        const float* Vr = V + (size_t)idxs[e] * QD;
        float pe = sc[e];
        a0 = fmaf(pe, Vr[c0], a0);
        a1 = fmaf(pe, Vr[c0 + 1], a1);
    }
    gatt[(size_t)s * QD + c0]     = a0 * inv;
    gatt[(size_t)s * QD + c0 + 1] = a1 * inv;
}

// ---------------- block reductions ----------------
__device__ __forceinline__ float blkMax(float v) {
    __shared__ float sh[8];
#pragma unroll
    for (int o = 16; o; o >>= 1) v = fmaxf(v, __shfl_xor_sync(0xffffffffu, v, o));
    if ((threadIdx.x & 31) == 0) sh[threadIdx.x >> 5] = v;
    __syncthreads();
    if (threadIdx.x < 32) {
        float w = (threadIdx.x < 8) ? sh[threadIdx.x] : -3.4e38f;
#pragma unroll
        for (int o = 4; o; o >>= 1) w = fmaxf(w, __shfl_xor_sync(0xffffffffu, w, o));
        if (threadIdx.x == 0) sh[0] = w;
    }
    __syncthreads();
    float r = sh[0];
    __syncthreads();
    return r;
}
__device__ __forceinline__ float blkSum(float v) {
    __shared__ float sh[8];
#pragma unroll
    for (int o = 16; o; o >>= 1) v += __shfl_xor_sync(0xffffffffu, v, o);
    if ((threadIdx.x & 31) == 0) sh[threadIdx.x >> 5] = v;
    __syncthreads();
    if (threadIdx.x < 32) {
        float w = (threadIdx.x < 8) ? sh[threadIdx.x] : 0.f;
#pragma unroll
        for (int o = 4; o; o >>= 1) w += __shfl_xor_sync(0xffffffffu, w, o);
        if (threadIdx.x == 0) sh[0] = w;
    }
    __syncthreads();
    float r = sh[0];
    __syncthreads();
    return r;
}

// ---------------- elementwise / small kernels ----------------
__global__ void zero_u32_k(unsigned* __restrict__ p, int n) {
    int i = blockIdx.x * blockDim.x + threadIdx.x;
    if (i < n) p[i] = 0u;
}
__global__ void zero_f32_k(float* __restrict__ p, int n) {
    int i = blockIdx.x * blockDim.x + threadIdx.x;
    if (i < n) p[i] = 0.f;
}
__global__ void build_mask_k(const int* __restrict__ ei, unsigned* __restrict__ mask) {
    int e = blockIdx.x * blockDim.x + threadIdx.x;
    if (e >= EE) return;
    int s = ei[e], t = ei[EE + e];
    atomicOr(&mask[(size_t)s * MW + (t >> 5)], 1u << (t & 31));
}
__global__ void stage_qkv_k(const float* __restrict__ Wq, const float* __restrict__ Wk,
                            const float* __restrict__ Wv, const float* __restrict__ bq,
                            const float* __restrict__ bk, const float* __restrict__ bv,
                            float* __restrict__ W3, float* __restrict__ b3) {
    int i = blockIdx.x * blockDim.x + threadIdx.x;
    const int per = HDIM * QD;
    if (i < 2 * per) {
        int l = i / per, r = i % per;
        W3[((size_t)l * 3 + 0) * per + r] = Wq[i];
        W3[((size_t)l * 3 + 1) * per + r] = Wk[i];
        W3[((size_t)l * 3 + 2) * per + r] = Wv[i];
    }
    if (i < 2 * QD) {
        int l = i / QD, r = i % QD;
        b3[(l * 3 + 0) * QD + r] = bq[i];
        b3[(l * 3 + 1) * QD + r] = bk[i];
        b3[(l * 3 + 2) * QD + r] = bv[i];
    }
}
__global__ void stage_bc_k(const float* __restrict__ Bc, float* __restrict__ Bc2) {
    int i = blockIdx.x * blockDim.x + threadIdx.x;
    if (i >= 2 * QD * QD) return;
    int l = i / (QD * QD), r = i % (QD * QD);
    int row = r / QD, col = r % QD;
    Bc2[((size_t)l * 2 + 0) * QD * QD + r] = Bc[i];
    Bc2[((size_t)l * 2 + 1) * QD * QD + (size_t)row * QD + col] =
        Bc[(size_t)l * QD * QD + (size_t)col * QD + row];
}
__global__ void vmean_k(const float* __restrict__ V, float* __restrict__ vm) {
    int c = blockIdx.x;
    float s = 0.f;
    for (int r = threadIdx.x; r < NN; r += 256) s += V[(size_t)r * QD + c];
    s = blkSum(s);
    if (threadIdx.x == 0) vm[c] = s * (1.f / NN);
}
__global__ void add_ce_k(float4* __restrict__ Q, float4* __restrict__ K,
                         const float4* __restrict__ ce, const int* __restrict__ ct) {
    int idx = blockIdx.x * blockDim.x + threadIdx.x;
    if (idx >= NN * (QD / 4)) return;
    int i = idx >> 6, j4 = idx & 63;
    float4 c = ce[ct[i] * (QD / 4) + j4];
    float4 q = Q[idx], k = K[idx];
    q.x += 0.1f * c.x; q.y += 0.1f * c.y; q.z += 0.1f * c.z; q.w += 0.1f * c.w;
    k.x += 0.1f * c.x; k.y += 0.1f * c.y; k.z += 0.1f * c.z; k.w += 0.1f * c.w;
    Q[idx] = q; K[idx] = k;
}
__global__ void combine_ln_k(float* __restrict__ h, const float* __restrict__ agg,
                             const float* __restrict__ mha, const float* __restrict__ gatt,
                             const float* __restrict__ g, const float* __restrict__ b) {
    int r = blockIdx.x, j = threadIdx.x;
    size_t idx = (size_t)r * HDIM + j;
    float v = h[idx] + agg[idx] + mha[idx] + gatt[idx];
    float mu = blkSum(v) * (1.f / HDIM);
    float d = v - mu;
    float var = blkSum(d * d) * (1.f / HDIM);
    h[idx] = d * rsqrtf(var + 1e-5f) * g[j] + b[j];
}
__global__ void pool_k(const float* __restrict__ h, float* __restrict__ pool) {
    int c = blockIdx.x, t = threadIdx.x;
    if (c < HDIM) {
        float s = 0.f;
        for (int r = t; r < NN; r += 256) s += h[(size_t)r * HDIM + c];
        s = blkSum(s);
        if (t == 0) pool[c] = s * (1.f / NN);
    } else {
        int cc = c - HDIM;
        float m = -3.4e38f;
        for (int r = t; r < NN; r += 256) m = fmaxf(m, h[(size_t)r * HDIM + cc]);
        m = blkMax(m);
        if (t == 0) pool[c] = m;
    }
}
__global__ void fc1_k(const float* __restrict__ pool, const float* __restrict__ W,
                      const float* __restrict__ b, float* __restrict__ z) {
    int o = blockIdx.x, t = threadIdx.x;
    float s = 0.f;
    for (int i = t; i < 2 * HDIM; i += 256) s += pool[i] * W[(size_t)i * HDIM + o];
    s = blkSum(s);
    if (t == 0) z[o] = fmaxf(s + b[o], 0.f);
}
__global__ void fc2_k(const float* __restrict__ z, const float* __restrict__ W,
                      const float* __restrict__ b, float* __restrict__ out) {
    int o = blockIdx.x, t = threadIdx.x;
    float s = 0.f;
    for (int i = t; i < HDIM; i += 256) s += z[i] * W[(size_t)i * OUTD + o];
    s = blkSum(s);
    if (t == 0) out[o] = s + b[o];
}

// ---------------- host side ----------------
static float* sym(const void* s) {
    void* p = nullptr;
    cudaGetSymbolAddress(&p, (const void*)s);
    return (float*)p;
}

#define NODE  64,128,32,32

template<int BM,int BN,int WM,int WN,int TRANSB,int STAGES>
static void launch_tg(dim3 grid, cudaStream_t st,
                      const float* A, int lda, long long sA,
                      const float* B, int ldb, long long sB,
                      float* C, int ldc, long long sC, int K,
                      const float* bias, long long sBias, int act)
{
    constexpr size_t sm = tg_smem<BM, BN, TRANSB, STAGES>();
    static bool attr_done = false;
    if (!attr_done) {
        cudaFuncSetAttribute(tgemm_k<BM,BN,WM,WN,TRANSB,STAGES>,
                             cudaFuncAttributeMaxDynamicSharedMemorySize, (int)sm);
        attr_done = true;
    }
    tgemm_k<BM,BN,WM,WN,TRANSB,STAGES><<<grid, 256, sm, st>>>(
        A, lda, sA, B, ldb, sB, C, ldc, sC, K, bias, sBias, act);
}

extern "C" void kernel_launch(void* const* d_in, const int* in_sizes, int n_in,
                              void* d_out, int out_size) {
    const float* x    = (const float*)d_in[0];
    const int*   ei   = (const int*)  d_in[1];
    const int*   ct   = (const int*)  d_in[2];
    const float* Wi   = (const float*)d_in[3];
    const float* bi   = (const float*)d_in[4];
    const float* Wq   = (const float*)d_in[5];
    const float* bq   = (const float*)d_in[6];
    const float* Wk   = (const float*)d_in[7];
    const float* bk   = (const float*)d_in[8];
    const float* Wv   = (const float*)d_in[9];
    const float* bv   = (const float*)d_in[10];
    const float* Bc   = (const float*)d_in[11];
    const float* cemb = (const float*)d_in[12];
    const float* Win  = (const float*)d_in[13];
    const float* binp = (const float*)d_in[14];
    const float* Wo   = (const float*)d_in[15];
    const float* bo   = (const float*)d_in[16];
    const float* Wm1  = (const float*)d_in[17];
    const float* bm1  = (const float*)d_in[18];
    const float* Wm2  = (const float*)d_in[19];
    const float* bm2  = (const float*)d_in[20];
    const float* Wm3  = (const float*)d_in[21];
    const float* bm3  = (const float*)d_in[22];
    const float* lng  = (const float*)d_in[23];
    const float* lnb  = (const float*)d_in[24];
    const float* Wc1  = (const float*)d_in[25];
    const float* bc1  = (const float*)d_in[26];
    const float* Wc2  = (const float*)d_in[27];
    const float* bc2  = (const float*)d_in[28];
    float* out = (float*)d_out;

    float* h    = sym(g_h);
    float* bufA = sym(g_bufA);
    float* bufB = sym(g_bufB);
    float* bufC = sym(g_bufC);
    float* bufD = sym(g_bufD);
    float* W3   = sym(g_W3);
    float* b3s  = sym(g_b3);
    float* Bc2  = sym(g_Bc2);
    float* vm   = sym(g_vm);
    float* gatt = sym(g_gatt);
    float* mo   = sym(g_mo);
    float* mha  = sym(g_mha);
    float* m2   = sym(g_m2);
    float* agg  = sym(g_agg);
    float* pool = sym(g_pool);
    float* z    = sym(g_z);
    unsigned* mask = (unsigned*)sym(g_mask);

    const int TPB = 256;
    const long long HQD = (long long)HDIM * QD;
    cudaStream_t s0 = 0;   // captured stream

    static cudaStream_t s2 = nullptr, s3 = nullptr;
    static cudaEvent_t  evR[LL], evB[LL], evA[LL], evG[LL], evMask;
    static bool attrs = false;
    if (!attrs) {
        cudaFuncSetAttribute(flash_mha_k,
                             cudaFuncAttributeMaxDynamicSharedMemorySize, FLASH_SMEM);
        cudaFuncSetAttribute(egemm_gather_k,
                             cudaFuncAttributeMaxDynamicSharedMemorySize, EG_SMEM);
        cudaFuncSetAttribute(egemm_scatter_k,
                             cudaFuncAttributeMaxDynamicSharedMemorySize, ES_SMEM);
        cudaStreamCreateWithFlags(&s2, cudaStreamNonBlocking);
        cudaStreamCreateWithFlags(&s3, cudaStreamNonBlocking);
        for (int i = 0; i < LL; i++) {
            cudaEventCreateWithFlags(&evR[i], cudaEventDisableTiming);
            cudaEventCreateWithFlags(&evB[i], cudaEventDisableTiming);
            cudaEventCreateWithFlags(&evA[i], cudaEventDisableTiming);
            cudaEventCreateWithFlags(&evG[i], cudaEventDisableTiming);
        }
        cudaEventCreateWithFlags(&evMask, cudaEventDisableTiming);
        attrs = true;
    }

    // fork setup: mask build on s2 (only sparse_gatt needs it), staging on s0
    cudaEventRecord(evR[0], s0);           // capture-origin anchor for s2/s3
    cudaStreamWaitEvent(s2, evR[0], 0);
    cudaStreamWaitEvent(s3, evR[0], 0);
    zero_u32_k<<<(NN * MW + TPB - 1) / TPB, TPB, 0, s2>>>(mask, NN * MW);
    build_mask_k<<<(EE + TPB - 1) / TPB, TPB, 0, s2>>>(ei, mask);
    cudaEventRecord(evMask, s2);

    stage_qkv_k<<<(2 * HDIM * QD + TPB - 1) / TPB, TPB, 0, s0>>>(Wq, Wk, Wv, bq, bk, bv, W3, b3s);
    stage_bc_k<<<(2 * QD * QD + TPB - 1) / TPB, TPB, 0, s0>>>(Bc, Bc2);

    // h = relu(x @ Wi + bi)
    launch_tg<NODE,0,3>(dim3(HDIM/128, NN/64, 1), s0,
        x, IND, 0, Wi, HDIM, 0, h, HDIM, 0, IND, bi, 0, 1);

    for (int l = 0; l < LL; l++) {
        const float* ce_l  = cemb + (size_t)l * 50 * QD;
        const float* Win_l = Win + (size_t)l * QD * 3 * QD;
        const float* bin_l = binp + (size_t)l * 3 * QD;
        const float* Wo_l  = Wo  + (size_t)l * QD * QD;
        const float* Wm1_l = Wm1 + (size_t)l * (2 * HDIM + QD) * QD;
        const float* Wm2_l = Wm2 + (size_t)l * QD * QD;
        const float* Wm3_l = Wm3 + (size_t)l * QD * HDIM;

        dim3 gNode(QD/128, NN/64, 1);

        // ---- fork B: edge branch on s2 (depends only on h) ----
        cudaEventRecord(evR[l], s0);
        cudaStreamWaitEvent(s2, evR[l], 0);
        launch_tg<NODE,0,3>(dim3(QD/128, NN/64, 2), s2,
            h, HDIM, 0, Wm1_l, QD, HQD,
            bufD, QD, NNQD, HDIM, nullptr, 0, 0);
        zero_f32_k<<<(NN * HDIM + TPB - 1) / TPB, TPB, 0, s2>>>(agg, NN * HDIM);
        egemm_gather_k<<<dim3(QD/128, EE/128), 256, EG_SMEM, s2>>>(
            bufD, bufD + NNQD, bm1 + l * QD, ei, Wm2_l, bm2 + l * QD, m2);
        egemm_scatter_k<<<dim3(HDIM/128, EE/128), 256, ES_SMEM, s2>>>(
            m2, ei, Wm3_l, bm3 + l * HDIM, agg);
        cudaEventRecord(evB[l], s2);

        // ---- branch A on s0 ----
        launch_tg<NODE,0,3>(dim3(QD/128, NN/64, 2), s0,
            h, HDIM, 0, W3 + (size_t)l * 3 * HQD, QD, HQD,
            bufA, QD, NNQD, HDIM, b3s + l * 3 * QD, QD, 0);
        launch_tg<NODE,0,3>(gNode, s0,
            h, HDIM, 0, W3 + (size_t)l * 3 * HQD + 2 * HQD, QD, 0,
            bufB + 2 * NNQD, QD, 0, HDIM, b3s + l * 3 * QD + 2 * QD, 0, 0);
        launch_tg<NODE,0,3>(dim3(QD/128, NN/64, 2), s0,
            bufA, QD, NNQD, Bc2 + (size_t)l * 2 * QD * QD, QD, (long long)QD * QD,
            bufB, QD, NNQD, QD, nullptr, 0, 0);
        add_ce_k<<<(NN * QD / 4 + TPB - 1) / TPB, TPB, 0, s0>>>(
            (float4*)bufB, (float4*)(bufB + NNQD), (const float4*)ce_l, ct);

        // ---- fork G: sparse graph attention on s3 (reads bufB, mask) ----
        cudaEventRecord(evA[l], s0);
        cudaStreamWaitEvent(s3, evA[l], 0);
        if (l == 0) cudaStreamWaitEvent(s3, evMask, 0);
        vmean_k<<<QD, 256, 0, s3>>>(bufB + 2 * NNQD, vm);
        sparse_gatt_k<<<NN, 128, 0, s3>>>(bufB, bufB + NNQD, bufB + 2 * NNQD, mask, vm,
                                          gatt, 0.0625f);
        cudaEventRecord(evG[l], s3);

        // ---- MHA chain continues on s0 (doesn't touch gatt) ----
        launch_tg<NODE,0,3>(dim3(QD/128, NN/64, 3), s0,
            bufB, QD, NNQD, Win_l, 3*QD, QD,
            bufC, QD, NNQD, QD, bin_l, QD, 0);
        flash_mha_k<<<dim3(NN/FBQ, NHD), 256, FLASH_SMEM, s0>>>(
            bufC, bufC + NNQD, bufC + 2 * NNQD, mo, 0.17677669529663687f);
        launch_tg<NODE,0,3>(gNode, s0, mo, QD, 0, Wo_l, QD, 0, mha, QD, 0,
                            QD, bo + l * QD, 0, 0);

        // ---- join all, then residual + aggregate + LN ----
        cudaStreamWaitEvent(s0, evB[l], 0);
        cudaStreamWaitEvent(s0, evG[l], 0);
        combine_ln_k<<<NN, HDIM, 0, s0>>>(h, agg, mha, gatt,
                                          lng + l * HDIM, lnb + l * HDIM);
    }

    // readout
    pool_k<<<2 * HDIM, 256, 0, s0>>>(h, pool);
    fc1_k<<<HDIM, 256, 0, s0>>>(pool, Wc1, bc1, z);
    fc2_k<<<OUTD, 256, 0, s0>>>(z, Wc2, bc2, out);
}